// round 3
// baseline (speedup 1.0000x reference)
#include <cuda_runtime.h>
#include <cuda_bf16.h>
#include <math.h>

// ---------------- problem dims (fixed) ----------------
#define T_    2048
#define HID_  1024
#define H_    16
#define DK_   64
#define DV_   128
#define VAL_  2048   // H_*DV_
#define QKD_  1024   // H_*DK_
#define CONV_ 4

// ---------------- scratch (device globals; no allocation allowed) ---------
__device__ float g_x    [T_*HID_];   // rmsnormed input
__device__ float g_qpre [T_*QKD_];
__device__ float g_kpre [T_*QKD_];
__device__ float g_vpre [T_*VAL_];
__device__ float g_q    [T_*QKD_];
__device__ float g_k    [T_*QKD_];
__device__ float g_v    [T_*VAL_];
__device__ float g_gate [T_*VAL_];
__device__ float g_beta [T_*H_];
__device__ float g_gdec [T_*H_];
__device__ float g_o    [T_*VAL_];
__device__ float g_o2   [T_*VAL_];
__device__ float g_y1   [T_*HID_];

// ---------------- helpers ----------------
__device__ __forceinline__ float sigmoidf_(float x) { return 1.f / (1.f + __expf(-x)); }
__device__ __forceinline__ float siluf_(float x)    { return x * sigmoidf_(x); }

// ---------------- 1) RMSNorm ----------------
__global__ void rmsnorm_kernel(const float* __restrict__ h,
                               const float* __restrict__ w,
                               float* __restrict__ x) {
    int t = blockIdx.x;
    const float* row = h + (size_t)t * HID_;
    float ss = 0.f;
    for (int i = threadIdx.x; i < HID_; i += 256) { float v = row[i]; ss += v * v; }
    // block reduce (256 threads)
    for (int off = 16; off > 0; off >>= 1) ss += __shfl_xor_sync(0xffffffffu, ss, off);
    __shared__ float red[8];
    int warp = threadIdx.x >> 5, lane = threadIdx.x & 31;
    if (lane == 0) red[warp] = ss;
    __syncthreads();
    float tot = 0.f;
    if (warp == 0) {
        tot = (lane < 8) ? red[lane] : 0.f;
        for (int off = 4; off > 0; off >>= 1) tot += __shfl_xor_sync(0xffffffffu, tot, off);
        if (lane == 0) red[0] = tot;
    }
    __syncthreads();
    float scale = rsqrtf(red[0] / (float)HID_ + 1e-6f);
    for (int i = threadIdx.x; i < HID_; i += 256)
        x[(size_t)t * HID_ + i] = row[i] * scale * w[i];
}

// ---------------- 2) generic GEMM  C[M,N] = X[M,K] @ W[N,K]^T ----------------
// All M,N,K multiples of 64/16 here, no bounds checks.
#define BM 64
#define BN 64
#define BK 16
__global__ __launch_bounds__(256) void gemm_xwT(const float* __restrict__ X,
                                                const float* __restrict__ W,
                                                float* __restrict__ C,
                                                int M, int N, int K) {
    __shared__ float Xs[BM][BK + 1];
    __shared__ float Ws[BN][BK + 1];
    int tid = threadIdx.x;
    int tx = tid & 15, ty = tid >> 4;
    int m0 = blockIdx.y * BM, n0 = blockIdx.x * BN;
    int lr = tid >> 2;          // 0..63
    int lc = (tid & 3) * 4;     // 0,4,8,12
    float acc[4][4] = {};
    const float* Xp = X + (size_t)(m0 + lr) * K + lc;
    const float* Wp = W + (size_t)(n0 + lr) * K + lc;
    for (int k0 = 0; k0 < K; k0 += BK) {
        float4 xa = *(const float4*)(Xp + k0);
        float4 wa = *(const float4*)(Wp + k0);
        Xs[lr][lc + 0] = xa.x; Xs[lr][lc + 1] = xa.y; Xs[lr][lc + 2] = xa.z; Xs[lr][lc + 3] = xa.w;
        Ws[lr][lc + 0] = wa.x; Ws[lr][lc + 1] = wa.y; Ws[lr][lc + 2] = wa.z; Ws[lr][lc + 3] = wa.w;
        __syncthreads();
        #pragma unroll
        for (int kk = 0; kk < BK; kk++) {
            float a[4], b[4];
            #pragma unroll
            for (int i = 0; i < 4; i++) a[i] = Xs[ty * 4 + i][kk];
            #pragma unroll
            for (int j = 0; j < 4; j++) b[j] = Ws[tx * 4 + j][kk];
            #pragma unroll
            for (int i = 0; i < 4; i++)
                #pragma unroll
                for (int j = 0; j < 4; j++)
                    acc[i][j] = fmaf(a[i], b[j], acc[i][j]);
        }
        __syncthreads();
    }
    #pragma unroll
    for (int i = 0; i < 4; i++) {
        float4 v; v.x = acc[i][0]; v.y = acc[i][1]; v.z = acc[i][2]; v.w = acc[i][3];
        *(float4*)&C[(size_t)(m0 + ty * 4 + i) * N + n0 + tx * 4] = v;
    }
}

// ---------------- 3) beta / g decay from a_w,b_w (N=16, done directly) -------
__global__ void ab_kernel(const float* __restrict__ x,
                          const float* __restrict__ a_w,
                          const float* __restrict__ b_w,
                          const float* __restrict__ dt_bias,
                          const float* __restrict__ A_log,
                          float* __restrict__ beta,
                          float* __restrict__ gdec) {
    __shared__ float xs[HID_];
    int t = blockIdx.x;
    for (int i = threadIdx.x; i < HID_; i += 256) xs[i] = x[(size_t)t * HID_ + i];
    __syncthreads();
    int warp = threadIdx.x >> 5, lane = threadIdx.x & 31;
    for (int h = warp; h < H_; h += 8) {
        float da = 0.f, db = 0.f;
        const float* ap = a_w + (size_t)h * HID_;
        const float* bp = b_w + (size_t)h * HID_;
        for (int i = lane; i < HID_; i += 32) {
            float xv = xs[i];
            da = fmaf(xv, ap[i], da);
            db = fmaf(xv, bp[i], db);
        }
        for (int off = 16; off > 0; off >>= 1) {
            da += __shfl_xor_sync(0xffffffffu, da, off);
            db += __shfl_xor_sync(0xffffffffu, db, off);
        }
        if (lane == 0) {
            beta[t * H_ + h] = 1.f / (1.f + expf(-db));
            float z = da + dt_bias[h];
            float sp = (z > 20.f) ? z : log1pf(expf(z));
            gdec[t * H_ + h] = -expf(A_log[h]) * sp;
        }
    }
}

// ---------------- 4) causal depthwise conv (K=4) + silu ----------------
__global__ void conv_silu_kernel(const float* __restrict__ in,
                                 const float* __restrict__ w,
                                 float* __restrict__ out, int C) {
    int idx = blockIdx.x * blockDim.x + threadIdx.x;
    if (idx >= T_ * C) return;
    int t = idx / C, c = idx - t * C;
    float acc = 0.f;
    #pragma unroll
    for (int i = 0; i < CONV_; i++) {
        int tt = t - (CONV_ - 1) + i;
        if (tt >= 0) acc = fmaf(in[(size_t)tt * C + c], w[c * CONV_ + i], acc);
    }
    out[idx] = acc * (1.f / (1.f + __expf(-acc)));
}

// ---------------- 5) k DC-removal + q/k L2 normalize ----------------
__global__ void qknorm_kernel(float* __restrict__ q, float* __restrict__ k) {
    int gw = (blockIdx.x * blockDim.x + threadIdx.x) >> 5;  // one warp per (t,h)
    int lane = threadIdx.x & 31;
    if (gw >= T_ * H_) return;
    float* kp = k + (size_t)gw * DK_;
    float k0 = kp[lane], k1 = kp[lane + 32];
    float s = k0 + k1;
    for (int off = 16; off > 0; off >>= 1) s += __shfl_xor_sync(0xffffffffu, s, off);
    float mean = s * (1.f / 64.f);
    k0 -= mean; k1 -= mean;
    float ss = k0 * k0 + k1 * k1;
    for (int off = 16; off > 0; off >>= 1) ss += __shfl_xor_sync(0xffffffffu, ss, off);
    float sc = rsqrtf(ss + 1e-6f);
    kp[lane] = k0 * sc; kp[lane + 32] = k1 * sc;

    float* qp = q + (size_t)gw * DK_;
    float q0 = qp[lane], q1 = qp[lane + 32];
    float qq = q0 * q0 + q1 * q1;
    for (int off = 16; off > 0; off >>= 1) qq += __shfl_xor_sync(0xffffffffu, qq, off);
    float qs = rsqrtf(qq + 1e-6f) * 0.125f;   // * DK^-0.5
    qp[lane] = q0 * qs; qp[lane + 32] = q1 * qs;
}

// ---------------- 6) gated delta-rule scan ----------------
// grid = H_*2 (head, dv-half), block = 256: thread = dv_l(64) x qr(4),
// owns S[qr+4i][dv], i<16. Double-buffered smem staging, 1-step prefetch.
__global__ __launch_bounds__(256) void scan_kernel(const float* __restrict__ q,
                                                   const float* __restrict__ k,
                                                   const float* __restrict__ v,
                                                   const float* __restrict__ beta,
                                                   const float* __restrict__ gdec,
                                                   float* __restrict__ o) {
    int h = blockIdx.x >> 1;
    int dvh = blockIdx.x & 1;
    int tid = threadIdx.x;
    int dv_l = tid >> 2, qr = tid & 3;
    int dv = dvh * 64 + dv_l;

    __shared__ float ks[2][64], qs[2][64], vs[2][64], sc[2][2];

    float S[16];
    #pragma unroll
    for (int i = 0; i < 16; i++) S[i] = 0.f;

    // prefetch step 0
    float pre = 0.f;
    {
        int t = 0;
        if (tid < 64)       pre = k[(size_t)(t * H_ + h) * DK_ + tid];
        else if (tid < 128) pre = q[(size_t)(t * H_ + h) * DK_ + tid - 64];
        else if (tid < 192) pre = v[(size_t)(t * H_ + h) * DV_ + dvh * 64 + tid - 128];
        else if (tid == 192) pre = __expf(gdec[t * H_ + h]);
        else if (tid == 193) pre = beta[t * H_ + h];
    }

    for (int t = 0; t < T_; t++) {
        int b = t & 1;
        if (tid < 64)        ks[b][tid] = pre;
        else if (tid < 128)  qs[b][tid - 64] = pre;
        else if (tid < 192)  vs[b][tid - 128] = pre;
        else if (tid == 192) sc[b][0] = pre;
        else if (tid == 193) sc[b][1] = pre;
        if (t + 1 < T_) {
            int tn = t + 1;
            if (tid < 64)       pre = k[(size_t)(tn * H_ + h) * DK_ + tid];
            else if (tid < 128) pre = q[(size_t)(tn * H_ + h) * DK_ + tid - 64];
            else if (tid < 192) pre = v[(size_t)(tn * H_ + h) * DV_ + dvh * 64 + tid - 128];
            else if (tid == 192) pre = __expf(gdec[tn * H_ + h]);
            else if (tid == 193) pre = beta[tn * H_ + h];
        }
        __syncthreads();

        float eg = sc[b][0], bt = sc[b][1], vv = vs[b][dv_l];
        float kr[16];
        float kv = 0.f;
        #pragma unroll
        for (int i = 0; i < 16; i++) {
            kr[i] = ks[b][qr + 4 * i];
            S[i] *= eg;
            kv = fmaf(kr[i], S[i], kv);
        }
        kv += __shfl_xor_sync(0xffffffffu, kv, 1);
        kv += __shfl_xor_sync(0xffffffffu, kv, 2);
        float vn = (vv - kv) * bt;
        float oo = 0.f;
        #pragma unroll
        for (int i = 0; i < 16; i++) {
            S[i] = fmaf(kr[i], vn, S[i]);
            oo = fmaf(qs[b][qr + 4 * i], S[i], oo);
        }
        oo += __shfl_xor_sync(0xffffffffu, oo, 1);
        oo += __shfl_xor_sync(0xffffffffu, oo, 2);
        if (qr == 0) o[(size_t)(t * H_ + h) * DV_ + dv] = oo;
    }
}

// ---------------- 7) gated RMSNorm over head output + silu gate -------------
__global__ void onorm_kernel(const float* __restrict__ o,
                             const float* __restrict__ gate,
                             const float* __restrict__ onw,
                             float* __restrict__ o2) {
    int th = blockIdx.x;                 // t*H + h
    int i = threadIdx.x;                 // 0..127 = dv
    float val = o[(size_t)th * DV_ + i];
    float ss = val * val;
    for (int off = 16; off > 0; off >>= 1) ss += __shfl_xor_sync(0xffffffffu, ss, off);
    __shared__ float red[4];
    int warp = i >> 5, lane = i & 31;
    if (lane == 0) red[warp] = ss;
    __syncthreads();
    float tot = red[0] + red[1] + red[2] + red[3];
    float scale = rsqrtf(tot / (float)DV_ + 1e-5f);
    float gv = gate[(size_t)th * DV_ + i];
    o2[(size_t)th * DV_ + i] = val * scale * onw[i] * (gv / (1.f + expf(-gv)));
}

// ---------------- launcher ----------------
extern "C" void kernel_launch(void* const* d_in, const int* in_sizes, int n_in,
                              void* d_out, int out_size) {
    const float* hidden    = (const float*)d_in[0];
    const float* norm_w    = (const float*)d_in[1];
    const float* q_w       = (const float*)d_in[2];
    const float* k_w       = (const float*)d_in[3];
    const float* v_w       = (const float*)d_in[4];
    const float* a_w       = (const float*)d_in[5];
    const float* b_w       = (const float*)d_in[6];
    const float* g_w       = (const float*)d_in[7];
    const float* dt_bias   = (const float*)d_in[8];
    const float* A_log     = (const float*)d_in[9];
    const float* conv_q_w  = (const float*)d_in[10];
    const float* conv_k_w  = (const float*)d_in[11];
    const float* conv_v_w  = (const float*)d_in[12];
    const float* o_norm_w  = (const float*)d_in[13];
    const float* o_proj_w  = (const float*)d_in[14];
    const float* out_proj_w= (const float*)d_in[15];
    float* out = (float*)d_out;

    float *px, *pqpre, *pkpre, *pvpre, *pq, *pk, *pv, *pgate, *pbeta, *pgdec, *po, *po2, *py1;
    cudaGetSymbolAddress((void**)&px,    g_x);
    cudaGetSymbolAddress((void**)&pqpre, g_qpre);
    cudaGetSymbolAddress((void**)&pkpre, g_kpre);
    cudaGetSymbolAddress((void**)&pvpre, g_vpre);
    cudaGetSymbolAddress((void**)&pq,    g_q);
    cudaGetSymbolAddress((void**)&pk,    g_k);
    cudaGetSymbolAddress((void**)&pv,    g_v);
    cudaGetSymbolAddress((void**)&pgate, g_gate);
    cudaGetSymbolAddress((void**)&pbeta, g_beta);
    cudaGetSymbolAddress((void**)&pgdec, g_gdec);
    cudaGetSymbolAddress((void**)&po,    g_o);
    cudaGetSymbolAddress((void**)&po2,   g_o2);
    cudaGetSymbolAddress((void**)&py1,   g_y1);

    // 1) RMSNorm
    rmsnorm_kernel<<<T_, 256>>>(hidden, norm_w, px);

    // 2) projections
    gemm_xwT<<<dim3(QKD_/BN, T_/BM), 256>>>(px, q_w, pqpre, T_, QKD_, HID_);
    gemm_xwT<<<dim3(QKD_/BN, T_/BM), 256>>>(px, k_w, pkpre, T_, QKD_, HID_);
    gemm_xwT<<<dim3(VAL_/BN, T_/BM), 256>>>(px, v_w, pvpre, T_, VAL_, HID_);
    gemm_xwT<<<dim3(VAL_/BN, T_/BM), 256>>>(px, g_w, pgate, T_, VAL_, HID_);
    ab_kernel<<<T_, 256>>>(px, a_w, b_w, dt_bias, A_log, pbeta, pgdec);

    // 3) convs + silu
    conv_silu_kernel<<<(T_*QKD_ + 255)/256, 256>>>(pqpre, conv_q_w, pq, QKD_);
    conv_silu_kernel<<<(T_*QKD_ + 255)/256, 256>>>(pkpre, conv_k_w, pk, QKD_);
    conv_silu_kernel<<<(T_*VAL_ + 255)/256, 256>>>(pvpre, conv_v_w, pv, VAL_);

    // 4) q/k normalize (+ k DC removal)
    qknorm_kernel<<<(T_*H_*32)/256, 256>>>(pq, pk);

    // 5) scan
    scan_kernel<<<H_*2, 256>>>(pq, pk, pv, pbeta, pgdec, po);

    // 6) gated output norm
    onorm_kernel<<<T_*H_, 128>>>(po, pgate, o_norm_w, po2);

    // 7) output projections
    gemm_xwT<<<dim3(HID_/BN, T_/BM), 256>>>(po2, o_proj_w, py1, T_, HID_, VAL_);
    gemm_xwT<<<dim3(HID_/BN, T_/BM), 256>>>(py1, out_proj_w, out, T_, HID_, HID_);
}

// round 4
// speedup vs baseline: 1.0036x; 1.0036x over previous
#include <cuda_runtime.h>
#include <cuda_bf16.h>
#include <math.h>

// ---------------- problem dims (fixed) ----------------
#define T_    2048
#define HID_  1024
#define H_    16
#define DK_   64
#define DV_   128
#define VAL_  2048   // H_*DV_
#define QKD_  1024   // H_*DK_
#define CONV_ 4

// ---------------- scratch (device globals; no allocation allowed) ---------
__device__ float g_x    [T_*HID_];   // rmsnormed input
__device__ float g_qpre [T_*QKD_];
__device__ float g_kpre [T_*QKD_];
__device__ float g_vpre [T_*VAL_];
__device__ float g_q    [T_*QKD_];
__device__ float g_k    [T_*QKD_];
__device__ float g_v    [T_*VAL_];
__device__ float g_gate [T_*VAL_];
__device__ float g_beta [T_*H_];
__device__ float g_gdec [T_*H_];
__device__ float g_o    [T_*VAL_];
__device__ float g_o2   [T_*VAL_];
__device__ float g_y1   [T_*HID_];

// ---------------- helpers ----------------
__device__ __forceinline__ float sigmoidf_(float x) { return 1.f / (1.f + __expf(-x)); }
__device__ __forceinline__ float siluf_(float x)    { return x * sigmoidf_(x); }

// ---------------- 1) RMSNorm ----------------
__global__ void rmsnorm_kernel(const float* __restrict__ h,
                               const float* __restrict__ w,
                               float* __restrict__ x) {
    int t = blockIdx.x;
    const float* row = h + (size_t)t * HID_;
    float ss = 0.f;
    for (int i = threadIdx.x; i < HID_; i += 256) { float v = row[i]; ss += v * v; }
    // block reduce (256 threads)
    for (int off = 16; off > 0; off >>= 1) ss += __shfl_xor_sync(0xffffffffu, ss, off);
    __shared__ float red[8];
    int warp = threadIdx.x >> 5, lane = threadIdx.x & 31;
    if (lane == 0) red[warp] = ss;
    __syncthreads();
    float tot = 0.f;
    if (warp == 0) {
        tot = (lane < 8) ? red[lane] : 0.f;
        for (int off = 4; off > 0; off >>= 1) tot += __shfl_xor_sync(0xffffffffu, tot, off);
        if (lane == 0) red[0] = tot;
    }
    __syncthreads();
    float scale = rsqrtf(red[0] / (float)HID_ + 1e-6f);
    for (int i = threadIdx.x; i < HID_; i += 256)
        x[(size_t)t * HID_ + i] = row[i] * scale * w[i];
}

// ---------------- 2) generic GEMM  C[M,N] = X[M,K] @ W[N,K]^T ----------------
// All M,N,K multiples of 64/16 here, no bounds checks.
#define BM 64
#define BN 64
#define BK 16
__global__ __launch_bounds__(256) void gemm_xwT(const float* __restrict__ X,
                                                const float* __restrict__ W,
                                                float* __restrict__ C,
                                                int M, int N, int K) {
    __shared__ float Xs[BM][BK + 1];
    __shared__ float Ws[BN][BK + 1];
    int tid = threadIdx.x;
    int tx = tid & 15, ty = tid >> 4;
    int m0 = blockIdx.y * BM, n0 = blockIdx.x * BN;
    int lr = tid >> 2;          // 0..63
    int lc = (tid & 3) * 4;     // 0,4,8,12
    float acc[4][4] = {};
    const float* Xp = X + (size_t)(m0 + lr) * K + lc;
    const float* Wp = W + (size_t)(n0 + lr) * K + lc;
    for (int k0 = 0; k0 < K; k0 += BK) {
        float4 xa = *(const float4*)(Xp + k0);
        float4 wa = *(const float4*)(Wp + k0);
        Xs[lr][lc + 0] = xa.x; Xs[lr][lc + 1] = xa.y; Xs[lr][lc + 2] = xa.z; Xs[lr][lc + 3] = xa.w;
        Ws[lr][lc + 0] = wa.x; Ws[lr][lc + 1] = wa.y; Ws[lr][lc + 2] = wa.z; Ws[lr][lc + 3] = wa.w;
        __syncthreads();
        #pragma unroll
        for (int kk = 0; kk < BK; kk++) {
            float a[4], b[4];
            #pragma unroll
            for (int i = 0; i < 4; i++) a[i] = Xs[ty * 4 + i][kk];
            #pragma unroll
            for (int j = 0; j < 4; j++) b[j] = Ws[tx * 4 + j][kk];
            #pragma unroll
            for (int i = 0; i < 4; i++)
                #pragma unroll
                for (int j = 0; j < 4; j++)
                    acc[i][j] = fmaf(a[i], b[j], acc[i][j]);
        }
        __syncthreads();
    }
    #pragma unroll
    for (int i = 0; i < 4; i++) {
        float4 v; v.x = acc[i][0]; v.y = acc[i][1]; v.z = acc[i][2]; v.w = acc[i][3];
        *(float4*)&C[(size_t)(m0 + ty * 4 + i) * N + n0 + tx * 4] = v;
    }
}

// ---------------- 3) beta / g decay from a_w,b_w (N=16, done directly) -------
__global__ void ab_kernel(const float* __restrict__ x,
                          const float* __restrict__ a_w,
                          const float* __restrict__ b_w,
                          const float* __restrict__ dt_bias,
                          const float* __restrict__ A_log,
                          float* __restrict__ beta,
                          float* __restrict__ gdec) {
    __shared__ float xs[HID_];
    int t = blockIdx.x;
    for (int i = threadIdx.x; i < HID_; i += 256) xs[i] = x[(size_t)t * HID_ + i];
    __syncthreads();
    int warp = threadIdx.x >> 5, lane = threadIdx.x & 31;
    for (int h = warp; h < H_; h += 8) {
        float da = 0.f, db = 0.f;
        const float* ap = a_w + (size_t)h * HID_;
        const float* bp = b_w + (size_t)h * HID_;
        for (int i = lane; i < HID_; i += 32) {
            float xv = xs[i];
            da = fmaf(xv, ap[i], da);
            db = fmaf(xv, bp[i], db);
        }
        for (int off = 16; off > 0; off >>= 1) {
            da += __shfl_xor_sync(0xffffffffu, da, off);
            db += __shfl_xor_sync(0xffffffffu, db, off);
        }
        if (lane == 0) {
            beta[t * H_ + h] = 1.f / (1.f + expf(-db));
            float z = da + dt_bias[h];
            float sp = (z > 20.f) ? z : log1pf(expf(z));
            gdec[t * H_ + h] = -expf(A_log[h]) * sp;
        }
    }
}

// ---------------- 4) causal depthwise conv (K=4) + silu ----------------
__global__ void conv_silu_kernel(const float* __restrict__ in,
                                 const float* __restrict__ w,
                                 float* __restrict__ out, int C) {
    int idx = blockIdx.x * blockDim.x + threadIdx.x;
    if (idx >= T_ * C) return;
    int t = idx / C, c = idx - t * C;
    float acc = 0.f;
    #pragma unroll
    for (int i = 0; i < CONV_; i++) {
        int tt = t - (CONV_ - 1) + i;
        if (tt >= 0) acc = fmaf(in[(size_t)tt * C + c], w[c * CONV_ + i], acc);
    }
    out[idx] = acc * (1.f / (1.f + __expf(-acc)));
}

// ---------------- 5) k DC-removal + q/k L2 normalize ----------------
__global__ void qknorm_kernel(float* __restrict__ q, float* __restrict__ k) {
    int gw = (blockIdx.x * blockDim.x + threadIdx.x) >> 5;  // one warp per (t,h)
    int lane = threadIdx.x & 31;
    if (gw >= T_ * H_) return;
    float* kp = k + (size_t)gw * DK_;
    float k0 = kp[lane], k1 = kp[lane + 32];
    float s = k0 + k1;
    for (int off = 16; off > 0; off >>= 1) s += __shfl_xor_sync(0xffffffffu, s, off);
    float mean = s * (1.f / 64.f);
    k0 -= mean; k1 -= mean;
    float ss = k0 * k0 + k1 * k1;
    for (int off = 16; off > 0; off >>= 1) ss += __shfl_xor_sync(0xffffffffu, ss, off);
    float sc = rsqrtf(ss + 1e-6f);
    kp[lane] = k0 * sc; kp[lane + 32] = k1 * sc;

    float* qp = q + (size_t)gw * DK_;
    float q0 = qp[lane], q1 = qp[lane + 32];
    float qq = q0 * q0 + q1 * q1;
    for (int off = 16; off > 0; off >>= 1) qq += __shfl_xor_sync(0xffffffffu, qq, off);
    float qs = rsqrtf(qq + 1e-6f) * 0.125f;   // * DK^-0.5
    qp[lane] = q0 * qs; qp[lane + 32] = q1 * qs;
}

// ---------------- 6) gated delta-rule scan ----------------
// grid = H_*2 (head, dv-half), block = 256: thread = dv_l(64) x qr(4),
// owns S[qr+4i][dv], i<16. Double-buffered smem staging, 1-step prefetch.
__global__ __launch_bounds__(256) void scan_kernel(const float* __restrict__ q,
                                                   const float* __restrict__ k,
                                                   const float* __restrict__ v,
                                                   const float* __restrict__ beta,
                                                   const float* __restrict__ gdec,
                                                   float* __restrict__ o) {
    int h = blockIdx.x >> 1;
    int dvh = blockIdx.x & 1;
    int tid = threadIdx.x;
    int dv_l = tid >> 2, qr = tid & 3;
    int dv = dvh * 64 + dv_l;

    __shared__ float ks[2][64], qs[2][64], vs[2][64], sc[2][2];

    float S[16];
    #pragma unroll
    for (int i = 0; i < 16; i++) S[i] = 0.f;

    // prefetch step 0
    float pre = 0.f;
    {
        int t = 0;
        if (tid < 64)       pre = k[(size_t)(t * H_ + h) * DK_ + tid];
        else if (tid < 128) pre = q[(size_t)(t * H_ + h) * DK_ + tid - 64];
        else if (tid < 192) pre = v[(size_t)(t * H_ + h) * DV_ + dvh * 64 + tid - 128];
        else if (tid == 192) pre = __expf(gdec[t * H_ + h]);
        else if (tid == 193) pre = beta[t * H_ + h];
    }

    for (int t = 0; t < T_; t++) {
        int b = t & 1;
        if (tid < 64)        ks[b][tid] = pre;
        else if (tid < 128)  qs[b][tid - 64] = pre;
        else if (tid < 192)  vs[b][tid - 128] = pre;
        else if (tid == 192) sc[b][0] = pre;
        else if (tid == 193) sc[b][1] = pre;
        if (t + 1 < T_) {
            int tn = t + 1;
            if (tid < 64)       pre = k[(size_t)(tn * H_ + h) * DK_ + tid];
            else if (tid < 128) pre = q[(size_t)(tn * H_ + h) * DK_ + tid - 64];
            else if (tid < 192) pre = v[(size_t)(tn * H_ + h) * DV_ + dvh * 64 + tid - 128];
            else if (tid == 192) pre = __expf(gdec[tn * H_ + h]);
            else if (tid == 193) pre = beta[tn * H_ + h];
        }
        __syncthreads();

        float eg = sc[b][0], bt = sc[b][1], vv = vs[b][dv_l];
        float kr[16];
        float kv = 0.f;
        #pragma unroll
        for (int i = 0; i < 16; i++) {
            kr[i] = ks[b][qr + 4 * i];
            S[i] *= eg;
            kv = fmaf(kr[i], S[i], kv);
        }
        kv += __shfl_xor_sync(0xffffffffu, kv, 1);
        kv += __shfl_xor_sync(0xffffffffu, kv, 2);
        float vn = (vv - kv) * bt;
        float oo = 0.f;
        #pragma unroll
        for (int i = 0; i < 16; i++) {
            S[i] = fmaf(kr[i], vn, S[i]);
            oo = fmaf(qs[b][qr + 4 * i], S[i], oo);
        }
        oo += __shfl_xor_sync(0xffffffffu, oo, 1);
        oo += __shfl_xor_sync(0xffffffffu, oo, 2);
        if (qr == 0) o[(size_t)(t * H_ + h) * DV_ + dv] = oo;
    }
}

// ---------------- 7) gated RMSNorm over head output + silu gate -------------
__global__ void onorm_kernel(const float* __restrict__ o,
                             const float* __restrict__ gate,
                             const float* __restrict__ onw,
                             float* __restrict__ o2) {
    int th = blockIdx.x;                 // t*H + h
    int i = threadIdx.x;                 // 0..127 = dv
    float val = o[(size_t)th * DV_ + i];
    float ss = val * val;
    for (int off = 16; off > 0; off >>= 1) ss += __shfl_xor_sync(0xffffffffu, ss, off);
    __shared__ float red[4];
    int warp = i >> 5, lane = i & 31;
    if (lane == 0) red[warp] = ss;
    __syncthreads();
    float tot = red[0] + red[1] + red[2] + red[3];
    float scale = rsqrtf(tot / (float)DV_ + 1e-5f);
    float gv = gate[(size_t)th * DV_ + i];
    o2[(size_t)th * DV_ + i] = val * scale * onw[i] * (gv / (1.f + expf(-gv)));
}

// ---------------- launcher ----------------
extern "C" void kernel_launch(void* const* d_in, const int* in_sizes, int n_in,
                              void* d_out, int out_size) {
    const float* hidden    = (const float*)d_in[0];
    const float* norm_w    = (const float*)d_in[1];
    const float* q_w       = (const float*)d_in[2];
    const float* k_w       = (const float*)d_in[3];
    const float* v_w       = (const float*)d_in[4];
    const float* a_w       = (const float*)d_in[5];
    const float* b_w       = (const float*)d_in[6];
    const float* g_w       = (const float*)d_in[7];
    const float* dt_bias   = (const float*)d_in[8];
    const float* A_log     = (const float*)d_in[9];
    const float* conv_q_w  = (const float*)d_in[10];
    const float* conv_k_w  = (const float*)d_in[11];
    const float* conv_v_w  = (const float*)d_in[12];
    const float* o_norm_w  = (const float*)d_in[13];
    const float* o_proj_w  = (const float*)d_in[14];
    const float* out_proj_w= (const float*)d_in[15];
    float* out = (float*)d_out;

    float *px, *pqpre, *pkpre, *pvpre, *pq, *pk, *pv, *pgate, *pbeta, *pgdec, *po, *po2, *py1;
    cudaGetSymbolAddress((void**)&px,    g_x);
    cudaGetSymbolAddress((void**)&pqpre, g_qpre);
    cudaGetSymbolAddress((void**)&pkpre, g_kpre);
    cudaGetSymbolAddress((void**)&pvpre, g_vpre);
    cudaGetSymbolAddress((void**)&pq,    g_q);
    cudaGetSymbolAddress((void**)&pk,    g_k);
    cudaGetSymbolAddress((void**)&pv,    g_v);
    cudaGetSymbolAddress((void**)&pgate, g_gate);
    cudaGetSymbolAddress((void**)&pbeta, g_beta);
    cudaGetSymbolAddress((void**)&pgdec, g_gdec);
    cudaGetSymbolAddress((void**)&po,    g_o);
    cudaGetSymbolAddress((void**)&po2,   g_o2);
    cudaGetSymbolAddress((void**)&py1,   g_y1);

    // 1) RMSNorm
    rmsnorm_kernel<<<T_, 256>>>(hidden, norm_w, px);

    // 2) projections
    gemm_xwT<<<dim3(QKD_/BN, T_/BM), 256>>>(px, q_w, pqpre, T_, QKD_, HID_);
    gemm_xwT<<<dim3(QKD_/BN, T_/BM), 256>>>(px, k_w, pkpre, T_, QKD_, HID_);
    gemm_xwT<<<dim3(VAL_/BN, T_/BM), 256>>>(px, v_w, pvpre, T_, VAL_, HID_);
    gemm_xwT<<<dim3(VAL_/BN, T_/BM), 256>>>(px, g_w, pgate, T_, VAL_, HID_);
    ab_kernel<<<T_, 256>>>(px, a_w, b_w, dt_bias, A_log, pbeta, pgdec);

    // 3) convs + silu
    conv_silu_kernel<<<(T_*QKD_ + 255)/256, 256>>>(pqpre, conv_q_w, pq, QKD_);
    conv_silu_kernel<<<(T_*QKD_ + 255)/256, 256>>>(pkpre, conv_k_w, pk, QKD_);
    conv_silu_kernel<<<(T_*VAL_ + 255)/256, 256>>>(pvpre, conv_v_w, pv, VAL_);

    // 4) q/k normalize (+ k DC removal)
    qknorm_kernel<<<(T_*H_*32)/256, 256>>>(pq, pk);

    // 5) scan
    scan_kernel<<<H_*2, 256>>>(pq, pk, pv, pbeta, pgdec, po);

    // 6) gated output norm
    onorm_kernel<<<T_*H_, 128>>>(po, pgate, o_norm_w, po2);

    // 7) output projections
    gemm_xwT<<<dim3(HID_/BN, T_/BM), 256>>>(po2, o_proj_w, py1, T_, HID_, VAL_);
    gemm_xwT<<<dim3(HID_/BN, T_/BM), 256>>>(py1, out_proj_w, out, T_, HID_, HID_);
}

// round 5
// speedup vs baseline: 1.8726x; 1.8659x over previous
#include <cuda_runtime.h>
#include <cuda_bf16.h>
#include <math.h>

// ---------------- problem dims (fixed) ----------------
#define T_    2048
#define HID_  1024
#define H_    16
#define DK_   64
#define DV_   128
#define VAL_  2048   // H_*DV_
#define QKD_  1024   // H_*DK_
#define CONV_ 4
#define BIGN_ 6144   // q(1024)+k(1024)+v(2048)+g(2048)

// ---------------- scratch (device globals; no allocation allowed) ---------
__device__ float g_x    [T_*HID_];    // rmsnormed input
__device__ float g_big  [T_*BIGN_];   // fused qkvg projection output
__device__ float g_q    [T_*QKD_];
__device__ float g_k    [T_*QKD_];
__device__ float g_v    [T_*VAL_];
__device__ float g_beta [T_*H_];
__device__ float g_gdec [T_*H_];
__device__ float g_o    [T_*VAL_];
__device__ float g_o2   [T_*VAL_];
__device__ float g_y1   [T_*HID_];

// ---------------- 1) RMSNorm ----------------
__global__ void rmsnorm_kernel(const float* __restrict__ h,
                               const float* __restrict__ w,
                               float* __restrict__ x) {
    int t = blockIdx.x;
    const float* row = h + (size_t)t * HID_;
    float ss = 0.f;
    for (int i = threadIdx.x; i < HID_; i += 256) { float v = row[i]; ss += v * v; }
    for (int off = 16; off > 0; off >>= 1) ss += __shfl_xor_sync(0xffffffffu, ss, off);
    __shared__ float red[8];
    int warp = threadIdx.x >> 5, lane = threadIdx.x & 31;
    if (lane == 0) red[warp] = ss;
    __syncthreads();
    float tot = 0.f;
    if (warp == 0) {
        tot = (lane < 8) ? red[lane] : 0.f;
        for (int off = 4; off > 0; off >>= 1) tot += __shfl_xor_sync(0xffffffffu, tot, off);
        if (lane == 0) red[0] = tot;
    }
    __syncthreads();
    float scale = rsqrtf(red[0] / (float)HID_ + 1e-6f);
    for (int i = threadIdx.x; i < HID_; i += 256)
        x[(size_t)t * HID_ + i] = row[i] * scale * w[i];
}

// ---------------- 2) 128x128x16 SGEMM core ----------------
// C[M,N] = X[M,K] @ W[N,K]^T. 256 threads, 8x8 per-thread fragments,
// warp tiling 2x4 warps of 64x32, lane tiling 8x4 of 8x8.
#define GBM 128
#define GBN 128
#define GBK 16
#define GPAD 132

__device__ __forceinline__ void gemm_tile(const float* __restrict__ Xt,  // X + m0*K
                                          const float* __restrict__ Wt,  // W + n0*K
                                          float* __restrict__ Ct,        // C + m0*ldc + n0
                                          int K, int ldc) {
    __shared__ float As[2][GBK][GPAD];
    __shared__ float Bs[2][GBK][GPAD];
    int tid = threadIdx.x;
    int lr = tid >> 2;            // 0..63
    int lc = (tid & 3) * 4;       // 0,4,8,12
    int wid = tid >> 5, lane = tid & 31;
    int rb = (wid >> 2) * 64 + (lane >> 2) * 8;   // row base 0..120
    int cb = (wid & 3) * 32 + (lane & 3) * 8;     // col base 0..120

    const float* xp0 = Xt + (size_t)lr * K + lc;
    const float* xp1 = Xt + (size_t)(lr + 64) * K + lc;
    const float* wp0 = Wt + (size_t)lr * K + lc;
    const float* wp1 = Wt + (size_t)(lr + 64) * K + lc;

    float acc[8][8];
    #pragma unroll
    for (int i = 0; i < 8; i++)
        #pragma unroll
        for (int j = 0; j < 8; j++) acc[i][j] = 0.f;

    // preload tile 0
    float4 xa0 = *(const float4*)xp0;
    float4 xa1 = *(const float4*)xp1;
    float4 wa0 = *(const float4*)wp0;
    float4 wa1 = *(const float4*)wp1;
    As[0][lc+0][lr]    = xa0.x; As[0][lc+1][lr]    = xa0.y; As[0][lc+2][lr]    = xa0.z; As[0][lc+3][lr]    = xa0.w;
    As[0][lc+0][lr+64] = xa1.x; As[0][lc+1][lr+64] = xa1.y; As[0][lc+2][lr+64] = xa1.z; As[0][lc+3][lr+64] = xa1.w;
    Bs[0][lc+0][lr]    = wa0.x; Bs[0][lc+1][lr]    = wa0.y; Bs[0][lc+2][lr]    = wa0.z; Bs[0][lc+3][lr]    = wa0.w;
    Bs[0][lc+0][lr+64] = wa1.x; Bs[0][lc+1][lr+64] = wa1.y; Bs[0][lc+2][lr+64] = wa1.z; Bs[0][lc+3][lr+64] = wa1.w;
    __syncthreads();

    int buf = 0;
    int nk = K / GBK;
    for (int it = 0; it < nk; it++) {
        bool more = (it + 1 < nk);
        if (more) {
            int k0 = (it + 1) * GBK;
            xa0 = *(const float4*)(xp0 + k0);
            xa1 = *(const float4*)(xp1 + k0);
            wa0 = *(const float4*)(wp0 + k0);
            wa1 = *(const float4*)(wp1 + k0);
        }
        #pragma unroll
        for (int kk = 0; kk < GBK; kk++) {
            float a[8], b[8];
            *(float4*)&a[0] = *(const float4*)&As[buf][kk][rb];
            *(float4*)&a[4] = *(const float4*)&As[buf][kk][rb + 4];
            *(float4*)&b[0] = *(const float4*)&Bs[buf][kk][cb];
            *(float4*)&b[4] = *(const float4*)&Bs[buf][kk][cb + 4];
            #pragma unroll
            for (int i = 0; i < 8; i++)
                #pragma unroll
                for (int j = 0; j < 8; j++)
                    acc[i][j] = fmaf(a[i], b[j], acc[i][j]);
        }
        if (more) {
            int nb = buf ^ 1;
            As[nb][lc+0][lr]    = xa0.x; As[nb][lc+1][lr]    = xa0.y; As[nb][lc+2][lr]    = xa0.z; As[nb][lc+3][lr]    = xa0.w;
            As[nb][lc+0][lr+64] = xa1.x; As[nb][lc+1][lr+64] = xa1.y; As[nb][lc+2][lr+64] = xa1.z; As[nb][lc+3][lr+64] = xa1.w;
            Bs[nb][lc+0][lr]    = wa0.x; Bs[nb][lc+1][lr]    = wa0.y; Bs[nb][lc+2][lr]    = wa0.z; Bs[nb][lc+3][lr]    = wa0.w;
            Bs[nb][lc+0][lr+64] = wa1.x; Bs[nb][lc+1][lr+64] = wa1.y; Bs[nb][lc+2][lr+64] = wa1.z; Bs[nb][lc+3][lr+64] = wa1.w;
            __syncthreads();
            buf = nb;
        }
    }
    #pragma unroll
    for (int i = 0; i < 8; i++) {
        float4 v0 = make_float4(acc[i][0], acc[i][1], acc[i][2], acc[i][3]);
        float4 v1 = make_float4(acc[i][4], acc[i][5], acc[i][6], acc[i][7]);
        *(float4*)&Ct[(size_t)(rb + i) * ldc + cb]     = v0;
        *(float4*)&Ct[(size_t)(rb + i) * ldc + cb + 4] = v1;
    }
}

__global__ __launch_bounds__(256, 2) void gemm128(const float* __restrict__ X,
                                                  const float* __restrict__ W,
                                                  float* __restrict__ C,
                                                  int K, int ldc) {
    gemm_tile(X + (size_t)blockIdx.y * GBM * K,
              W + (size_t)blockIdx.x * GBN * K,
              C + (size_t)blockIdx.y * GBM * ldc + blockIdx.x * GBN,
              K, ldc);
}

// fused q/k/v/g projection: N=6144 columns, per-block weight segment select
__global__ __launch_bounds__(256, 2) void gemm128_qkvg(const float* __restrict__ X,
                                                       const float* __restrict__ wq,
                                                       const float* __restrict__ wk,
                                                       const float* __restrict__ wv,
                                                       const float* __restrict__ wg,
                                                       float* __restrict__ C, int K) {
    int n0 = blockIdx.x * GBN;
    const float* W; int ln;
    if (n0 < 1024)      { W = wq; ln = n0; }
    else if (n0 < 2048) { W = wk; ln = n0 - 1024; }
    else if (n0 < 4096) { W = wv; ln = n0 - 2048; }
    else                { W = wg; ln = n0 - 4096; }
    gemm_tile(X + (size_t)blockIdx.y * GBM * K,
              W + (size_t)ln * K,
              C + (size_t)blockIdx.y * GBM * BIGN_ + n0,
              K, BIGN_);
}

// ---------------- 3) beta / g decay ----------------
__global__ void ab_kernel(const float* __restrict__ x,
                          const float* __restrict__ a_w,
                          const float* __restrict__ b_w,
                          const float* __restrict__ dt_bias,
                          const float* __restrict__ A_log,
                          float* __restrict__ beta,
                          float* __restrict__ gdec) {
    __shared__ float xs[HID_];
    int t = blockIdx.x;
    for (int i = threadIdx.x; i < HID_; i += 256) xs[i] = x[(size_t)t * HID_ + i];
    __syncthreads();
    int warp = threadIdx.x >> 5, lane = threadIdx.x & 31;
    for (int h = warp; h < H_; h += 8) {
        float da = 0.f, db = 0.f;
        const float* ap = a_w + (size_t)h * HID_;
        const float* bp = b_w + (size_t)h * HID_;
        for (int i = lane; i < HID_; i += 32) {
            float xv = xs[i];
            da = fmaf(xv, ap[i], da);
            db = fmaf(xv, bp[i], db);
        }
        for (int off = 16; off > 0; off >>= 1) {
            da += __shfl_xor_sync(0xffffffffu, da, off);
            db += __shfl_xor_sync(0xffffffffu, db, off);
        }
        if (lane == 0) {
            beta[t * H_ + h] = 1.f / (1.f + expf(-db));
            float z = da + dt_bias[h];
            float sp = (z > 20.f) ? z : log1pf(expf(z));
            gdec[t * H_ + h] = -expf(A_log[h]) * sp;
        }
    }
}

// ---------------- 4) causal depthwise conv (K=4) + silu ----------------
__global__ void conv_silu_kernel(const float* __restrict__ in, int ldin,
                                 const float* __restrict__ w,
                                 float* __restrict__ out, int C) {
    int idx = blockIdx.x * blockDim.x + threadIdx.x;
    if (idx >= T_ * C) return;
    int t = idx / C, c = idx - t * C;
    float acc = 0.f;
    #pragma unroll
    for (int i = 0; i < CONV_; i++) {
        int tt = t - (CONV_ - 1) + i;
        if (tt >= 0) acc = fmaf(in[(size_t)tt * ldin + c], w[c * CONV_ + i], acc);
    }
    out[idx] = acc * (1.f / (1.f + __expf(-acc)));
}

// ---------------- 5) k DC-removal + q/k L2 normalize ----------------
__global__ void qknorm_kernel(float* __restrict__ q, float* __restrict__ k) {
    int gw = (blockIdx.x * blockDim.x + threadIdx.x) >> 5;  // one warp per (t,h)
    int lane = threadIdx.x & 31;
    if (gw >= T_ * H_) return;
    float* kp = k + (size_t)gw * DK_;
    float k0 = kp[lane], k1 = kp[lane + 32];
    float s = k0 + k1;
    for (int off = 16; off > 0; off >>= 1) s += __shfl_xor_sync(0xffffffffu, s, off);
    float mean = s * (1.f / 64.f);
    k0 -= mean; k1 -= mean;
    float ss = k0 * k0 + k1 * k1;
    for (int off = 16; off > 0; off >>= 1) ss += __shfl_xor_sync(0xffffffffu, ss, off);
    float sc = rsqrtf(ss + 1e-6f);
    kp[lane] = k0 * sc; kp[lane + 32] = k1 * sc;

    float* qp = q + (size_t)gw * DK_;
    float q0 = qp[lane], q1 = qp[lane + 32];
    float qq = q0 * q0 + q1 * q1;
    for (int off = 16; off > 0; off >>= 1) qq += __shfl_xor_sync(0xffffffffu, qq, off);
    float qs = rsqrtf(qq + 1e-6f) * 0.125f;   // * DK^-0.5
    qp[lane] = q0 * qs; qp[lane + 32] = q1 * qs;
}

// ---------------- 6) gated delta-rule scan ----------------
// grid = H_*2 (head, dv-half), block = 256: thread = dv_l(64) x qr(4),
// thread owns S[qr*16 + i][dv], i<16 (contiguous dk slice -> float4 LDS).
// cp.async 4-stage ring, 2 timesteps per stage, 1 barrier per 2 steps.
__global__ __launch_bounds__(256) void scan_kernel(const float* __restrict__ q,
                                                   const float* __restrict__ k,
                                                   const float* __restrict__ v,
                                                   const float* __restrict__ beta,
                                                   const float* __restrict__ gdec,
                                                   float* __restrict__ o) {
    int h = blockIdx.x >> 1;
    int dvh = blockIdx.x & 1;
    int tid = threadIdx.x;
    int dv_l = tid >> 2, qr = tid & 3;
    int dv = dvh * 64 + dv_l;

    __shared__ float ks[4][2][64], qs[4][2][64], vs[4][2][64], gb[4][2][2];

    // copy roles: tid 0-31 -> k, 32-63 -> q, 64-95 -> v, 96-99 -> scalars
    int role  = tid >> 5;
    int sstep = (tid >> 4) & 1;
    int chunk = tid & 15;

    float S[16];
    #pragma unroll
    for (int i = 0; i < 16; i++) S[i] = 0.f;

    const int NP = T_ / 2;

    #define ISSUE_PAIR(P) do {                                                      \
        int set_ = (P) & 3;                                                         \
        int t0_ = (P) * 2;                                                          \
        if (role == 0) {                                                            \
            unsigned d = (unsigned)__cvta_generic_to_shared(&ks[set_][sstep][chunk*4]); \
            const float* sp = k + ((size_t)(t0_ + sstep) * H_ + h) * DK_ + chunk*4;  \
            asm volatile("cp.async.cg.shared.global [%0], [%1], 16;\n" :: "r"(d), "l"(sp)); \
        } else if (role == 1) {                                                     \
            unsigned d = (unsigned)__cvta_generic_to_shared(&qs[set_][sstep][chunk*4]); \
            const float* sp = q + ((size_t)(t0_ + sstep) * H_ + h) * DK_ + chunk*4;  \
            asm volatile("cp.async.cg.shared.global [%0], [%1], 16;\n" :: "r"(d), "l"(sp)); \
        } else if (role == 2) {                                                     \
            unsigned d = (unsigned)__cvta_generic_to_shared(&vs[set_][sstep][chunk*4]); \
            const float* sp = v + ((size_t)(t0_ + sstep) * H_ + h) * DV_ + dvh*64 + chunk*4; \
            asm volatile("cp.async.cg.shared.global [%0], [%1], 16;\n" :: "r"(d), "l"(sp)); \
        } else if (role == 3 && sstep == 0 && chunk < 4) {                          \
            int s2 = chunk & 1; int which = chunk >> 1;                             \
            unsigned d = (unsigned)__cvta_generic_to_shared(&gb[set_][s2][which]);  \
            const float* sp = (which ? beta : gdec) + (size_t)(t0_ + s2) * H_ + h;  \
            asm volatile("cp.async.ca.shared.global [%0], [%1], 4;\n" :: "r"(d), "l"(sp)); \
        }                                                                           \
    } while (0)

    // prologue: pairs 0,1,2
    #pragma unroll
    for (int p = 0; p < 3; p++) {
        ISSUE_PAIR(p);
        asm volatile("cp.async.commit_group;\n");
    }

    for (int p = 0; p < NP; p++) {
        asm volatile("cp.async.wait_group 2;\n");
        __syncthreads();
        if (p + 3 < NP) ISSUE_PAIR(p + 3);
        asm volatile("cp.async.commit_group;\n");
        int set = p & 3;
        #pragma unroll
        for (int s = 0; s < 2; s++) {
            float eg = __expf(gb[set][s][0]);
            float bt = gb[set][s][1];
            float vv = vs[set][s][dv_l];
            float kr[16];
            #pragma unroll
            for (int j = 0; j < 4; j++)
                *(float4*)&kr[j*4] = *(const float4*)&ks[set][s][qr*16 + j*4];
            float kv0 = 0.f, kv1 = 0.f, kv2 = 0.f, kv3 = 0.f;
            #pragma unroll
            for (int j = 0; j < 4; j++) {
                S[j*4+0] *= eg; kv0 = fmaf(kr[j*4+0], S[j*4+0], kv0);
                S[j*4+1] *= eg; kv1 = fmaf(kr[j*4+1], S[j*4+1], kv1);
                S[j*4+2] *= eg; kv2 = fmaf(kr[j*4+2], S[j*4+2], kv2);
                S[j*4+3] *= eg; kv3 = fmaf(kr[j*4+3], S[j*4+3], kv3);
            }
            float kv = (kv0 + kv1) + (kv2 + kv3);
            kv += __shfl_xor_sync(0xffffffffu, kv, 1);
            kv += __shfl_xor_sync(0xffffffffu, kv, 2);
            float vn = (vv - kv) * bt;
            float qv[16];
            #pragma unroll
            for (int j = 0; j < 4; j++)
                *(float4*)&qv[j*4] = *(const float4*)&qs[set][s][qr*16 + j*4];
            float o0 = 0.f, o1 = 0.f, o2 = 0.f, o3 = 0.f;
            #pragma unroll
            for (int j = 0; j < 4; j++) {
                S[j*4+0] = fmaf(kr[j*4+0], vn, S[j*4+0]); o0 = fmaf(qv[j*4+0], S[j*4+0], o0);
                S[j*4+1] = fmaf(kr[j*4+1], vn, S[j*4+1]); o1 = fmaf(qv[j*4+1], S[j*4+1], o1);
                S[j*4+2] = fmaf(kr[j*4+2], vn, S[j*4+2]); o2 = fmaf(qv[j*4+2], S[j*4+2], o2);
                S[j*4+3] = fmaf(kr[j*4+3], vn, S[j*4+3]); o3 = fmaf(qv[j*4+3], S[j*4+3], o3);
            }
            float oo = (o0 + o1) + (o2 + o3);
            oo += __shfl_xor_sync(0xffffffffu, oo, 1);
            oo += __shfl_xor_sync(0xffffffffu, oo, 2);
            if (qr == 0) o[((size_t)(p*2 + s) * H_ + h) * DV_ + dv] = oo;
        }
    }
    #undef ISSUE_PAIR
}

// ---------------- 7) gated RMSNorm over head output + silu gate ------------
__global__ void onorm_kernel(const float* __restrict__ o,
                             const float* __restrict__ gateb,   // g_big + 4096, ld=BIGN_
                             const float* __restrict__ onw,
                             float* __restrict__ o2) {
    int th = blockIdx.x;                 // t*H + h
    int t = th >> 4, h = th & 15;
    int i = threadIdx.x;                 // 0..127 = dv
    float val = o[(size_t)th * DV_ + i];
    float ss = val * val;
    for (int off = 16; off > 0; off >>= 1) ss += __shfl_xor_sync(0xffffffffu, ss, off);
    __shared__ float red[4];
    int warp = i >> 5, lane = i & 31;
    if (lane == 0) red[warp] = ss;
    __syncthreads();
    float tot = red[0] + red[1] + red[2] + red[3];
    float scale = rsqrtf(tot / (float)DV_ + 1e-5f);
    float gv = gateb[(size_t)t * BIGN_ + h * DV_ + i];
    o2[(size_t)th * DV_ + i] = val * scale * onw[i] * (gv / (1.f + expf(-gv)));
}

// ---------------- launcher ----------------
extern "C" void kernel_launch(void* const* d_in, const int* in_sizes, int n_in,
                              void* d_out, int out_size) {
    const float* hidden    = (const float*)d_in[0];
    const float* norm_w    = (const float*)d_in[1];
    const float* q_w       = (const float*)d_in[2];
    const float* k_w       = (const float*)d_in[3];
    const float* v_w       = (const float*)d_in[4];
    const float* a_w       = (const float*)d_in[5];
    const float* b_w       = (const float*)d_in[6];
    const float* g_w       = (const float*)d_in[7];
    const float* dt_bias   = (const float*)d_in[8];
    const float* A_log     = (const float*)d_in[9];
    const float* conv_q_w  = (const float*)d_in[10];
    const float* conv_k_w  = (const float*)d_in[11];
    const float* conv_v_w  = (const float*)d_in[12];
    const float* o_norm_w  = (const float*)d_in[13];
    const float* o_proj_w  = (const float*)d_in[14];
    const float* out_proj_w= (const float*)d_in[15];
    float* out = (float*)d_out;

    float *px, *pbig, *pq, *pk, *pv, *pbeta, *pgdec, *po, *po2, *py1;
    cudaGetSymbolAddress((void**)&px,    g_x);
    cudaGetSymbolAddress((void**)&pbig,  g_big);
    cudaGetSymbolAddress((void**)&pq,    g_q);
    cudaGetSymbolAddress((void**)&pk,    g_k);
    cudaGetSymbolAddress((void**)&pv,    g_v);
    cudaGetSymbolAddress((void**)&pbeta, g_beta);
    cudaGetSymbolAddress((void**)&pgdec, g_gdec);
    cudaGetSymbolAddress((void**)&po,    g_o);
    cudaGetSymbolAddress((void**)&po2,   g_o2);
    cudaGetSymbolAddress((void**)&py1,   g_y1);

    // 1) RMSNorm
    rmsnorm_kernel<<<T_, 256>>>(hidden, norm_w, px);

    // 2) fused q/k/v/g projection  [T,1024]x[6144,1024]^T -> [T,6144]
    gemm128_qkvg<<<dim3(BIGN_/GBN, T_/GBM), 256>>>(px, q_w, k_w, v_w, g_w, pbig, HID_);
    ab_kernel<<<T_, 256>>>(px, a_w, b_w, dt_bias, A_log, pbeta, pgdec);

    // 3) convs + silu (strided reads from fused buffer)
    conv_silu_kernel<<<(T_*QKD_ + 255)/256, 256>>>(pbig + 0,    BIGN_, conv_q_w, pq, QKD_);
    conv_silu_kernel<<<(T_*QKD_ + 255)/256, 256>>>(pbig + 1024, BIGN_, conv_k_w, pk, QKD_);
    conv_silu_kernel<<<(T_*VAL_ + 255)/256, 256>>>(pbig + 2048, BIGN_, conv_v_w, pv, VAL_);

    // 4) q/k normalize (+ k DC removal)
    qknorm_kernel<<<(T_*H_*32)/256, 256>>>(pq, pk);

    // 5) scan
    scan_kernel<<<H_*2, 256>>>(pq, pk, pv, pbeta, pgdec, po);

    // 6) gated output norm (gate read straight from fused buffer)
    onorm_kernel<<<T_*H_, 128>>>(po, pbig + 4096, o_norm_w, po2);

    // 7) output projections
    gemm128<<<dim3(HID_/GBN, T_/GBM), 256>>>(po2, o_proj_w, py1, VAL_, HID_);
    gemm128<<<dim3(HID_/GBN, T_/GBM), 256>>>(py1, out_proj_w, out, HID_, HID_);
}

// round 6
// speedup vs baseline: 2.6242x; 1.4014x over previous
#include <cuda_runtime.h>
#include <cuda_bf16.h>
#include <math.h>

// ---------------- problem dims (fixed) ----------------
#define T_    2048
#define HID_  1024
#define H_    16
#define DK_   64
#define DV_   128
#define VAL_  2048   // H_*DV_
#define QKD_  1024   // H_*DK_
#define CONV_ 4
#define BIGN_ 6144   // q(1024)+k(1024)+v(2048)+g(2048)

// ---------------- scratch (device globals; no allocation allowed) ---------
__device__ float g_x    [T_*HID_];    // rmsnormed input
__device__ float g_big  [T_*BIGN_];   // fused qkvg projection output
__device__ float g_q    [T_*QKD_];
__device__ float g_k    [T_*QKD_];
__device__ float g_v    [T_*VAL_];
__device__ float g_beta [T_*H_];
__device__ float g_gdec [T_*H_];
__device__ float g_o    [T_*VAL_];
__device__ float g_o2   [T_*VAL_];
__device__ float g_y1   [T_*HID_];

// ---------------- 1) RMSNorm ----------------
__global__ void rmsnorm_kernel(const float* __restrict__ h,
                               const float* __restrict__ w,
                               float* __restrict__ x) {
    int t = blockIdx.x;
    const float* row = h + (size_t)t * HID_;
    float ss = 0.f;
    for (int i = threadIdx.x; i < HID_; i += 256) { float v = row[i]; ss += v * v; }
    for (int off = 16; off > 0; off >>= 1) ss += __shfl_xor_sync(0xffffffffu, ss, off);
    __shared__ float red[8];
    int warp = threadIdx.x >> 5, lane = threadIdx.x & 31;
    if (lane == 0) red[warp] = ss;
    __syncthreads();
    float tot = 0.f;
    if (warp == 0) {
        tot = (lane < 8) ? red[lane] : 0.f;
        for (int off = 4; off > 0; off >>= 1) tot += __shfl_xor_sync(0xffffffffu, tot, off);
        if (lane == 0) red[0] = tot;
    }
    __syncthreads();
    float scale = rsqrtf(red[0] / (float)HID_ + 1e-6f);
    for (int i = threadIdx.x; i < HID_; i += 256)
        x[(size_t)t * HID_ + i] = row[i] * scale * w[i];
}

// ---------------- 2) TF32 tensor-core GEMM  C[M,N] = X[M,K] @ W[N,K]^T -----
// 128x128 block, BK=16, 256 threads = 8 warps (2M x 4N), warp tile 64x32,
// mma.sync m16n8k8 tf32. Operands in smem as [row][k] stride 20 (BK+4):
// conflict-free fragment LDS, vectorized STS.128 with inline fp32->tf32 cvt.
#define GBM 128
#define GBN 128
#define GBK 16
#define LDA 20

__device__ __forceinline__ unsigned f2tf32(float f) {
    unsigned u; asm("cvt.rna.tf32.f32 %0, %1;" : "=r"(u) : "f"(f)); return u;
}
__device__ __forceinline__ uint4 cvt4(float4 v) {
    uint4 u; u.x = f2tf32(v.x); u.y = f2tf32(v.y); u.z = f2tf32(v.z); u.w = f2tf32(v.w);
    return u;
}

#define MMA_TF32(C, A, B)                                                     \
    asm volatile("mma.sync.aligned.m16n8k8.row.col.f32.tf32.tf32.f32 "        \
                 "{%0,%1,%2,%3}, {%4,%5,%6,%7}, {%8,%9}, {%0,%1,%2,%3};"      \
                 : "+f"((C)[0]), "+f"((C)[1]), "+f"((C)[2]), "+f"((C)[3])     \
                 : "r"((A)[0]), "r"((A)[1]), "r"((A)[2]), "r"((A)[3]),        \
                   "r"((B)[0]), "r"((B)[1]))

__device__ __forceinline__ void gemm_tile_tf32(const float* __restrict__ Xt, // X + m0*K
                                               const float* __restrict__ Wt, // W + n0*K
                                               float* __restrict__ Ct,       // C + m0*ldc + n0
                                               int K, int ldc) {
    __shared__ unsigned As[2][GBM][LDA];
    __shared__ unsigned Bs[2][GBN][LDA];
    int tid = threadIdx.x;
    int lr = tid >> 2;            // 0..63
    int lc = (tid & 3) * 4;       // 0,4,8,12
    int wid = tid >> 5, lane = tid & 31;
    int gid = lane >> 2, tig = lane & 3;
    int wm = (wid >> 2) * 64;     // warp m base 0/64
    int wn = (wid & 3) * 32;      // warp n base 0..96

    const float* xp0 = Xt + (size_t)lr * K + lc;
    const float* xp1 = Xt + (size_t)(lr + 64) * K + lc;
    const float* wp0 = Wt + (size_t)lr * K + lc;
    const float* wp1 = Wt + (size_t)(lr + 64) * K + lc;

    float acc[16][4];
    #pragma unroll
    for (int i = 0; i < 16; i++)
        #pragma unroll
        for (int j = 0; j < 4; j++) acc[i][j] = 0.f;

    // preload tile 0
    float4 xa0 = *(const float4*)xp0;
    float4 xa1 = *(const float4*)xp1;
    float4 wa0 = *(const float4*)wp0;
    float4 wa1 = *(const float4*)wp1;
    *(uint4*)&As[0][lr][lc]      = cvt4(xa0);
    *(uint4*)&As[0][lr + 64][lc] = cvt4(xa1);
    *(uint4*)&Bs[0][lr][lc]      = cvt4(wa0);
    *(uint4*)&Bs[0][lr + 64][lc] = cvt4(wa1);
    __syncthreads();

    int buf = 0;
    int nk = K / GBK;
    for (int it = 0; it < nk; it++) {
        bool more = (it + 1 < nk);
        if (more) {
            int k0 = (it + 1) * GBK;
            xa0 = *(const float4*)(xp0 + k0);
            xa1 = *(const float4*)(xp1 + k0);
            wa0 = *(const float4*)(wp0 + k0);
            wa1 = *(const float4*)(wp1 + k0);
        }
        #pragma unroll
        for (int k8 = 0; k8 < 2; k8++) {
            int kk = k8 * 8;
            unsigned a[4][4], b[4][2];
            #pragma unroll
            for (int mt = 0; mt < 4; mt++) {
                int m = wm + mt * 16 + gid;
                a[mt][0] = As[buf][m][kk + tig];
                a[mt][1] = As[buf][m + 8][kk + tig];
                a[mt][2] = As[buf][m][kk + 4 + tig];
                a[mt][3] = As[buf][m + 8][kk + 4 + tig];
            }
            #pragma unroll
            for (int nt = 0; nt < 4; nt++) {
                int n = wn + nt * 8 + gid;
                b[nt][0] = Bs[buf][n][kk + tig];
                b[nt][1] = Bs[buf][n][kk + 4 + tig];
            }
            #pragma unroll
            for (int mt = 0; mt < 4; mt++)
                #pragma unroll
                for (int nt = 0; nt < 4; nt++)
                    MMA_TF32(acc[mt * 4 + nt], a[mt], b[nt]);
        }
        if (more) {
            int nb = buf ^ 1;
            *(uint4*)&As[nb][lr][lc]      = cvt4(xa0);
            *(uint4*)&As[nb][lr + 64][lc] = cvt4(xa1);
            *(uint4*)&Bs[nb][lr][lc]      = cvt4(wa0);
            *(uint4*)&Bs[nb][lr + 64][lc] = cvt4(wa1);
            __syncthreads();
            buf = nb;
        }
    }

    // epilogue: c0/c1 -> (row, col..col+1), c2/c3 -> (row+8, ...)
    #pragma unroll
    for (int mt = 0; mt < 4; mt++) {
        int row = wm + mt * 16 + gid;
        #pragma unroll
        for (int nt = 0; nt < 4; nt++) {
            int col = wn + nt * 8 + tig * 2;
            float* c = acc[mt * 4 + nt];
            *(float2*)&Ct[(size_t)row * ldc + col]       = make_float2(c[0], c[1]);
            *(float2*)&Ct[(size_t)(row + 8) * ldc + col] = make_float2(c[2], c[3]);
        }
    }
}

__global__ __launch_bounds__(256) void gemm128(const float* __restrict__ X,
                                               const float* __restrict__ W,
                                               float* __restrict__ C,
                                               int K, int ldc) {
    gemm_tile_tf32(X + (size_t)blockIdx.y * GBM * K,
                   W + (size_t)blockIdx.x * GBN * K,
                   C + (size_t)blockIdx.y * GBM * ldc + blockIdx.x * GBN,
                   K, ldc);
}

// fused q/k/v/g projection: N=6144 columns, per-block weight segment select
__global__ __launch_bounds__(256) void gemm128_qkvg(const float* __restrict__ X,
                                                    const float* __restrict__ wq,
                                                    const float* __restrict__ wk,
                                                    const float* __restrict__ wv,
                                                    const float* __restrict__ wg,
                                                    float* __restrict__ C, int K) {
    int n0 = blockIdx.x * GBN;
    const float* W; int ln;
    if (n0 < 1024)      { W = wq; ln = n0; }
    else if (n0 < 2048) { W = wk; ln = n0 - 1024; }
    else if (n0 < 4096) { W = wv; ln = n0 - 2048; }
    else                { W = wg; ln = n0 - 4096; }
    gemm_tile_tf32(X + (size_t)blockIdx.y * GBM * K,
                   W + (size_t)ln * K,
                   C + (size_t)blockIdx.y * GBM * BIGN_ + n0,
                   K, BIGN_);
}

// ---------------- 3) beta / g decay ----------------
__global__ void ab_kernel(const float* __restrict__ x,
                          const float* __restrict__ a_w,
                          const float* __restrict__ b_w,
                          const float* __restrict__ dt_bias,
                          const float* __restrict__ A_log,
                          float* __restrict__ beta,
                          float* __restrict__ gdec) {
    __shared__ float xs[HID_];
    int t = blockIdx.x;
    for (int i = threadIdx.x; i < HID_; i += 256) xs[i] = x[(size_t)t * HID_ + i];
    __syncthreads();
    int warp = threadIdx.x >> 5, lane = threadIdx.x & 31;
    for (int h = warp; h < H_; h += 8) {
        float da = 0.f, db = 0.f;
        const float* ap = a_w + (size_t)h * HID_;
        const float* bp = b_w + (size_t)h * HID_;
        for (int i = lane; i < HID_; i += 32) {
            float xv = xs[i];
            da = fmaf(xv, ap[i], da);
            db = fmaf(xv, bp[i], db);
        }
        for (int off = 16; off > 0; off >>= 1) {
            da += __shfl_xor_sync(0xffffffffu, da, off);
            db += __shfl_xor_sync(0xffffffffu, db, off);
        }
        if (lane == 0) {
            beta[t * H_ + h] = 1.f / (1.f + expf(-db));
            float z = da + dt_bias[h];
            float sp = (z > 20.f) ? z : log1pf(expf(z));
            gdec[t * H_ + h] = -expf(A_log[h]) * sp;
        }
    }
}

// ---------------- 4) causal depthwise conv (K=4) + silu ----------------
__global__ void conv_silu_kernel(const float* __restrict__ in, int ldin,
                                 const float* __restrict__ w,
                                 float* __restrict__ out, int C) {
    int idx = blockIdx.x * blockDim.x + threadIdx.x;
    if (idx >= T_ * C) return;
    int t = idx / C, c = idx - t * C;
    float acc = 0.f;
    #pragma unroll
    for (int i = 0; i < CONV_; i++) {
        int tt = t - (CONV_ - 1) + i;
        if (tt >= 0) acc = fmaf(in[(size_t)tt * ldin + c], w[c * CONV_ + i], acc);
    }
    out[idx] = acc * (1.f / (1.f + __expf(-acc)));
}

// ---------------- 5) k DC-removal + q/k L2 normalize ----------------
__global__ void qknorm_kernel(float* __restrict__ q, float* __restrict__ k) {
    int gw = (blockIdx.x * blockDim.x + threadIdx.x) >> 5;  // one warp per (t,h)
    int lane = threadIdx.x & 31;
    if (gw >= T_ * H_) return;
    float* kp = k + (size_t)gw * DK_;
    float k0 = kp[lane], k1 = kp[lane + 32];
    float s = k0 + k1;
    for (int off = 16; off > 0; off >>= 1) s += __shfl_xor_sync(0xffffffffu, s, off);
    float mean = s * (1.f / 64.f);
    k0 -= mean; k1 -= mean;
    float ss = k0 * k0 + k1 * k1;
    for (int off = 16; off > 0; off >>= 1) ss += __shfl_xor_sync(0xffffffffu, ss, off);
    float sc = rsqrtf(ss + 1e-6f);
    kp[lane] = k0 * sc; kp[lane + 32] = k1 * sc;

    float* qp = q + (size_t)gw * DK_;
    float q0 = qp[lane], q1 = qp[lane + 32];
    float qq = q0 * q0 + q1 * q1;
    for (int off = 16; off > 0; off >>= 1) qq += __shfl_xor_sync(0xffffffffu, qq, off);
    float qs = rsqrtf(qq + 1e-6f) * 0.125f;   // * DK^-0.5
    qp[lane] = q0 * qs; qp[lane + 32] = q1 * qs;
}

// ---------------- 6) gated delta-rule scan ----------------
// grid = H_*2 (head, dv-half), block = 256: thread = dv_l(64) x qr(4),
// thread owns S[qr*16 + i][dv], i<16 (contiguous dk slice -> float4 LDS).
// cp.async 4-stage ring, 2 timesteps per stage, 1 barrier per 2 steps.
__global__ __launch_bounds__(256) void scan_kernel(const float* __restrict__ q,
                                                   const float* __restrict__ k,
                                                   const float* __restrict__ v,
                                                   const float* __restrict__ beta,
                                                   const float* __restrict__ gdec,
                                                   float* __restrict__ o) {
    int h = blockIdx.x >> 1;
    int dvh = blockIdx.x & 1;
    int tid = threadIdx.x;
    int dv_l = tid >> 2, qr = tid & 3;
    int dv = dvh * 64 + dv_l;

    __shared__ float ks[4][2][64], qs[4][2][64], vs[4][2][64], gb[4][2][2];

    // copy roles: tid 0-31 -> k, 32-63 -> q, 64-95 -> v, 96-99 -> scalars
    int role  = tid >> 5;
    int sstep = (tid >> 4) & 1;
    int chunk = tid & 15;

    float S[16];
    #pragma unroll
    for (int i = 0; i < 16; i++) S[i] = 0.f;

    const int NP = T_ / 2;

    #define ISSUE_PAIR(P) do {                                                      \
        int set_ = (P) & 3;                                                         \
        int t0_ = (P) * 2;                                                          \
        if (role == 0) {                                                            \
            unsigned d = (unsigned)__cvta_generic_to_shared(&ks[set_][sstep][chunk*4]); \
            const float* sp = k + ((size_t)(t0_ + sstep) * H_ + h) * DK_ + chunk*4;  \
            asm volatile("cp.async.cg.shared.global [%0], [%1], 16;\n" :: "r"(d), "l"(sp)); \
        } else if (role == 1) {                                                     \
            unsigned d = (unsigned)__cvta_generic_to_shared(&qs[set_][sstep][chunk*4]); \
            const float* sp = q + ((size_t)(t0_ + sstep) * H_ + h) * DK_ + chunk*4;  \
            asm volatile("cp.async.cg.shared.global [%0], [%1], 16;\n" :: "r"(d), "l"(sp)); \
        } else if (role == 2) {                                                     \
            unsigned d = (unsigned)__cvta_generic_to_shared(&vs[set_][sstep][chunk*4]); \
            const float* sp = v + ((size_t)(t0_ + sstep) * H_ + h) * DV_ + dvh*64 + chunk*4; \
            asm volatile("cp.async.cg.shared.global [%0], [%1], 16;\n" :: "r"(d), "l"(sp)); \
        } else if (role == 3 && sstep == 0 && chunk < 4) {                          \
            int s2 = chunk & 1; int which = chunk >> 1;                             \
            unsigned d = (unsigned)__cvta_generic_to_shared(&gb[set_][s2][which]);  \
            const float* sp = (which ? beta : gdec) + (size_t)(t0_ + s2) * H_ + h;  \
            asm volatile("cp.async.ca.shared.global [%0], [%1], 4;\n" :: "r"(d), "l"(sp)); \
        }                                                                           \
    } while (0)

    // prologue: pairs 0,1,2
    #pragma unroll
    for (int p = 0; p < 3; p++) {
        ISSUE_PAIR(p);
        asm volatile("cp.async.commit_group;\n");
    }

    for (int p = 0; p < NP; p++) {
        asm volatile("cp.async.wait_group 2;\n");
        __syncthreads();
        if (p + 3 < NP) ISSUE_PAIR(p + 3);
        asm volatile("cp.async.commit_group;\n");
        int set = p & 3;
        #pragma unroll
        for (int s = 0; s < 2; s++) {
            float eg = __expf(gb[set][s][0]);
            float bt = gb[set][s][1];
            float vv = vs[set][s][dv_l];
            float kr[16];
            #pragma unroll
            for (int j = 0; j < 4; j++)
                *(float4*)&kr[j*4] = *(const float4*)&ks[set][s][qr*16 + j*4];
            float kv0 = 0.f, kv1 = 0.f, kv2 = 0.f, kv3 = 0.f;
            #pragma unroll
            for (int j = 0; j < 4; j++) {
                S[j*4+0] *= eg; kv0 = fmaf(kr[j*4+0], S[j*4+0], kv0);
                S[j*4+1] *= eg; kv1 = fmaf(kr[j*4+1], S[j*4+1], kv1);
                S[j*4+2] *= eg; kv2 = fmaf(kr[j*4+2], S[j*4+2], kv2);
                S[j*4+3] *= eg; kv3 = fmaf(kr[j*4+3], S[j*4+3], kv3);
            }
            float kv = (kv0 + kv1) + (kv2 + kv3);
            kv += __shfl_xor_sync(0xffffffffu, kv, 1);
            kv += __shfl_xor_sync(0xffffffffu, kv, 2);
            float vn = (vv - kv) * bt;
            float qv[16];
            #pragma unroll
            for (int j = 0; j < 4; j++)
                *(float4*)&qv[j*4] = *(const float4*)&qs[set][s][qr*16 + j*4];
            float o0 = 0.f, o1 = 0.f, o2 = 0.f, o3 = 0.f;
            #pragma unroll
            for (int j = 0; j < 4; j++) {
                S[j*4+0] = fmaf(kr[j*4+0], vn, S[j*4+0]); o0 = fmaf(qv[j*4+0], S[j*4+0], o0);
                S[j*4+1] = fmaf(kr[j*4+1], vn, S[j*4+1]); o1 = fmaf(qv[j*4+1], S[j*4+1], o1);
                S[j*4+2] = fmaf(kr[j*4+2], vn, S[j*4+2]); o2 = fmaf(qv[j*4+2], S[j*4+2], o2);
                S[j*4+3] = fmaf(kr[j*4+3], vn, S[j*4+3]); o3 = fmaf(qv[j*4+3], S[j*4+3], o3);
            }
            float oo = (o0 + o1) + (o2 + o3);
            oo += __shfl_xor_sync(0xffffffffu, oo, 1);
            oo += __shfl_xor_sync(0xffffffffu, oo, 2);
            if (qr == 0) o[((size_t)(p*2 + s) * H_ + h) * DV_ + dv] = oo;
        }
    }
    #undef ISSUE_PAIR
}

// ---------------- 7) gated RMSNorm over head output + silu gate ------------
__global__ void onorm_kernel(const float* __restrict__ o,
                             const float* __restrict__ gateb,   // g_big + 4096, ld=BIGN_
                             const float* __restrict__ onw,
                             float* __restrict__ o2) {
    int th = blockIdx.x;                 // t*H + h
    int t = th >> 4, h = th & 15;
    int i = threadIdx.x;                 // 0..127 = dv
    float val = o[(size_t)th * DV_ + i];
    float ss = val * val;
    for (int off = 16; off > 0; off >>= 1) ss += __shfl_xor_sync(0xffffffffu, ss, off);
    __shared__ float red[4];
    int warp = i >> 5, lane = i & 31;
    if (lane == 0) red[warp] = ss;
    __syncthreads();
    float tot = red[0] + red[1] + red[2] + red[3];
    float scale = rsqrtf(tot / (float)DV_ + 1e-5f);
    float gv = gateb[(size_t)t * BIGN_ + h * DV_ + i];
    o2[(size_t)th * DV_ + i] = val * scale * onw[i] * (gv / (1.f + expf(-gv)));
}

// ---------------- launcher ----------------
extern "C" void kernel_launch(void* const* d_in, const int* in_sizes, int n_in,
                              void* d_out, int out_size) {
    const float* hidden    = (const float*)d_in[0];
    const float* norm_w    = (const float*)d_in[1];
    const float* q_w       = (const float*)d_in[2];
    const float* k_w       = (const float*)d_in[3];
    const float* v_w       = (const float*)d_in[4];
    const float* a_w       = (const float*)d_in[5];
    const float* b_w       = (const float*)d_in[6];
    const float* g_w       = (const float*)d_in[7];
    const float* dt_bias   = (const float*)d_in[8];
    const float* A_log     = (const float*)d_in[9];
    const float* conv_q_w  = (const float*)d_in[10];
    const float* conv_k_w  = (const float*)d_in[11];
    const float* conv_v_w  = (const float*)d_in[12];
    const float* o_norm_w  = (const float*)d_in[13];
    const float* o_proj_w  = (const float*)d_in[14];
    const float* out_proj_w= (const float*)d_in[15];
    float* out = (float*)d_out;

    float *px, *pbig, *pq, *pk, *pv, *pbeta, *pgdec, *po, *po2, *py1;
    cudaGetSymbolAddress((void**)&px,    g_x);
    cudaGetSymbolAddress((void**)&pbig,  g_big);
    cudaGetSymbolAddress((void**)&pq,    g_q);
    cudaGetSymbolAddress((void**)&pk,    g_k);
    cudaGetSymbolAddress((void**)&pv,    g_v);
    cudaGetSymbolAddress((void**)&pbeta, g_beta);
    cudaGetSymbolAddress((void**)&pgdec, g_gdec);
    cudaGetSymbolAddress((void**)&po,    g_o);
    cudaGetSymbolAddress((void**)&po2,   g_o2);
    cudaGetSymbolAddress((void**)&py1,   g_y1);

    // 1) RMSNorm
    rmsnorm_kernel<<<T_, 256>>>(hidden, norm_w, px);

    // 2) fused q/k/v/g projection  [T,1024]x[6144,1024]^T -> [T,6144]  (tf32 MMA)
    gemm128_qkvg<<<dim3(BIGN_/GBN, T_/GBM), 256>>>(px, q_w, k_w, v_w, g_w, pbig, HID_);
    ab_kernel<<<T_, 256>>>(px, a_w, b_w, dt_bias, A_log, pbeta, pgdec);

    // 3) convs + silu (strided reads from fused buffer)
    conv_silu_kernel<<<(T_*QKD_ + 255)/256, 256>>>(pbig + 0,    BIGN_, conv_q_w, pq, QKD_);
    conv_silu_kernel<<<(T_*QKD_ + 255)/256, 256>>>(pbig + 1024, BIGN_, conv_k_w, pk, QKD_);
    conv_silu_kernel<<<(T_*VAL_ + 255)/256, 256>>>(pbig + 2048, BIGN_, conv_v_w, pv, VAL_);

    // 4) q/k normalize (+ k DC removal)
    qknorm_kernel<<<(T_*H_*32)/256, 256>>>(pq, pk);

    // 5) scan
    scan_kernel<<<H_*2, 256>>>(pq, pk, pv, pbeta, pgdec, po);

    // 6) gated output norm (gate read straight from fused buffer)
    onorm_kernel<<<T_*H_, 128>>>(po, pbig + 4096, o_norm_w, po2);

    // 7) output projections (tf32 MMA)
    gemm128<<<dim3(HID_/GBN, T_/GBM), 256>>>(po2, o_proj_w, py1, VAL_, HID_);
    gemm128<<<dim3(HID_/GBN, T_/GBM), 256>>>(py1, out_proj_w, out, HID_, HID_);
}

// round 7
// speedup vs baseline: 3.6311x; 1.3837x over previous
#include <cuda_runtime.h>
#include <cuda_bf16.h>
#include <math.h>

// ---------------- problem dims (fixed) ----------------
#define T_    2048
#define HID_  1024
#define H_    16
#define DK_   64
#define DV_   128
#define VAL_  2048   // H_*DV_
#define QKD_  1024   // H_*DK_
#define CONV_ 4
#define BIGN_ 6144   // q(1024)+k(1024)+v(2048)+g(2048)

// ---------------- scratch (device globals; no allocation allowed) ---------
__device__ float g_x    [T_*HID_];    // rmsnormed input
__device__ float g_rs   [T_];         // per-row inverse rms
__device__ float g_big  [T_*BIGN_];   // fused qkvg projection output
__device__ float g_q    [T_*QKD_];
__device__ float g_k    [T_*QKD_];
__device__ float g_v    [T_*VAL_];
__device__ float g_beta [T_*H_];
__device__ float g_eg   [T_*H_];      // exp(g) decay, precomputed
__device__ float g_o    [T_*VAL_];
__device__ float g_o2   [T_*VAL_];
__device__ float g_y1   [T_*HID_];

// ---------------- 1a) RMSNorm reduce: one warp per row ----------------
__global__ void rms_reduce_kernel(const float* __restrict__ h,
                                  float* __restrict__ rs) {
    int row = blockIdx.x * 8 + (threadIdx.x >> 5);
    int lane = threadIdx.x & 31;
    const float4* p = (const float4*)(h + (size_t)row * HID_);
    float ss = 0.f;
    #pragma unroll
    for (int i = 0; i < 8; i++) {
        float4 v = p[lane + i * 32];
        ss += v.x * v.x + v.y * v.y + v.z * v.z + v.w * v.w;
    }
    for (int off = 16; off > 0; off >>= 1) ss += __shfl_xor_sync(0xffffffffu, ss, off);
    if (lane == 0) rs[row] = rsqrtf(ss / (float)HID_ + 1e-6f);
}

// ---------------- 1b) RMSNorm apply (vectorized) ----------------
__global__ void rms_apply_kernel(const float* __restrict__ h,
                                 const float* __restrict__ rs,
                                 const float* __restrict__ w,
                                 float* __restrict__ x) {
    int idx = blockIdx.x * blockDim.x + threadIdx.x;   // float4 index
    int t = idx >> 8;                                  // HID_/4 = 256
    float s = rs[t];
    float4 hv = ((const float4*)h)[idx];
    float4 wv = ((const float4*)w)[idx & 255];
    float4 o;
    o.x = hv.x * s * wv.x; o.y = hv.y * s * wv.y;
    o.z = hv.z * s * wv.z; o.w = hv.w * s * wv.w;
    ((float4*)x)[idx] = o;
}

// ---------------- TF32 helpers ----------------
__device__ __forceinline__ unsigned f2tf32(float f) {
    unsigned u; asm("cvt.rna.tf32.f32 %0, %1;" : "=r"(u) : "f"(f)); return u;
}
__device__ __forceinline__ uint4 cvt4(float4 v) {
    uint4 u; u.x = f2tf32(v.x); u.y = f2tf32(v.y); u.z = f2tf32(v.z); u.w = f2tf32(v.w);
    return u;
}
#define MMA_TF32(C, A, B)                                                     \
    asm volatile("mma.sync.aligned.m16n8k8.row.col.f32.tf32.tf32.f32 "        \
                 "{%0,%1,%2,%3}, {%4,%5,%6,%7}, {%8,%9}, {%0,%1,%2,%3};"      \
                 : "+f"((C)[0]), "+f"((C)[1]), "+f"((C)[2]), "+f"((C)[3])     \
                 : "r"((A)[0]), "r"((A)[1]), "r"((A)[2]), "r"((A)[3]),        \
                   "r"((B)[0]), "r"((B)[1]))

#define GBK 16
#define LDA 20

// ---------------- 2a) qkvg GEMM: 128x256 block, 8 warps, warp tile 64x64 ---
// C[T,BIGN] = X[T,K] @ Wseg[N,K]^T with per-block weight segment select.
__global__ __launch_bounds__(256, 1) void gemm128_qkvg(const float* __restrict__ X,
                                                       const float* __restrict__ wq,
                                                       const float* __restrict__ wk,
                                                       const float* __restrict__ wv,
                                                       const float* __restrict__ wg,
                                                       float* __restrict__ C, int K) {
    int n0 = blockIdx.x * 256;
    const float* W; int ln;
    if (n0 < 1024)      { W = wq; ln = n0; }
    else if (n0 < 2048) { W = wk; ln = n0 - 1024; }
    else if (n0 < 4096) { W = wv; ln = n0 - 2048; }
    else                { W = wg; ln = n0 - 4096; }
    const float* Xt = X + (size_t)blockIdx.y * 128 * K;
    const float* Wt = W + (size_t)ln * K;
    float* Ct = C + (size_t)blockIdx.y * 128 * BIGN_ + n0;

    __shared__ unsigned As[2][128][LDA];
    __shared__ unsigned Bs[2][256][LDA];
    int tid = threadIdx.x;
    int lr = tid >> 2;            // 0..63
    int lc = (tid & 3) * 4;       // 0,4,8,12
    int wid = tid >> 5, lane = tid & 31;
    int gid = lane >> 2, tig = lane & 3;
    int wm = (wid >> 2) * 64;     // 0 / 64
    int wn = (wid & 3) * 64;      // 0..192

    const float* xp0 = Xt + (size_t)lr * K + lc;
    const float* xp1 = Xt + (size_t)(lr + 64) * K + lc;
    const float* wp0 = Wt + (size_t)lr * K + lc;
    const float* wp1 = Wt + (size_t)(lr + 64) * K + lc;
    const float* wp2 = Wt + (size_t)(lr + 128) * K + lc;
    const float* wp3 = Wt + (size_t)(lr + 192) * K + lc;

    float acc[32][4];
    #pragma unroll
    for (int i = 0; i < 32; i++)
        #pragma unroll
        for (int j = 0; j < 4; j++) acc[i][j] = 0.f;

    float4 xa0 = *(const float4*)xp0;
    float4 xa1 = *(const float4*)xp1;
    float4 wa0 = *(const float4*)wp0;
    float4 wa1 = *(const float4*)wp1;
    float4 wa2 = *(const float4*)wp2;
    float4 wa3 = *(const float4*)wp3;
    *(uint4*)&As[0][lr][lc]       = cvt4(xa0);
    *(uint4*)&As[0][lr + 64][lc]  = cvt4(xa1);
    *(uint4*)&Bs[0][lr][lc]       = cvt4(wa0);
    *(uint4*)&Bs[0][lr + 64][lc]  = cvt4(wa1);
    *(uint4*)&Bs[0][lr + 128][lc] = cvt4(wa2);
    *(uint4*)&Bs[0][lr + 192][lc] = cvt4(wa3);
    __syncthreads();

    int buf = 0;
    int nk = K / GBK;
    for (int it = 0; it < nk; it++) {
        bool more = (it + 1 < nk);
        if (more) {
            int k0 = (it + 1) * GBK;
            xa0 = *(const float4*)(xp0 + k0);
            xa1 = *(const float4*)(xp1 + k0);
            wa0 = *(const float4*)(wp0 + k0);
            wa1 = *(const float4*)(wp1 + k0);
            wa2 = *(const float4*)(wp2 + k0);
            wa3 = *(const float4*)(wp3 + k0);
        }
        #pragma unroll
        for (int k8 = 0; k8 < 2; k8++) {
            int kk = k8 * 8;
            unsigned a[4][4], b[8][2];
            #pragma unroll
            for (int mt = 0; mt < 4; mt++) {
                int m = wm + mt * 16 + gid;
                a[mt][0] = As[buf][m][kk + tig];
                a[mt][1] = As[buf][m + 8][kk + tig];
                a[mt][2] = As[buf][m][kk + 4 + tig];
                a[mt][3] = As[buf][m + 8][kk + 4 + tig];
            }
            #pragma unroll
            for (int nt = 0; nt < 8; nt++) {
                int n = wn + nt * 8 + gid;
                b[nt][0] = Bs[buf][n][kk + tig];
                b[nt][1] = Bs[buf][n][kk + 4 + tig];
            }
            #pragma unroll
            for (int mt = 0; mt < 4; mt++)
                #pragma unroll
                for (int nt = 0; nt < 8; nt++)
                    MMA_TF32(acc[mt * 8 + nt], a[mt], b[nt]);
        }
        if (more) {
            int nb = buf ^ 1;
            *(uint4*)&As[nb][lr][lc]       = cvt4(xa0);
            *(uint4*)&As[nb][lr + 64][lc]  = cvt4(xa1);
            *(uint4*)&Bs[nb][lr][lc]       = cvt4(wa0);
            *(uint4*)&Bs[nb][lr + 64][lc]  = cvt4(wa1);
            *(uint4*)&Bs[nb][lr + 128][lc] = cvt4(wa2);
            *(uint4*)&Bs[nb][lr + 192][lc] = cvt4(wa3);
            __syncthreads();
            buf = nb;
        }
    }
    #pragma unroll
    for (int mt = 0; mt < 4; mt++) {
        int row = wm + mt * 16 + gid;
        #pragma unroll
        for (int nt = 0; nt < 8; nt++) {
            int col = wn + nt * 8 + tig * 2;
            float* c = acc[mt * 8 + nt];
            *(float2*)&Ct[(size_t)row * BIGN_ + col]        = make_float2(c[0], c[1]);
            *(float2*)&Ct[(size_t)(row + 8) * BIGN_ + col]  = make_float2(c[2], c[3]);
        }
    }
}

// ---------------- 2b) 128x128 GEMM (o_proj / out_proj) ----------------
__global__ __launch_bounds__(256) void gemm128(const float* __restrict__ X,
                                               const float* __restrict__ W,
                                               float* __restrict__ C,
                                               int K, int ldc) {
    const float* Xt = X + (size_t)blockIdx.y * 128 * K;
    const float* Wt = W + (size_t)blockIdx.x * 128 * K;
    float* Ct = C + (size_t)blockIdx.y * 128 * ldc + blockIdx.x * 128;

    __shared__ unsigned As[2][128][LDA];
    __shared__ unsigned Bs[2][128][LDA];
    int tid = threadIdx.x;
    int lr = tid >> 2;
    int lc = (tid & 3) * 4;
    int wid = tid >> 5, lane = tid & 31;
    int gid = lane >> 2, tig = lane & 3;
    int wm = (wid >> 2) * 64;
    int wn = (wid & 3) * 32;

    const float* xp0 = Xt + (size_t)lr * K + lc;
    const float* xp1 = Xt + (size_t)(lr + 64) * K + lc;
    const float* wp0 = Wt + (size_t)lr * K + lc;
    const float* wp1 = Wt + (size_t)(lr + 64) * K + lc;

    float acc[16][4];
    #pragma unroll
    for (int i = 0; i < 16; i++)
        #pragma unroll
        for (int j = 0; j < 4; j++) acc[i][j] = 0.f;

    float4 xa0 = *(const float4*)xp0;
    float4 xa1 = *(const float4*)xp1;
    float4 wa0 = *(const float4*)wp0;
    float4 wa1 = *(const float4*)wp1;
    *(uint4*)&As[0][lr][lc]      = cvt4(xa0);
    *(uint4*)&As[0][lr + 64][lc] = cvt4(xa1);
    *(uint4*)&Bs[0][lr][lc]      = cvt4(wa0);
    *(uint4*)&Bs[0][lr + 64][lc] = cvt4(wa1);
    __syncthreads();

    int buf = 0;
    int nk = K / GBK;
    for (int it = 0; it < nk; it++) {
        bool more = (it + 1 < nk);
        if (more) {
            int k0 = (it + 1) * GBK;
            xa0 = *(const float4*)(xp0 + k0);
            xa1 = *(const float4*)(xp1 + k0);
            wa0 = *(const float4*)(wp0 + k0);
            wa1 = *(const float4*)(wp1 + k0);
        }
        #pragma unroll
        for (int k8 = 0; k8 < 2; k8++) {
            int kk = k8 * 8;
            unsigned a[4][4], b[4][2];
            #pragma unroll
            for (int mt = 0; mt < 4; mt++) {
                int m = wm + mt * 16 + gid;
                a[mt][0] = As[buf][m][kk + tig];
                a[mt][1] = As[buf][m + 8][kk + tig];
                a[mt][2] = As[buf][m][kk + 4 + tig];
                a[mt][3] = As[buf][m + 8][kk + 4 + tig];
            }
            #pragma unroll
            for (int nt = 0; nt < 4; nt++) {
                int n = wn + nt * 8 + gid;
                b[nt][0] = Bs[buf][n][kk + tig];
                b[nt][1] = Bs[buf][n][kk + 4 + tig];
            }
            #pragma unroll
            for (int mt = 0; mt < 4; mt++)
                #pragma unroll
                for (int nt = 0; nt < 4; nt++)
                    MMA_TF32(acc[mt * 4 + nt], a[mt], b[nt]);
        }
        if (more) {
            int nb = buf ^ 1;
            *(uint4*)&As[nb][lr][lc]      = cvt4(xa0);
            *(uint4*)&As[nb][lr + 64][lc] = cvt4(xa1);
            *(uint4*)&Bs[nb][lr][lc]      = cvt4(wa0);
            *(uint4*)&Bs[nb][lr + 64][lc] = cvt4(wa1);
            __syncthreads();
            buf = nb;
        }
    }
    #pragma unroll
    for (int mt = 0; mt < 4; mt++) {
        int row = wm + mt * 16 + gid;
        #pragma unroll
        for (int nt = 0; nt < 4; nt++) {
            int col = wn + nt * 8 + tig * 2;
            float* c = acc[mt * 4 + nt];
            *(float2*)&Ct[(size_t)row * ldc + col]       = make_float2(c[0], c[1]);
            *(float2*)&Ct[(size_t)(row + 8) * ldc + col] = make_float2(c[2], c[3]);
        }
    }
}

// ---------------- 3) beta / exp(g) decay ----------------
__global__ void ab_kernel(const float* __restrict__ x,
                          const float* __restrict__ a_w,
                          const float* __restrict__ b_w,
                          const float* __restrict__ dt_bias,
                          const float* __restrict__ A_log,
                          float* __restrict__ beta,
                          float* __restrict__ eg) {
    __shared__ float xs[HID_];
    int t = blockIdx.x;
    for (int i = threadIdx.x; i < HID_; i += 256) xs[i] = x[(size_t)t * HID_ + i];
    __syncthreads();
    int warp = threadIdx.x >> 5, lane = threadIdx.x & 31;
    for (int h = warp; h < H_; h += 8) {
        float da = 0.f, db = 0.f;
        const float* ap = a_w + (size_t)h * HID_;
        const float* bp = b_w + (size_t)h * HID_;
        for (int i = lane; i < HID_; i += 32) {
            float xv = xs[i];
            da = fmaf(xv, ap[i], da);
            db = fmaf(xv, bp[i], db);
        }
        for (int off = 16; off > 0; off >>= 1) {
            da += __shfl_xor_sync(0xffffffffu, da, off);
            db += __shfl_xor_sync(0xffffffffu, db, off);
        }
        if (lane == 0) {
            beta[t * H_ + h] = 1.f / (1.f + expf(-db));
            float z = da + dt_bias[h];
            float sp = (z > 20.f) ? z : log1pf(expf(z));
            eg[t * H_ + h] = expf(-expf(A_log[h]) * sp);
        }
    }
}

// ---------------- 4) fused causal conv (K=4) + silu, float4 ----------------
// covers q (c<1024), k (1024..2048), v (2048..4096) from g_big columns.
__global__ void conv_fused_kernel(const float* __restrict__ big,
                                  const float* __restrict__ wq,
                                  const float* __restrict__ wk,
                                  const float* __restrict__ wv,
                                  float* __restrict__ oq,
                                  float* __restrict__ ok,
                                  float* __restrict__ ov) {
    int idx = blockIdx.x * blockDim.x + threadIdx.x;   // over T_*4096/4
    int t = idx >> 10;                                  // 4096/4 = 1024 vec per row
    int c4 = (idx & 1023) * 4;                          // channel (of 4096)
    const float* w; float* outp; int cl;
    if (c4 < 1024)      { w = wq; outp = oq + (size_t)t * QKD_ + c4;        cl = c4; }
    else if (c4 < 2048) { w = wk; outp = ok + (size_t)t * QKD_ + c4 - 1024; cl = c4 - 1024; }
    else                { w = wv; outp = ov + (size_t)t * VAL_ + c4 - 2048; cl = c4 - 2048; }
    float4 w0 = ((const float4*)w)[cl + 0];
    float4 w1 = ((const float4*)w)[cl + 1];
    float4 w2 = ((const float4*)w)[cl + 2];
    float4 w3 = ((const float4*)w)[cl + 3];
    float4 acc = make_float4(0.f, 0.f, 0.f, 0.f);
    #pragma unroll
    for (int i = 0; i < CONV_; i++) {
        int tt = t - 3 + i;
        if (tt >= 0) {
            float4 xv = *(const float4*)(big + (size_t)tt * BIGN_ + c4);
            acc.x = fmaf(xv.x, (&w0.x)[i], acc.x);
            acc.y = fmaf(xv.y, (&w1.x)[i], acc.y);
            acc.z = fmaf(xv.z, (&w2.x)[i], acc.z);
            acc.w = fmaf(xv.w, (&w3.x)[i], acc.w);
        }
    }
    acc.x *= 1.f / (1.f + __expf(-acc.x));
    acc.y *= 1.f / (1.f + __expf(-acc.y));
    acc.z *= 1.f / (1.f + __expf(-acc.z));
    acc.w *= 1.f / (1.f + __expf(-acc.w));
    *(float4*)outp = acc;
}

// ---------------- 5) k DC-removal + q/k L2 normalize ----------------
__global__ void qknorm_kernel(float* __restrict__ q, float* __restrict__ k) {
    int gw = (blockIdx.x * blockDim.x + threadIdx.x) >> 5;  // one warp per (t,h)
    int lane = threadIdx.x & 31;
    if (gw >= T_ * H_) return;
    float* kp = k + (size_t)gw * DK_;
    float k0 = kp[lane], k1 = kp[lane + 32];
    float s = k0 + k1;
    for (int off = 16; off > 0; off >>= 1) s += __shfl_xor_sync(0xffffffffu, s, off);
    float mean = s * (1.f / 64.f);
    k0 -= mean; k1 -= mean;
    float ss = k0 * k0 + k1 * k1;
    for (int off = 16; off > 0; off >>= 1) ss += __shfl_xor_sync(0xffffffffu, ss, off);
    float sc = rsqrtf(ss + 1e-6f);
    kp[lane] = k0 * sc; kp[lane + 32] = k1 * sc;

    float* qp = q + (size_t)gw * DK_;
    float q0 = qp[lane], q1 = qp[lane + 32];
    float qq = q0 * q0 + q1 * q1;
    for (int off = 16; off > 0; off >>= 1) qq += __shfl_xor_sync(0xffffffffu, qq, off);
    float qs = rsqrtf(qq + 1e-6f) * 0.125f;   // * DK^-0.5
    qp[lane] = q0 * qs; qp[lane + 32] = q1 * qs;
}

// ---------------- 6) gated delta-rule scan ----------------
// grid = H_*2 (head, dv-half), block = 128: thread = dv_l(64) x qr(2),
// owns S[qr*32 + i][dv], i<32. cp.async 4-stage ring, 4 timesteps per stage,
// 1 barrier per 4 steps, single shfl per reduction.
__global__ __launch_bounds__(128) void scan_kernel(const float* __restrict__ q,
                                                   const float* __restrict__ k,
                                                   const float* __restrict__ v,
                                                   const float* __restrict__ beta,
                                                   const float* __restrict__ eg,
                                                   float* __restrict__ o) {
    int h = blockIdx.x >> 1;
    int dvh = blockIdx.x & 1;
    int tid = threadIdx.x;
    int dv_l = tid >> 1, qr = tid & 1;
    int dv = dvh * 64 + dv_l;

    __shared__ float ks[4][4][64], qs[4][4][64], vs[4][4][64], gb[4][4][2];

    int role  = tid >> 5;          // 0:k 1:q 2:v 3:scalars
    int lane  = tid & 31;
    int sub   = lane >> 4;         // 0/1
    int chunk = lane & 15;

    float S[32];
    #pragma unroll
    for (int i = 0; i < 32; i++) S[i] = 0.f;

    const int NP = T_ / 4;   // 512 stages

    #define ISSUE_STAGE(P) do {                                                       \
        int set_ = (P) & 3;                                                           \
        int t0_ = (P) * 4;                                                            \
        if (role == 0) {                                                              \
            _Pragma("unroll")                                                         \
            for (int s2 = 0; s2 < 2; s2++) {                                          \
                int ss = s2 * 2 + sub;                                                \
                unsigned d = (unsigned)__cvta_generic_to_shared(&ks[set_][ss][chunk*4]); \
                const float* sp = k + ((size_t)(t0_ + ss) * H_ + h) * DK_ + chunk*4;  \
                asm volatile("cp.async.cg.shared.global [%0], [%1], 16;\n" :: "r"(d), "l"(sp)); \
            }                                                                         \
        } else if (role == 1) {                                                       \
            _Pragma("unroll")                                                         \
            for (int s2 = 0; s2 < 2; s2++) {                                          \
                int ss = s2 * 2 + sub;                                                \
                unsigned d = (unsigned)__cvta_generic_to_shared(&qs[set_][ss][chunk*4]); \
                const float* sp = q + ((size_t)(t0_ + ss) * H_ + h) * DK_ + chunk*4;  \
                asm volatile("cp.async.cg.shared.global [%0], [%1], 16;\n" :: "r"(d), "l"(sp)); \
            }                                                                         \
        } else if (role == 2) {                                                       \
            _Pragma("unroll")                                                         \
            for (int s2 = 0; s2 < 2; s2++) {                                          \
                int ss = s2 * 2 + sub;                                                \
                unsigned d = (unsigned)__cvta_generic_to_shared(&vs[set_][ss][chunk*4]); \
                const float* sp = v + ((size_t)(t0_ + ss) * H_ + h) * DV_ + dvh*64 + chunk*4; \
                asm volatile("cp.async.cg.shared.global [%0], [%1], 16;\n" :: "r"(d), "l"(sp)); \
            }                                                                         \
        } else if (lane < 8) {                                                        \
            int ss = lane >> 1; int which = lane & 1;                                 \
            unsigned d = (unsigned)__cvta_generic_to_shared(&gb[set_][ss][which]);    \
            const float* sp = (which ? beta : eg) + (size_t)(t0_ + ss) * H_ + h;      \
            asm volatile("cp.async.ca.shared.global [%0], [%1], 4;\n" :: "r"(d), "l"(sp)); \
        }                                                                             \
    } while (0)

    #pragma unroll
    for (int p = 0; p < 3; p++) {
        ISSUE_STAGE(p);
        asm volatile("cp.async.commit_group;\n");
    }

    for (int p = 0; p < NP; p++) {
        asm volatile("cp.async.wait_group 2;\n");
        __syncthreads();
        if (p + 3 < NP) ISSUE_STAGE(p + 3);
        asm volatile("cp.async.commit_group;\n");
        int set = p & 3;
        #pragma unroll
        for (int s = 0; s < 4; s++) {
            float egv = gb[set][s][0];
            float bt  = gb[set][s][1];
            float vv  = vs[set][s][dv_l];
            float kr[32];
            #pragma unroll
            for (int j = 0; j < 8; j++)
                *(float4*)&kr[j*4] = *(const float4*)&ks[set][s][qr*32 + j*4];
            float kv0 = 0.f, kv1 = 0.f, kv2 = 0.f, kv3 = 0.f;
            #pragma unroll
            for (int j = 0; j < 8; j++) {
                S[j*4+0] *= egv; kv0 = fmaf(kr[j*4+0], S[j*4+0], kv0);
                S[j*4+1] *= egv; kv1 = fmaf(kr[j*4+1], S[j*4+1], kv1);
                S[j*4+2] *= egv; kv2 = fmaf(kr[j*4+2], S[j*4+2], kv2);
                S[j*4+3] *= egv; kv3 = fmaf(kr[j*4+3], S[j*4+3], kv3);
            }
            float kv = (kv0 + kv1) + (kv2 + kv3);
            kv += __shfl_xor_sync(0xffffffffu, kv, 1);
            float vn = (vv - kv) * bt;
            float qv[32];
            #pragma unroll
            for (int j = 0; j < 8; j++)
                *(float4*)&qv[j*4] = *(const float4*)&qs[set][s][qr*32 + j*4];
            float o0 = 0.f, o1 = 0.f, o2 = 0.f, o3 = 0.f;
            #pragma unroll
            for (int j = 0; j < 8; j++) {
                S[j*4+0] = fmaf(kr[j*4+0], vn, S[j*4+0]); o0 = fmaf(qv[j*4+0], S[j*4+0], o0);
                S[j*4+1] = fmaf(kr[j*4+1], vn, S[j*4+1]); o1 = fmaf(qv[j*4+1], S[j*4+1], o1);
                S[j*4+2] = fmaf(kr[j*4+2], vn, S[j*4+2]); o2 = fmaf(qv[j*4+2], S[j*4+2], o2);
                S[j*4+3] = fmaf(kr[j*4+3], vn, S[j*4+3]); o3 = fmaf(qv[j*4+3], S[j*4+3], o3);
            }
            float oo = (o0 + o1) + (o2 + o3);
            oo += __shfl_xor_sync(0xffffffffu, oo, 1);
            if (qr == 0) o[((size_t)(p*4 + s) * H_ + h) * DV_ + dv] = oo;
        }
    }
    #undef ISSUE_STAGE
}

// ---------------- 7) gated RMSNorm over head output + silu gate ------------
__global__ void onorm_kernel(const float* __restrict__ o,
                             const float* __restrict__ gateb,   // g_big + 4096, ld=BIGN_
                             const float* __restrict__ onw,
                             float* __restrict__ o2) {
    int th = blockIdx.x;                 // t*H + h
    int t = th >> 4, h = th & 15;
    int i = threadIdx.x;                 // 0..127 = dv
    float val = o[(size_t)th * DV_ + i];
    float ss = val * val;
    for (int off = 16; off > 0; off >>= 1) ss += __shfl_xor_sync(0xffffffffu, ss, off);
    __shared__ float red[4];
    int warp = i >> 5, lane = i & 31;
    if (lane == 0) red[warp] = ss;
    __syncthreads();
    float tot = red[0] + red[1] + red[2] + red[3];
    float scale = rsqrtf(tot / (float)DV_ + 1e-5f);
    float gv = gateb[(size_t)t * BIGN_ + h * DV_ + i];
    o2[(size_t)th * DV_ + i] = val * scale * onw[i] * (gv / (1.f + expf(-gv)));
}

// ---------------- launcher ----------------
extern "C" void kernel_launch(void* const* d_in, const int* in_sizes, int n_in,
                              void* d_out, int out_size) {
    const float* hidden    = (const float*)d_in[0];
    const float* norm_w    = (const float*)d_in[1];
    const float* q_w       = (const float*)d_in[2];
    const float* k_w       = (const float*)d_in[3];
    const float* v_w       = (const float*)d_in[4];
    const float* a_w       = (const float*)d_in[5];
    const float* b_w       = (const float*)d_in[6];
    const float* g_w       = (const float*)d_in[7];
    const float* dt_bias   = (const float*)d_in[8];
    const float* A_log     = (const float*)d_in[9];
    const float* conv_q_w  = (const float*)d_in[10];
    const float* conv_k_w  = (const float*)d_in[11];
    const float* conv_v_w  = (const float*)d_in[12];
    const float* o_norm_w  = (const float*)d_in[13];
    const float* o_proj_w  = (const float*)d_in[14];
    const float* out_proj_w= (const float*)d_in[15];
    float* out = (float*)d_out;

    float *px, *prs, *pbig, *pq, *pk, *pv, *pbeta, *peg, *po, *po2, *py1;
    cudaGetSymbolAddress((void**)&px,    g_x);
    cudaGetSymbolAddress((void**)&prs,   g_rs);
    cudaGetSymbolAddress((void**)&pbig,  g_big);
    cudaGetSymbolAddress((void**)&pq,    g_q);
    cudaGetSymbolAddress((void**)&pk,    g_k);
    cudaGetSymbolAddress((void**)&pv,    g_v);
    cudaGetSymbolAddress((void**)&pbeta, g_beta);
    cudaGetSymbolAddress((void**)&peg,   g_eg);
    cudaGetSymbolAddress((void**)&po,    g_o);
    cudaGetSymbolAddress((void**)&po2,   g_o2);
    cudaGetSymbolAddress((void**)&py1,   g_y1);

    // 0,1) RMSNorm (reduce + apply)
    rms_reduce_kernel<<<T_/8, 256>>>(hidden, prs);
    rms_apply_kernel<<<(T_*HID_/4)/256, 256>>>(hidden, prs, norm_w, px);

    // 2) beta / exp(g)
    ab_kernel<<<T_, 256>>>(px, a_w, b_w, dt_bias, A_log, pbeta, peg);

    // 3) fused q/k/v/g projection (tf32 MMA, 128x256 tiles) -- capture slot
    gemm128_qkvg<<<dim3(BIGN_/256, T_/128), 256>>>(px, q_w, k_w, v_w, g_w, pbig, HID_);

    // 4) fused convs + silu
    conv_fused_kernel<<<(T_*4096/4)/256, 256>>>(pbig, conv_q_w, conv_k_w, conv_v_w,
                                                pq, pk, pv);

    // 5) q/k normalize (+ k DC removal)
    qknorm_kernel<<<(T_*H_*32)/256, 256>>>(pq, pk);

    // 6) scan
    scan_kernel<<<H_*2, 128>>>(pq, pk, pv, pbeta, peg, po);

    // 7) gated output norm (gate read straight from fused buffer)
    onorm_kernel<<<T_*H_, 128>>>(po, pbig + 4096, o_norm_w, po2);

    // 8) output projections (tf32 MMA)
    gemm128<<<dim3(HID_/128, T_/128), 256>>>(po2, o_proj_w, py1, VAL_, HID_);
    gemm128<<<dim3(HID_/128, T_/128), 256>>>(py1, out_proj_w, out, HID_, HID_);
}

// round 8
// speedup vs baseline: 3.6830x; 1.0143x over previous
#include <cuda_runtime.h>
#include <cuda_bf16.h>
#include <math.h>

// ---------------- problem dims (fixed) ----------------
#define T_    2048
#define HID_  1024
#define H_    16
#define DK_   64
#define DV_   128
#define VAL_  2048   // H_*DV_
#define QKD_  1024   // H_*DK_
#define CONV_ 4
#define BIGN_ 6144   // q(1024)+k(1024)+v(2048)+g(2048)

// ---------------- scratch (device globals; no allocation allowed) ---------
__device__ float g_x    [T_*HID_];    // rmsnormed input
__device__ float g_rs   [T_];         // per-row inverse rms
__device__ float g_big  [T_*BIGN_];   // fused qkvg projection output
__device__ float g_q    [T_*QKD_];
__device__ float g_k    [T_*QKD_];
__device__ float g_v    [T_*VAL_];
__device__ float g_beta [T_*H_];
__device__ float g_eg   [T_*H_];      // exp(g) decay, precomputed
__device__ float g_o    [T_*VAL_];
__device__ float g_o2   [T_*VAL_];
__device__ float g_y1   [T_*HID_];

// ---------------- 1a) RMSNorm reduce: one warp per row ----------------
__global__ void rms_reduce_kernel(const float* __restrict__ h,
                                  float* __restrict__ rs) {
    int row = blockIdx.x * 8 + (threadIdx.x >> 5);
    int lane = threadIdx.x & 31;
    const float4* p = (const float4*)(h + (size_t)row * HID_);
    float ss = 0.f;
    #pragma unroll
    for (int i = 0; i < 8; i++) {
        float4 v = p[lane + i * 32];
        ss += v.x * v.x + v.y * v.y + v.z * v.z + v.w * v.w;
    }
    for (int off = 16; off > 0; off >>= 1) ss += __shfl_xor_sync(0xffffffffu, ss, off);
    if (lane == 0) rs[row] = rsqrtf(ss / (float)HID_ + 1e-6f);
}

// ---------------- 1b) RMSNorm apply (vectorized) ----------------
__global__ void rms_apply_kernel(const float* __restrict__ h,
                                 const float* __restrict__ rs,
                                 const float* __restrict__ w,
                                 float* __restrict__ x) {
    int idx = blockIdx.x * blockDim.x + threadIdx.x;   // float4 index
    int t = idx >> 8;                                  // HID_/4 = 256
    float s = rs[t];
    float4 hv = ((const float4*)h)[idx];
    float4 wv = ((const float4*)w)[idx & 255];
    float4 o;
    o.x = hv.x * s * wv.x; o.y = hv.y * s * wv.y;
    o.z = hv.z * s * wv.z; o.w = hv.w * s * wv.w;
    ((float4*)x)[idx] = o;
}

// ---------------- TF32 helpers ----------------
__device__ __forceinline__ unsigned f2tf32(float f) {
    unsigned u; asm("cvt.rna.tf32.f32 %0, %1;" : "=r"(u) : "f"(f)); return u;
}
__device__ __forceinline__ uint4 cvt4(float4 v) {
    uint4 u; u.x = f2tf32(v.x); u.y = f2tf32(v.y); u.z = f2tf32(v.z); u.w = f2tf32(v.w);
    return u;
}
#define MMA_TF32(C, A, B)                                                     \
    asm volatile("mma.sync.aligned.m16n8k8.row.col.f32.tf32.tf32.f32 "        \
                 "{%0,%1,%2,%3}, {%4,%5,%6,%7}, {%8,%9}, {%0,%1,%2,%3};"      \
                 : "+f"((C)[0]), "+f"((C)[1]), "+f"((C)[2]), "+f"((C)[3])     \
                 : "r"((A)[0]), "r"((A)[1]), "r"((A)[2]), "r"((A)[3]),        \
                   "r"((B)[0]), "r"((B)[1]))

#define GBK 16
#define LDA 20

// ---------------- 2) 128x128 TF32 GEMM core (2 CTAs/SM) ----------------
__device__ __forceinline__ void gemm_tile_128(const float* __restrict__ Xt,
                                              const float* __restrict__ Wt,
                                              float* __restrict__ Ct,
                                              int K, int ldc) {
    __shared__ unsigned As[2][128][LDA];
    __shared__ unsigned Bs[2][128][LDA];
    int tid = threadIdx.x;
    int lr = tid >> 2;
    int lc = (tid & 3) * 4;
    int wid = tid >> 5, lane = tid & 31;
    int gid = lane >> 2, tig = lane & 3;
    int wm = (wid >> 2) * 64;
    int wn = (wid & 3) * 32;

    const float* xp0 = Xt + (size_t)lr * K + lc;
    const float* xp1 = Xt + (size_t)(lr + 64) * K + lc;
    const float* wp0 = Wt + (size_t)lr * K + lc;
    const float* wp1 = Wt + (size_t)(lr + 64) * K + lc;

    float acc[16][4];
    #pragma unroll
    for (int i = 0; i < 16; i++)
        #pragma unroll
        for (int j = 0; j < 4; j++) acc[i][j] = 0.f;

    float4 xa0 = *(const float4*)xp0;
    float4 xa1 = *(const float4*)xp1;
    float4 wa0 = *(const float4*)wp0;
    float4 wa1 = *(const float4*)wp1;
    *(uint4*)&As[0][lr][lc]      = cvt4(xa0);
    *(uint4*)&As[0][lr + 64][lc] = cvt4(xa1);
    *(uint4*)&Bs[0][lr][lc]      = cvt4(wa0);
    *(uint4*)&Bs[0][lr + 64][lc] = cvt4(wa1);
    __syncthreads();

    int buf = 0;
    int nk = K / GBK;
    for (int it = 0; it < nk; it++) {
        bool more = (it + 1 < nk);
        if (more) {
            int k0 = (it + 1) * GBK;
            xa0 = *(const float4*)(xp0 + k0);
            xa1 = *(const float4*)(xp1 + k0);
            wa0 = *(const float4*)(wp0 + k0);
            wa1 = *(const float4*)(wp1 + k0);
        }
        #pragma unroll
        for (int k8 = 0; k8 < 2; k8++) {
            int kk = k8 * 8;
            unsigned a[4][4], b[4][2];
            #pragma unroll
            for (int mt = 0; mt < 4; mt++) {
                int m = wm + mt * 16 + gid;
                a[mt][0] = As[buf][m][kk + tig];
                a[mt][1] = As[buf][m + 8][kk + tig];
                a[mt][2] = As[buf][m][kk + 4 + tig];
                a[mt][3] = As[buf][m + 8][kk + 4 + tig];
            }
            #pragma unroll
            for (int nt = 0; nt < 4; nt++) {
                int n = wn + nt * 8 + gid;
                b[nt][0] = Bs[buf][n][kk + tig];
                b[nt][1] = Bs[buf][n][kk + 4 + tig];
            }
            #pragma unroll
            for (int mt = 0; mt < 4; mt++)
                #pragma unroll
                for (int nt = 0; nt < 4; nt++)
                    MMA_TF32(acc[mt * 4 + nt], a[mt], b[nt]);
        }
        if (more) {
            int nb = buf ^ 1;
            *(uint4*)&As[nb][lr][lc]      = cvt4(xa0);
            *(uint4*)&As[nb][lr + 64][lc] = cvt4(xa1);
            *(uint4*)&Bs[nb][lr][lc]      = cvt4(wa0);
            *(uint4*)&Bs[nb][lr + 64][lc] = cvt4(wa1);
            __syncthreads();
            buf = nb;
        }
    }
    #pragma unroll
    for (int mt = 0; mt < 4; mt++) {
        int row = wm + mt * 16 + gid;
        #pragma unroll
        for (int nt = 0; nt < 4; nt++) {
            int col = wn + nt * 8 + tig * 2;
            float* c = acc[mt * 4 + nt];
            *(float2*)&Ct[(size_t)row * ldc + col]       = make_float2(c[0], c[1]);
            *(float2*)&Ct[(size_t)(row + 8) * ldc + col] = make_float2(c[2], c[3]);
        }
    }
}

__global__ __launch_bounds__(256, 2) void gemm128(const float* __restrict__ X,
                                                  const float* __restrict__ W,
                                                  float* __restrict__ C,
                                                  int K, int ldc) {
    gemm_tile_128(X + (size_t)blockIdx.y * 128 * K,
                  W + (size_t)blockIdx.x * 128 * K,
                  C + (size_t)blockIdx.y * 128 * ldc + blockIdx.x * 128,
                  K, ldc);
}

// fused q/k/v/g projection: 128-col tiles with weight segment select
__global__ __launch_bounds__(256, 2) void gemm128_qkvg(const float* __restrict__ X,
                                                       const float* __restrict__ wq,
                                                       const float* __restrict__ wk,
                                                       const float* __restrict__ wv,
                                                       const float* __restrict__ wg,
                                                       float* __restrict__ C, int K) {
    int n0 = blockIdx.x * 128;
    const float* W; int ln;
    if (n0 < 1024)      { W = wq; ln = n0; }
    else if (n0 < 2048) { W = wk; ln = n0 - 1024; }
    else if (n0 < 4096) { W = wv; ln = n0 - 2048; }
    else                { W = wg; ln = n0 - 4096; }
    gemm_tile_128(X + (size_t)blockIdx.y * 128 * K,
                  W + (size_t)ln * K,
                  C + (size_t)blockIdx.y * 128 * BIGN_ + n0,
                  K, BIGN_);
}

// ---------------- 3) beta / exp(g) decay ----------------
__global__ void ab_kernel(const float* __restrict__ x,
                          const float* __restrict__ a_w,
                          const float* __restrict__ b_w,
                          const float* __restrict__ dt_bias,
                          const float* __restrict__ A_log,
                          float* __restrict__ beta,
                          float* __restrict__ eg) {
    __shared__ float xs[HID_];
    int t = blockIdx.x;
    for (int i = threadIdx.x; i < HID_; i += 256) xs[i] = x[(size_t)t * HID_ + i];
    __syncthreads();
    int warp = threadIdx.x >> 5, lane = threadIdx.x & 31;
    for (int h = warp; h < H_; h += 8) {
        float da = 0.f, db = 0.f;
        const float* ap = a_w + (size_t)h * HID_;
        const float* bp = b_w + (size_t)h * HID_;
        for (int i = lane; i < HID_; i += 32) {
            float xv = xs[i];
            da = fmaf(xv, ap[i], da);
            db = fmaf(xv, bp[i], db);
        }
        for (int off = 16; off > 0; off >>= 1) {
            da += __shfl_xor_sync(0xffffffffu, da, off);
            db += __shfl_xor_sync(0xffffffffu, db, off);
        }
        if (lane == 0) {
            beta[t * H_ + h] = 1.f / (1.f + expf(-db));
            float z = da + dt_bias[h];
            float sp = (z > 20.f) ? z : log1pf(expf(z));
            eg[t * H_ + h] = expf(-expf(A_log[h]) * sp);
        }
    }
}

// ---------------- 4) fused causal conv (K=4) + silu, float4 ----------------
__global__ void conv_fused_kernel(const float* __restrict__ big,
                                  const float* __restrict__ wq,
                                  const float* __restrict__ wk,
                                  const float* __restrict__ wv,
                                  float* __restrict__ oq,
                                  float* __restrict__ ok,
                                  float* __restrict__ ov) {
    int idx = blockIdx.x * blockDim.x + threadIdx.x;   // over T_*4096/4
    int t = idx >> 10;                                  // 4096/4 = 1024 vec per row
    int c4 = (idx & 1023) * 4;                          // channel (of 4096)
    const float* w; float* outp; int cl;
    if (c4 < 1024)      { w = wq; outp = oq + (size_t)t * QKD_ + c4;        cl = c4; }
    else if (c4 < 2048) { w = wk; outp = ok + (size_t)t * QKD_ + c4 - 1024; cl = c4 - 1024; }
    else                { w = wv; outp = ov + (size_t)t * VAL_ + c4 - 2048; cl = c4 - 2048; }
    float4 w0 = ((const float4*)w)[cl + 0];
    float4 w1 = ((const float4*)w)[cl + 1];
    float4 w2 = ((const float4*)w)[cl + 2];
    float4 w3 = ((const float4*)w)[cl + 3];
    float4 acc = make_float4(0.f, 0.f, 0.f, 0.f);
    #pragma unroll
    for (int i = 0; i < CONV_; i++) {
        int tt = t - 3 + i;
        if (tt >= 0) {
            float4 xv = *(const float4*)(big + (size_t)tt * BIGN_ + c4);
            acc.x = fmaf(xv.x, (&w0.x)[i], acc.x);
            acc.y = fmaf(xv.y, (&w1.x)[i], acc.y);
            acc.z = fmaf(xv.z, (&w2.x)[i], acc.z);
            acc.w = fmaf(xv.w, (&w3.x)[i], acc.w);
        }
    }
    acc.x *= 1.f / (1.f + __expf(-acc.x));
    acc.y *= 1.f / (1.f + __expf(-acc.y));
    acc.z *= 1.f / (1.f + __expf(-acc.z));
    acc.w *= 1.f / (1.f + __expf(-acc.w));
    *(float4*)outp = acc;
}

// ---------------- 5) k DC-removal + q/k L2 normalize ----------------
__global__ void qknorm_kernel(float* __restrict__ q, float* __restrict__ k) {
    int gw = (blockIdx.x * blockDim.x + threadIdx.x) >> 5;  // one warp per (t,h)
    int lane = threadIdx.x & 31;
    if (gw >= T_ * H_) return;
    float* kp = k + (size_t)gw * DK_;
    float k0 = kp[lane], k1 = kp[lane + 32];
    float s = k0 + k1;
    for (int off = 16; off > 0; off >>= 1) s += __shfl_xor_sync(0xffffffffu, s, off);
    float mean = s * (1.f / 64.f);
    k0 -= mean; k1 -= mean;
    float ss = k0 * k0 + k1 * k1;
    for (int off = 16; off > 0; off >>= 1) ss += __shfl_xor_sync(0xffffffffu, ss, off);
    float sc = rsqrtf(ss + 1e-6f);
    kp[lane] = k0 * sc; kp[lane + 32] = k1 * sc;

    float* qp = q + (size_t)gw * DK_;
    float q0 = qp[lane], q1 = qp[lane + 32];
    float qq = q0 * q0 + q1 * q1;
    for (int off = 16; off > 0; off >>= 1) qq += __shfl_xor_sync(0xffffffffu, qq, off);
    float qs = rsqrtf(qq + 1e-6f) * 0.125f;   // * DK^-0.5
    qp[lane] = q0 * qs; qp[lane + 32] = q1 * qs;
}

// ---------------- 6) gated delta-rule scan ----------------
// grid = H_*4 (head, dv-quarter), block = 128: thread = dv_l(32) x qr(4),
// owns S[qr*16 + i][dv], i<16. cp.async 4-stage ring, 4 timesteps per stage.
__global__ __launch_bounds__(128) void scan_kernel(const float* __restrict__ q,
                                                   const float* __restrict__ k,
                                                   const float* __restrict__ v,
                                                   const float* __restrict__ beta,
                                                   const float* __restrict__ eg,
                                                   float* __restrict__ o) {
    int h = blockIdx.x >> 2;
    int dvq = blockIdx.x & 3;
    int tid = threadIdx.x;
    int dv_l = tid >> 2, qr = tid & 3;
    int dv = dvq * 32 + dv_l;

    __shared__ float ks[4][4][64], qs[4][4][64], vs[4][4][32], gb[4][4][2];

    int role = tid >> 5;           // warp: 0=k 1=q 2=v 3=scalars
    int lane = tid & 31;

    float S[16];
    #pragma unroll
    for (int i = 0; i < 16; i++) S[i] = 0.f;

    const int NP = T_ / 4;   // 512 stages

    #define ISSUE_STAGE(P) do {                                                       \
        int set_ = (P) & 3;                                                           \
        int t0_ = (P) * 4;                                                            \
        if (role == 0) {                                                              \
            _Pragma("unroll")                                                         \
            for (int r2 = 0; r2 < 2; r2++) {                                          \
                int idx = lane + r2 * 32;                                             \
                int ss = idx >> 4, ch = idx & 15;                                     \
                unsigned d = (unsigned)__cvta_generic_to_shared(&ks[set_][ss][ch*4]); \
                const float* sp = k + ((size_t)(t0_ + ss) * H_ + h) * DK_ + ch*4;     \
                asm volatile("cp.async.cg.shared.global [%0], [%1], 16;\n" :: "r"(d), "l"(sp)); \
            }                                                                         \
        } else if (role == 1) {                                                       \
            _Pragma("unroll")                                                         \
            for (int r2 = 0; r2 < 2; r2++) {                                          \
                int idx = lane + r2 * 32;                                             \
                int ss = idx >> 4, ch = idx & 15;                                     \
                unsigned d = (unsigned)__cvta_generic_to_shared(&qs[set_][ss][ch*4]); \
                const float* sp = q + ((size_t)(t0_ + ss) * H_ + h) * DK_ + ch*4;     \
                asm volatile("cp.async.cg.shared.global [%0], [%1], 16;\n" :: "r"(d), "l"(sp)); \
            }                                                                         \
        } else if (role == 2) {                                                       \
            int ss = lane >> 3, ch = lane & 7;                                        \
            unsigned d = (unsigned)__cvta_generic_to_shared(&vs[set_][ss][ch*4]);     \
            const float* sp = v + ((size_t)(t0_ + ss) * H_ + h) * DV_ + dvq*32 + ch*4;\
            asm volatile("cp.async.cg.shared.global [%0], [%1], 16;\n" :: "r"(d), "l"(sp)); \
        } else if (lane < 8) {                                                        \
            int ss = lane >> 1; int which = lane & 1;                                 \
            unsigned d = (unsigned)__cvta_generic_to_shared(&gb[set_][ss][which]);    \
            const float* sp = (which ? beta : eg) + (size_t)(t0_ + ss) * H_ + h;      \
            asm volatile("cp.async.ca.shared.global [%0], [%1], 4;\n" :: "r"(d), "l"(sp)); \
        }                                                                             \
    } while (0)

    #pragma unroll
    for (int p = 0; p < 3; p++) {
        ISSUE_STAGE(p);
        asm volatile("cp.async.commit_group;\n");
    }

    for (int p = 0; p < NP; p++) {
        asm volatile("cp.async.wait_group 2;\n");
        __syncthreads();
        if (p + 3 < NP) ISSUE_STAGE(p + 3);
        asm volatile("cp.async.commit_group;\n");
        int set = p & 3;
        #pragma unroll
        for (int s = 0; s < 4; s++) {
            float egv = gb[set][s][0];
            float bt  = gb[set][s][1];
            float vv  = vs[set][s][dv_l];
            float kr[16];
            #pragma unroll
            for (int j = 0; j < 4; j++)
                *(float4*)&kr[j*4] = *(const float4*)&ks[set][s][qr*16 + j*4];
            float kv0 = 0.f, kv1 = 0.f, kv2 = 0.f, kv3 = 0.f;
            #pragma unroll
            for (int j = 0; j < 4; j++) {
                S[j*4+0] *= egv; kv0 = fmaf(kr[j*4+0], S[j*4+0], kv0);
                S[j*4+1] *= egv; kv1 = fmaf(kr[j*4+1], S[j*4+1], kv1);
                S[j*4+2] *= egv; kv2 = fmaf(kr[j*4+2], S[j*4+2], kv2);
                S[j*4+3] *= egv; kv3 = fmaf(kr[j*4+3], S[j*4+3], kv3);
            }
            float kv = (kv0 + kv1) + (kv2 + kv3);
            kv += __shfl_xor_sync(0xffffffffu, kv, 1);
            kv += __shfl_xor_sync(0xffffffffu, kv, 2);
            float vn = (vv - kv) * bt;
            float qv[16];
            #pragma unroll
            for (int j = 0; j < 4; j++)
                *(float4*)&qv[j*4] = *(const float4*)&qs[set][s][qr*16 + j*4];
            float o0 = 0.f, o1 = 0.f, o2 = 0.f, o3 = 0.f;
            #pragma unroll
            for (int j = 0; j < 4; j++) {
                S[j*4+0] = fmaf(kr[j*4+0], vn, S[j*4+0]); o0 = fmaf(qv[j*4+0], S[j*4+0], o0);
                S[j*4+1] = fmaf(kr[j*4+1], vn, S[j*4+1]); o1 = fmaf(qv[j*4+1], S[j*4+1], o1);
                S[j*4+2] = fmaf(kr[j*4+2], vn, S[j*4+2]); o2 = fmaf(qv[j*4+2], S[j*4+2], o2);
                S[j*4+3] = fmaf(kr[j*4+3], vn, S[j*4+3]); o3 = fmaf(qv[j*4+3], S[j*4+3], o3);
            }
            float oo = (o0 + o1) + (o2 + o3);
            oo += __shfl_xor_sync(0xffffffffu, oo, 1);
            oo += __shfl_xor_sync(0xffffffffu, oo, 2);
            if (qr == 0) o[((size_t)(p*4 + s) * H_ + h) * DV_ + dv] = oo;
        }
    }
    #undef ISSUE_STAGE
}

// ---------------- 7) gated RMSNorm over head output + silu gate ------------
__global__ void onorm_kernel(const float* __restrict__ o,
                             const float* __restrict__ gateb,   // g_big + 4096, ld=BIGN_
                             const float* __restrict__ onw,
                             float* __restrict__ o2) {
    int th = blockIdx.x;                 // t*H + h
    int t = th >> 4, h = th & 15;
    int i = threadIdx.x;                 // 0..127 = dv
    float val = o[(size_t)th * DV_ + i];
    float ss = val * val;
    for (int off = 16; off > 0; off >>= 1) ss += __shfl_xor_sync(0xffffffffu, ss, off);
    __shared__ float red[4];
    int warp = i >> 5, lane = i & 31;
    if (lane == 0) red[warp] = ss;
    __syncthreads();
    float tot = red[0] + red[1] + red[2] + red[3];
    float scale = rsqrtf(tot / (float)DV_ + 1e-5f);
    float gv = gateb[(size_t)t * BIGN_ + h * DV_ + i];
    o2[(size_t)th * DV_ + i] = val * scale * onw[i] * (gv / (1.f + expf(-gv)));
}

// ---------------- launcher ----------------
extern "C" void kernel_launch(void* const* d_in, const int* in_sizes, int n_in,
                              void* d_out, int out_size) {
    const float* hidden    = (const float*)d_in[0];
    const float* norm_w    = (const float*)d_in[1];
    const float* q_w       = (const float*)d_in[2];
    const float* k_w       = (const float*)d_in[3];
    const float* v_w       = (const float*)d_in[4];
    const float* a_w       = (const float*)d_in[5];
    const float* b_w       = (const float*)d_in[6];
    const float* g_w       = (const float*)d_in[7];
    const float* dt_bias   = (const float*)d_in[8];
    const float* A_log     = (const float*)d_in[9];
    const float* conv_q_w  = (const float*)d_in[10];
    const float* conv_k_w  = (const float*)d_in[11];
    const float* conv_v_w  = (const float*)d_in[12];
    const float* o_norm_w  = (const float*)d_in[13];
    const float* o_proj_w  = (const float*)d_in[14];
    const float* out_proj_w= (const float*)d_in[15];
    float* out = (float*)d_out;

    float *px, *prs, *pbig, *pq, *pk, *pv, *pbeta, *peg, *po, *po2, *py1;
    cudaGetSymbolAddress((void**)&px,    g_x);
    cudaGetSymbolAddress((void**)&prs,   g_rs);
    cudaGetSymbolAddress((void**)&pbig,  g_big);
    cudaGetSymbolAddress((void**)&pq,    g_q);
    cudaGetSymbolAddress((void**)&pk,    g_k);
    cudaGetSymbolAddress((void**)&pv,    g_v);
    cudaGetSymbolAddress((void**)&pbeta, g_beta);
    cudaGetSymbolAddress((void**)&peg,   g_eg);
    cudaGetSymbolAddress((void**)&po,    g_o);
    cudaGetSymbolAddress((void**)&po2,   g_o2);
    cudaGetSymbolAddress((void**)&py1,   g_y1);

    // 0,1) RMSNorm (reduce + apply)
    rms_reduce_kernel<<<T_/8, 256>>>(hidden, prs);
    rms_apply_kernel<<<(T_*HID_/4)/256, 256>>>(hidden, prs, norm_w, px);

    // 2) beta / exp(g)
    ab_kernel<<<T_, 256>>>(px, a_w, b_w, dt_bias, A_log, pbeta, peg);

    // 3) fused q/k/v/g projection (tf32 MMA, 128x128, 2 CTA/SM) -- capture slot
    gemm128_qkvg<<<dim3(BIGN_/128, T_/128), 256>>>(px, q_w, k_w, v_w, g_w, pbig, HID_);

    // 4) fused convs + silu
    conv_fused_kernel<<<(T_*4096/4)/256, 256>>>(pbig, conv_q_w, conv_k_w, conv_v_w,
                                                pq, pk, pv);

    // 5) q/k normalize (+ k DC removal)
    qknorm_kernel<<<(T_*H_*32)/256, 256>>>(pq, pk);

    // 6) scan (dv split 4 -> 64 blocks)
    scan_kernel<<<H_*4, 128>>>(pq, pk, pv, pbeta, peg, po);

    // 7) gated output norm (gate read straight from fused buffer)
    onorm_kernel<<<T_*H_, 128>>>(po, pbig + 4096, o_norm_w, po2);

    // 8) output projections (tf32 MMA)
    gemm128<<<dim3(HID_/128, T_/128), 256>>>(po2, o_proj_w, py1, VAL_, HID_);
    gemm128<<<dim3(HID_/128, T_/128), 256>>>(py1, out_proj_w, out, HID_, HID_);
}

// round 9
// speedup vs baseline: 3.7845x; 1.0276x over previous
#include <cuda_runtime.h>
#include <cuda_bf16.h>
#include <math.h>

// ---------------- problem dims (fixed) ----------------
#define T_    2048
#define HID_  1024
#define H_    16
#define DK_   64
#define DV_   128
#define VAL_  2048   // H_*DV_
#define QKD_  1024   // H_*DK_
#define CONV_ 4
#define BIGN_ 6144   // q(1024)+k(1024)+v(2048)+g(2048)

// concatenated tf32 weight buffer offsets (elements)
#define WQKVG_OFF 0
#define WO_OFF    6291456            // 6144*1024
#define WOUT_OFF  8388608            // + 1024*2048
#define WT_ELEMS  9437184            // + 1024*1024

// ---------------- scratch (device globals; no allocation allowed) ---------
__device__ float    g_x   [T_*HID_];   // rmsnormed input (fp32, for ab)
__device__ unsigned g_xt  [T_*HID_];   // rmsnormed input (tf32)
__device__ unsigned g_wt  [WT_ELEMS];  // all weights, tf32, concatenated
__device__ float    g_big [T_*BIGN_];  // fused qkvg projection output
__device__ float    g_q   [T_*QKD_];
__device__ float    g_k   [T_*QKD_];
__device__ float    g_v   [T_*VAL_];
__device__ float    g_beta[T_*H_];
__device__ float    g_eg  [T_*H_];
__device__ float    g_o   [T_*VAL_];
__device__ unsigned g_o2t [T_*VAL_];   // gated-normed output heads (tf32)
__device__ unsigned g_y1t [T_*HID_];   // o_proj output (tf32)

// ---------------- TF32 helpers ----------------
__device__ __forceinline__ unsigned f2tf32(float f) {
    unsigned u; asm("cvt.rna.tf32.f32 %0, %1;" : "=r"(u) : "f"(f)); return u;
}
__device__ __forceinline__ uint4 cvt4(float4 v) {
    uint4 u; u.x = f2tf32(v.x); u.y = f2tf32(v.y); u.z = f2tf32(v.z); u.w = f2tf32(v.w);
    return u;
}
#define MMA_TF32(C, A, B)                                                     \
    asm volatile("mma.sync.aligned.m16n8k8.row.col.f32.tf32.tf32.f32 "        \
                 "{%0,%1,%2,%3}, {%4,%5,%6,%7}, {%8,%9}, {%0,%1,%2,%3};"      \
                 : "+f"((C)[0]), "+f"((C)[1]), "+f"((C)[2]), "+f"((C)[3])     \
                 : "r"((A)[0]), "r"((A)[1]), "r"((A)[2]), "r"((A)[3]),        \
                   "r"((B)[0]), "r"((B)[1]))
#define CP16(dst, src) \
    asm volatile("cp.async.cg.shared.global [%0], [%1], 16;\n" :: "r"(dst), "l"(src))

// ---------------- 0) weights -> tf32 (single kernel, concatenated) --------
// float4 segments: wq 262144 | wk 262144 | wv 524288 | wg 524288 | wo 524288 | wout 262144
__global__ void cvt_weights_kernel(const float4* __restrict__ wq,
                                   const float4* __restrict__ wk,
                                   const float4* __restrict__ wv,
                                   const float4* __restrict__ wg,
                                   const float4* __restrict__ wo,
                                   const float4* __restrict__ wout,
                                   uint4* __restrict__ dst) {
    int idx = blockIdx.x * 256 + threadIdx.x;
    const float4* src; int off;
    if (idx < 262144)       { src = wq;   off = idx; }
    else if (idx < 524288)  { src = wk;   off = idx - 262144; }
    else if (idx < 1048576) { src = wv;   off = idx - 524288; }
    else if (idx < 1572864) { src = wg;   off = idx - 1048576; }
    else if (idx < 2097152) { src = wo;   off = idx - 1572864; }
    else                    { src = wout; off = idx - 2097152; }
    dst[idx] = cvt4(src[off]);
}

// ---------------- 1a) RMSNorm reduce: one warp per row ----------------
__global__ void rms_reduce_kernel(const float* __restrict__ h,
                                  float* __restrict__ rs) {
    int row = blockIdx.x * 8 + (threadIdx.x >> 5);
    int lane = threadIdx.x & 31;
    const float4* p = (const float4*)(h + (size_t)row * HID_);
    float ss = 0.f;
    #pragma unroll
    for (int i = 0; i < 8; i++) {
        float4 v = p[lane + i * 32];
        ss += v.x * v.x + v.y * v.y + v.z * v.z + v.w * v.w;
    }
    for (int off = 16; off > 0; off >>= 1) ss += __shfl_xor_sync(0xffffffffu, ss, off);
    if (lane == 0) rs[row] = rsqrtf(ss / (float)HID_ + 1e-6f);
}
__device__ float g_rs[T_];

// ---------------- 1b) RMSNorm apply (fp32 + tf32 outputs) ----------------
__global__ void rms_apply_kernel(const float* __restrict__ h,
                                 const float* __restrict__ rs,
                                 const float* __restrict__ w,
                                 float* __restrict__ x,
                                 unsigned* __restrict__ xt) {
    int idx = blockIdx.x * blockDim.x + threadIdx.x;   // float4 index
    int t = idx >> 8;                                  // HID_/4 = 256
    float s = rs[t];
    float4 hv = ((const float4*)h)[idx];
    float4 wv = ((const float4*)w)[idx & 255];
    float4 o;
    o.x = hv.x * s * wv.x; o.y = hv.y * s * wv.y;
    o.z = hv.z * s * wv.z; o.w = hv.w * s * wv.w;
    ((float4*)x)[idx] = o;
    ((uint4*)xt)[idx] = cvt4(o);
}

#define LDA 20

// ---------------- 2) 128x128 TF32 GEMM, cp.async 2-stage ----------------
// C[M,N] = X[M,K] @ W[N,K]^T, operands already tf32. OUT_TF32: also/only
// write tf32 (for chained GEMMs).
template<int OUT_TF32>
__global__ __launch_bounds__(256, 2) void gemm128_t(const unsigned* __restrict__ X,
                                                    const unsigned* __restrict__ W,
                                                    float* __restrict__ C,
                                                    unsigned* __restrict__ Ct32,
                                                    int K, int ldc) {
    __shared__ unsigned As[2][128][LDA];
    __shared__ unsigned Bs[2][128][LDA];
    const unsigned* Xt = X + (size_t)blockIdx.y * 128 * K;
    const unsigned* Wt = W + (size_t)blockIdx.x * 128 * K;
    int tid = threadIdx.x;
    int lr = tid >> 2;            // 0..63
    int lc = (tid & 3) * 4;       // 0,4,8,12
    int wid = tid >> 5, lane = tid & 31;
    int gid = lane >> 2, tig = lane & 3;
    int wm = (wid >> 2) * 64;
    int wn = (wid & 3) * 32;

    const unsigned* xs0 = Xt + (size_t)lr * K + lc;
    const unsigned* xs1 = Xt + (size_t)(lr + 64) * K + lc;
    const unsigned* ws0 = Wt + (size_t)lr * K + lc;
    const unsigned* ws1 = Wt + (size_t)(lr + 64) * K + lc;

    unsigned da0 = (unsigned)__cvta_generic_to_shared(&As[0][lr][lc]);
    unsigned da1 = (unsigned)__cvta_generic_to_shared(&As[0][lr + 64][lc]);
    unsigned db0 = (unsigned)__cvta_generic_to_shared(&Bs[0][lr][lc]);
    unsigned db1 = (unsigned)__cvta_generic_to_shared(&Bs[0][lr + 64][lc]);
    const unsigned BUFSZ = 128 * LDA * 4;   // bytes per stage buffer

    float acc[16][4];
    #pragma unroll
    for (int i = 0; i < 16; i++)
        #pragma unroll
        for (int j = 0; j < 4; j++) acc[i][j] = 0.f;

    // prologue: stage 0
    CP16(da0, xs0); CP16(da1, xs1); CP16(db0, ws0); CP16(db1, ws1);
    asm volatile("cp.async.commit_group;\n");

    int nk = K / 16;
    for (int it = 0; it < nk; it++) {
        int buf = it & 1;
        asm volatile("cp.async.wait_group 0;\n");
        __syncthreads();
        if (it + 1 < nk) {
            int k0 = (it + 1) * 16;
            unsigned boff = (buf ^ 1) * BUFSZ;
            CP16(da0 + boff, xs0 + k0); CP16(da1 + boff, xs1 + k0);
            CP16(db0 + boff, ws0 + k0); CP16(db1 + boff, ws1 + k0);
            asm volatile("cp.async.commit_group;\n");
        }
        #pragma unroll
        for (int k8 = 0; k8 < 2; k8++) {
            int kk = k8 * 8;
            unsigned a[4][4], b[4][2];
            #pragma unroll
            for (int mt = 0; mt < 4; mt++) {
                int m = wm + mt * 16 + gid;
                a[mt][0] = As[buf][m][kk + tig];
                a[mt][1] = As[buf][m + 8][kk + tig];
                a[mt][2] = As[buf][m][kk + 4 + tig];
                a[mt][3] = As[buf][m + 8][kk + 4 + tig];
            }
            #pragma unroll
            for (int nt = 0; nt < 4; nt++) {
                int n = wn + nt * 8 + gid;
                b[nt][0] = Bs[buf][n][kk + tig];
                b[nt][1] = Bs[buf][n][kk + 4 + tig];
            }
            #pragma unroll
            for (int mt = 0; mt < 4; mt++)
                #pragma unroll
                for (int nt = 0; nt < 4; nt++)
                    MMA_TF32(acc[mt * 4 + nt], a[mt], b[nt]);
        }
    }

    size_t base = (size_t)blockIdx.y * 128 * ldc + blockIdx.x * 128;
    #pragma unroll
    for (int mt = 0; mt < 4; mt++) {
        int row = wm + mt * 16 + gid;
        #pragma unroll
        for (int nt = 0; nt < 4; nt++) {
            int col = wn + nt * 8 + tig * 2;
            float* c = acc[mt * 4 + nt];
            if (OUT_TF32) {
                uint2 u0 = make_uint2(f2tf32(c[0]), f2tf32(c[1]));
                uint2 u1 = make_uint2(f2tf32(c[2]), f2tf32(c[3]));
                *(uint2*)&Ct32[base + (size_t)row * ldc + col]       = u0;
                *(uint2*)&Ct32[base + (size_t)(row + 8) * ldc + col] = u1;
            } else {
                *(float2*)&C[base + (size_t)row * ldc + col]       = make_float2(c[0], c[1]);
                *(float2*)&C[base + (size_t)(row + 8) * ldc + col] = make_float2(c[2], c[3]);
            }
        }
    }
}

// ---------------- 3) beta / exp(g) decay ----------------
__global__ void ab_kernel(const float* __restrict__ x,
                          const float* __restrict__ a_w,
                          const float* __restrict__ b_w,
                          const float* __restrict__ dt_bias,
                          const float* __restrict__ A_log,
                          float* __restrict__ beta,
                          float* __restrict__ eg) {
    __shared__ float xs[HID_];
    int t = blockIdx.x;
    for (int i = threadIdx.x; i < HID_; i += 256) xs[i] = x[(size_t)t * HID_ + i];
    __syncthreads();
    int warp = threadIdx.x >> 5, lane = threadIdx.x & 31;
    for (int h = warp; h < H_; h += 8) {
        float da = 0.f, db = 0.f;
        const float* ap = a_w + (size_t)h * HID_;
        const float* bp = b_w + (size_t)h * HID_;
        for (int i = lane; i < HID_; i += 32) {
            float xv = xs[i];
            da = fmaf(xv, ap[i], da);
            db = fmaf(xv, bp[i], db);
        }
        for (int off = 16; off > 0; off >>= 1) {
            da += __shfl_xor_sync(0xffffffffu, da, off);
            db += __shfl_xor_sync(0xffffffffu, db, off);
        }
        if (lane == 0) {
            beta[t * H_ + h] = 1.f / (1.f + expf(-db));
            float z = da + dt_bias[h];
            float sp = (z > 20.f) ? z : log1pf(expf(z));
            eg[t * H_ + h] = expf(-expf(A_log[h]) * sp);
        }
    }
}

// ---------------- 4) fused causal conv (K=4) + silu, float4 ----------------
__global__ void conv_fused_kernel(const float* __restrict__ big,
                                  const float* __restrict__ wq,
                                  const float* __restrict__ wk,
                                  const float* __restrict__ wv,
                                  float* __restrict__ oq,
                                  float* __restrict__ ok,
                                  float* __restrict__ ov) {
    int idx = blockIdx.x * blockDim.x + threadIdx.x;   // over T_*4096/4
    int t = idx >> 10;
    int c4 = (idx & 1023) * 4;
    const float* w; float* outp; int cl;
    if (c4 < 1024)      { w = wq; outp = oq + (size_t)t * QKD_ + c4;        cl = c4; }
    else if (c4 < 2048) { w = wk; outp = ok + (size_t)t * QKD_ + c4 - 1024; cl = c4 - 1024; }
    else                { w = wv; outp = ov + (size_t)t * VAL_ + c4 - 2048; cl = c4 - 2048; }
    float4 w0 = ((const float4*)w)[cl + 0];
    float4 w1 = ((const float4*)w)[cl + 1];
    float4 w2 = ((const float4*)w)[cl + 2];
    float4 w3 = ((const float4*)w)[cl + 3];
    float4 acc = make_float4(0.f, 0.f, 0.f, 0.f);
    #pragma unroll
    for (int i = 0; i < CONV_; i++) {
        int tt = t - 3 + i;
        if (tt >= 0) {
            float4 xv = *(const float4*)(big + (size_t)tt * BIGN_ + c4);
            acc.x = fmaf(xv.x, (&w0.x)[i], acc.x);
            acc.y = fmaf(xv.y, (&w1.x)[i], acc.y);
            acc.z = fmaf(xv.z, (&w2.x)[i], acc.z);
            acc.w = fmaf(xv.w, (&w3.x)[i], acc.w);
        }
    }
    acc.x *= 1.f / (1.f + __expf(-acc.x));
    acc.y *= 1.f / (1.f + __expf(-acc.y));
    acc.z *= 1.f / (1.f + __expf(-acc.z));
    acc.w *= 1.f / (1.f + __expf(-acc.w));
    *(float4*)outp = acc;
}

// ---------------- 5) k DC-removal + q/k L2 normalize ----------------
__global__ void qknorm_kernel(float* __restrict__ q, float* __restrict__ k) {
    int gw = (blockIdx.x * blockDim.x + threadIdx.x) >> 5;
    int lane = threadIdx.x & 31;
    if (gw >= T_ * H_) return;
    float* kp = k + (size_t)gw * DK_;
    float k0 = kp[lane], k1 = kp[lane + 32];
    float s = k0 + k1;
    for (int off = 16; off > 0; off >>= 1) s += __shfl_xor_sync(0xffffffffu, s, off);
    float mean = s * (1.f / 64.f);
    k0 -= mean; k1 -= mean;
    float ss = k0 * k0 + k1 * k1;
    for (int off = 16; off > 0; off >>= 1) ss += __shfl_xor_sync(0xffffffffu, ss, off);
    float sc = rsqrtf(ss + 1e-6f);
    kp[lane] = k0 * sc; kp[lane + 32] = k1 * sc;

    float* qp = q + (size_t)gw * DK_;
    float q0 = qp[lane], q1 = qp[lane + 32];
    float qq = q0 * q0 + q1 * q1;
    for (int off = 16; off > 0; off >>= 1) qq += __shfl_xor_sync(0xffffffffu, qq, off);
    float qs = rsqrtf(qq + 1e-6f) * 0.125f;
    qp[lane] = q0 * qs; qp[lane + 32] = q1 * qs;
}

// ---------------- 6) gated delta-rule scan ----------------
__global__ __launch_bounds__(128) void scan_kernel(const float* __restrict__ q,
                                                   const float* __restrict__ k,
                                                   const float* __restrict__ v,
                                                   const float* __restrict__ beta,
                                                   const float* __restrict__ eg,
                                                   float* __restrict__ o) {
    int h = blockIdx.x >> 2;
    int dvq = blockIdx.x & 3;
    int tid = threadIdx.x;
    int dv_l = tid >> 2, qr = tid & 3;
    int dv = dvq * 32 + dv_l;

    __shared__ float ks[4][4][64], qs[4][4][64], vs[4][4][32], gb[4][4][2];

    int role = tid >> 5;
    int lane = tid & 31;

    float S[16];
    #pragma unroll
    for (int i = 0; i < 16; i++) S[i] = 0.f;

    const int NP = T_ / 4;

    #define ISSUE_STAGE(P) do {                                                       \
        int set_ = (P) & 3;                                                           \
        int t0_ = (P) * 4;                                                            \
        if (role == 0) {                                                              \
            _Pragma("unroll")                                                         \
            for (int r2 = 0; r2 < 2; r2++) {                                          \
                int idx = lane + r2 * 32;                                             \
                int ss = idx >> 4, ch = idx & 15;                                     \
                unsigned d = (unsigned)__cvta_generic_to_shared(&ks[set_][ss][ch*4]); \
                const float* sp = k + ((size_t)(t0_ + ss) * H_ + h) * DK_ + ch*4;     \
                CP16(d, sp);                                                          \
            }                                                                         \
        } else if (role == 1) {                                                       \
            _Pragma("unroll")                                                         \
            for (int r2 = 0; r2 < 2; r2++) {                                          \
                int idx = lane + r2 * 32;                                             \
                int ss = idx >> 4, ch = idx & 15;                                     \
                unsigned d = (unsigned)__cvta_generic_to_shared(&qs[set_][ss][ch*4]); \
                const float* sp = q + ((size_t)(t0_ + ss) * H_ + h) * DK_ + ch*4;     \
                CP16(d, sp);                                                          \
            }                                                                         \
        } else if (role == 2) {                                                       \
            int ss = lane >> 3, ch = lane & 7;                                        \
            unsigned d = (unsigned)__cvta_generic_to_shared(&vs[set_][ss][ch*4]);     \
            const float* sp = v + ((size_t)(t0_ + ss) * H_ + h) * DV_ + dvq*32 + ch*4;\
            CP16(d, sp);                                                              \
        } else if (lane < 8) {                                                        \
            int ss = lane >> 1; int which = lane & 1;                                 \
            unsigned d = (unsigned)__cvta_generic_to_shared(&gb[set_][ss][which]);    \
            const float* sp = (which ? beta : eg) + (size_t)(t0_ + ss) * H_ + h;      \
            asm volatile("cp.async.ca.shared.global [%0], [%1], 4;\n" :: "r"(d), "l"(sp)); \
        }                                                                             \
    } while (0)

    #pragma unroll
    for (int p = 0; p < 3; p++) {
        ISSUE_STAGE(p);
        asm volatile("cp.async.commit_group;\n");
    }

    for (int p = 0; p < NP; p++) {
        asm volatile("cp.async.wait_group 2;\n");
        __syncthreads();
        if (p + 3 < NP) ISSUE_STAGE(p + 3);
        asm volatile("cp.async.commit_group;\n");
        int set = p & 3;
        #pragma unroll
        for (int s = 0; s < 4; s++) {
            float egv = gb[set][s][0];
            float bt  = gb[set][s][1];
            float vv  = vs[set][s][dv_l];
            float kr[16];
            #pragma unroll
            for (int j = 0; j < 4; j++)
                *(float4*)&kr[j*4] = *(const float4*)&ks[set][s][qr*16 + j*4];
            float kv0 = 0.f, kv1 = 0.f, kv2 = 0.f, kv3 = 0.f;
            #pragma unroll
            for (int j = 0; j < 4; j++) {
                S[j*4+0] *= egv; kv0 = fmaf(kr[j*4+0], S[j*4+0], kv0);
                S[j*4+1] *= egv; kv1 = fmaf(kr[j*4+1], S[j*4+1], kv1);
                S[j*4+2] *= egv; kv2 = fmaf(kr[j*4+2], S[j*4+2], kv2);
                S[j*4+3] *= egv; kv3 = fmaf(kr[j*4+3], S[j*4+3], kv3);
            }
            float kv = (kv0 + kv1) + (kv2 + kv3);
            kv += __shfl_xor_sync(0xffffffffu, kv, 1);
            kv += __shfl_xor_sync(0xffffffffu, kv, 2);
            float vn = (vv - kv) * bt;
            float qv[16];
            #pragma unroll
            for (int j = 0; j < 4; j++)
                *(float4*)&qv[j*4] = *(const float4*)&qs[set][s][qr*16 + j*4];
            float o0 = 0.f, o1 = 0.f, o2 = 0.f, o3 = 0.f;
            #pragma unroll
            for (int j = 0; j < 4; j++) {
                S[j*4+0] = fmaf(kr[j*4+0], vn, S[j*4+0]); o0 = fmaf(qv[j*4+0], S[j*4+0], o0);
                S[j*4+1] = fmaf(kr[j*4+1], vn, S[j*4+1]); o1 = fmaf(qv[j*4+1], S[j*4+1], o1);
                S[j*4+2] = fmaf(kr[j*4+2], vn, S[j*4+2]); o2 = fmaf(qv[j*4+2], S[j*4+2], o2);
                S[j*4+3] = fmaf(kr[j*4+3], vn, S[j*4+3]); o3 = fmaf(qv[j*4+3], S[j*4+3], o3);
            }
            float oo = (o0 + o1) + (o2 + o3);
            oo += __shfl_xor_sync(0xffffffffu, oo, 1);
            oo += __shfl_xor_sync(0xffffffffu, oo, 2);
            if (qr == 0) o[((size_t)(p*4 + s) * H_ + h) * DV_ + dv] = oo;
        }
    }
    #undef ISSUE_STAGE
}

// ---------------- 7) gated RMSNorm + silu gate -> tf32 ----------------
__global__ void onorm_kernel(const float* __restrict__ o,
                             const float* __restrict__ gateb,   // g_big + 4096, ld=BIGN_
                             const float* __restrict__ onw,
                             unsigned* __restrict__ o2t) {
    int th = blockIdx.x;                 // t*H + h
    int t = th >> 4, h = th & 15;
    int i = threadIdx.x;                 // 0..127 = dv
    float val = o[(size_t)th * DV_ + i];
    float ss = val * val;
    for (int off = 16; off > 0; off >>= 1) ss += __shfl_xor_sync(0xffffffffu, ss, off);
    __shared__ float red[4];
    int warp = i >> 5, lane = i & 31;
    if (lane == 0) red[warp] = ss;
    __syncthreads();
    float tot = red[0] + red[1] + red[2] + red[3];
    float scale = rsqrtf(tot / (float)DV_ + 1e-5f);
    float gv = gateb[(size_t)t * BIGN_ + h * DV_ + i];
    float r = val * scale * onw[i] * (gv / (1.f + expf(-gv)));
    o2t[(size_t)th * DV_ + i] = f2tf32(r);
}

// ---------------- launcher ----------------
extern "C" void kernel_launch(void* const* d_in, const int* in_sizes, int n_in,
                              void* d_out, int out_size) {
    const float* hidden    = (const float*)d_in[0];
    const float* norm_w    = (const float*)d_in[1];
    const float* q_w       = (const float*)d_in[2];
    const float* k_w       = (const float*)d_in[3];
    const float* v_w       = (const float*)d_in[4];
    const float* a_w       = (const float*)d_in[5];
    const float* b_w       = (const float*)d_in[6];
    const float* g_w       = (const float*)d_in[7];
    const float* dt_bias   = (const float*)d_in[8];
    const float* A_log     = (const float*)d_in[9];
    const float* conv_q_w  = (const float*)d_in[10];
    const float* conv_k_w  = (const float*)d_in[11];
    const float* conv_v_w  = (const float*)d_in[12];
    const float* o_norm_w  = (const float*)d_in[13];
    const float* o_proj_w  = (const float*)d_in[14];
    const float* out_proj_w= (const float*)d_in[15];
    float* out = (float*)d_out;

    float *px, *prs, *pbig, *pq, *pk, *pv, *pbeta, *peg, *po;
    unsigned *pxt, *pwt, *po2t, *py1t;
    cudaGetSymbolAddress((void**)&px,    g_x);
    cudaGetSymbolAddress((void**)&pxt,   g_xt);
    cudaGetSymbolAddress((void**)&prs,   g_rs);
    cudaGetSymbolAddress((void**)&pwt,   g_wt);
    cudaGetSymbolAddress((void**)&pbig,  g_big);
    cudaGetSymbolAddress((void**)&pq,    g_q);
    cudaGetSymbolAddress((void**)&pk,    g_k);
    cudaGetSymbolAddress((void**)&pv,    g_v);
    cudaGetSymbolAddress((void**)&pbeta, g_beta);
    cudaGetSymbolAddress((void**)&peg,   g_eg);
    cudaGetSymbolAddress((void**)&po,    g_o);
    cudaGetSymbolAddress((void**)&po2t,  g_o2t);
    cudaGetSymbolAddress((void**)&py1t,  g_y1t);

    // 0) weights -> tf32 (concatenated)
    cvt_weights_kernel<<<WT_ELEMS/4/256, 256>>>(
        (const float4*)q_w, (const float4*)k_w, (const float4*)v_w,
        (const float4*)g_w, (const float4*)o_proj_w, (const float4*)out_proj_w,
        (uint4*)pwt);

    // 1) RMSNorm (reduce + apply, fp32 + tf32)
    rms_reduce_kernel<<<T_/8, 256>>>(hidden, prs);
    rms_apply_kernel<<<(T_*HID_/4)/256, 256>>>(hidden, prs, norm_w, px, pxt);

    // 2) beta / exp(g)
    ab_kernel<<<T_, 256>>>(px, a_w, b_w, dt_bias, A_log, pbeta, peg);

    // 3) fused q/k/v/g projection (plain GEMM on concatenated weights)
    gemm128_t<0><<<dim3(BIGN_/128, T_/128), 256>>>(pxt, pwt + WQKVG_OFF,
                                                   pbig, nullptr, HID_, BIGN_);

    // 4) fused convs + silu
    conv_fused_kernel<<<(T_*4096/4)/256, 256>>>(pbig, conv_q_w, conv_k_w, conv_v_w,
                                                pq, pk, pv);

    // 5) q/k normalize (+ k DC removal)
    qknorm_kernel<<<(T_*H_*32)/256, 256>>>(pq, pk);

    // 6) scan (dv split 4 -> 64 blocks)
    scan_kernel<<<H_*4, 128>>>(pq, pk, pv, pbeta, peg, po);

    // 7) gated output norm -> tf32
    onorm_kernel<<<T_*H_, 128>>>(po, pbig + 4096, o_norm_w, po2t);

    // 8) output projections
    gemm128_t<1><<<dim3(HID_/128, T_/128), 256>>>(po2t, pwt + WO_OFF,
                                                  nullptr, py1t, VAL_, HID_);
    gemm128_t<0><<<dim3(HID_/128, T_/128), 256>>>(py1t, pwt + WOUT_OFF,
                                                  out, nullptr, HID_, HID_);
}

// round 10
// speedup vs baseline: 4.8130x; 1.2718x over previous
#include <cuda_runtime.h>
#include <cuda_fp16.h>
#include <math.h>

// ---------------- problem dims (fixed) ----------------
#define T_    2048
#define HID_  1024
#define H_    16
#define DK_   64
#define DV_   128
#define VAL_  2048
#define QKD_  1024
#define CONV_ 4
#define BIGN_ 6272   // q(1024)+k(1024)+v(2048)+g(2048)+ab_pad(128)

// fp16 weight buffer offsets (halves)
#define WQKVG_OFF 0u
#define WAB_OFF   6291456u              // 6144*1024
#define WO_OFF    6422528u              // + 128*1024
#define WOUT_OFF  8519680u              // + 1024*2048
#define WT_HALVES 9568256u              // + 1024*1024

// ---------------- scratch (device globals) ----------------
__device__ __half g_wt  [WT_HALVES];
__device__ __half g_xh  [T_*HID_];
__device__ float  g_rs  [T_];
__device__ float  g_big [T_*BIGN_];
__device__ float  g_q   [T_*QKD_];
__device__ float  g_k   [T_*QKD_];
__device__ float  g_v   [T_*VAL_];
__device__ float  g_beta[T_*H_];
__device__ float  g_eg  [T_*H_];
__device__ float  g_o   [T_*VAL_];
__device__ __half g_o2h [T_*VAL_];
__device__ __half g_y1h [T_*HID_];

// ---------------- helpers ----------------
__device__ __forceinline__ unsigned pack2(float a, float b) {
    __half2 h = __floats2half2_rn(a, b);
    return *reinterpret_cast<unsigned*>(&h);
}
#define MMA_F16(C, A, B)                                                      \
    asm volatile("mma.sync.aligned.m16n8k16.row.col.f32.f16.f16.f32 "         \
                 "{%0,%1,%2,%3}, {%4,%5,%6,%7}, {%8,%9}, {%0,%1,%2,%3};"      \
                 : "+f"((C)[0]), "+f"((C)[1]), "+f"((C)[2]), "+f"((C)[3])     \
                 : "r"((A)[0]), "r"((A)[1]), "r"((A)[2]), "r"((A)[3]),        \
                   "r"((B)[0]), "r"((B)[1]))
#define LDSM4(R0, R1, R2, R3, addr)                                           \
    asm volatile("ldmatrix.sync.aligned.m8n8.x4.shared.b16 {%0,%1,%2,%3}, [%4];" \
                 : "=r"(R0), "=r"(R1), "=r"(R2), "=r"(R3) : "r"(addr))
#define CP16(dst, src) \
    asm volatile("cp.async.cg.shared.global [%0], [%1], 16;\n" :: "r"(dst), "l"(src))

// ---------------- 0a) weights -> fp16 (q,k,v,g,o,out concatenated) --------
// 8-float units; float4 stream: wq 262144 | wk 262144 | wv 524288 | wg 524288
//                               | wo 524288 | wout 262144
__global__ void cvt_weights_h(const float4* __restrict__ wq,
                              const float4* __restrict__ wk,
                              const float4* __restrict__ wv,
                              const float4* __restrict__ wg,
                              const float4* __restrict__ wo,
                              const float4* __restrict__ wout,
                              __half* __restrict__ dst) {
    int idx = blockIdx.x * 256 + threadIdx.x;       // 0 .. 1179647
    int f4 = idx * 2;
    const float4* src; int off;
    if (f4 < 262144)       { src = wq;   off = f4; }
    else if (f4 < 524288)  { src = wk;   off = f4 - 262144; }
    else if (f4 < 1048576) { src = wv;   off = f4 - 524288; }
    else if (f4 < 1572864) { src = wg;   off = f4 - 1048576; }
    else if (f4 < 2097152) { src = wo;   off = f4 - 1572864; }
    else                   { src = wout; off = f4 - 2097152; }
    unsigned hbase = (unsigned)idx * 8;
    if (hbase >= WAB_OFF) hbase += 131072;          // skip ab region
    float4 v0 = src[off], v1 = src[off + 1];
    uint4 u;
    u.x = pack2(v0.x, v0.y); u.y = pack2(v0.z, v0.w);
    u.z = pack2(v1.x, v1.y); u.w = pack2(v1.z, v1.w);
    *(uint4*)&dst[hbase] = u;
}

// ---------------- 0b) a_w/b_w -> fp16 padded 128x1024 tile ----------------
__global__ void cvt_ab_h(const float* __restrict__ a_w,
                         const float* __restrict__ b_w,
                         __half* __restrict__ dst) {
    int u = blockIdx.x * 256 + threadIdx.x;         // 0 .. 16383 (8 halves each)
    int base = u * 8;
    int row = base >> 10, col = base & 1023;
    float vals[8];
    #pragma unroll
    for (int i = 0; i < 8; i++) vals[i] = 0.f;
    if (row < 16) {
        #pragma unroll
        for (int i = 0; i < 8; i++) vals[i] = a_w[row * 1024 + col + i];
    } else if (row < 32) {
        #pragma unroll
        for (int i = 0; i < 8; i++) vals[i] = b_w[(row - 16) * 1024 + col + i];
    }
    uint4 uu;
    uu.x = pack2(vals[0], vals[1]); uu.y = pack2(vals[2], vals[3]);
    uu.z = pack2(vals[4], vals[5]); uu.w = pack2(vals[6], vals[7]);
    *(uint4*)&dst[WAB_OFF + base] = uu;
}

// ---------------- 1a) RMSNorm reduce ----------------
__global__ void rms_reduce_kernel(const float* __restrict__ h,
                                  float* __restrict__ rs) {
    int row = blockIdx.x * 8 + (threadIdx.x >> 5);
    int lane = threadIdx.x & 31;
    const float4* p = (const float4*)(h + (size_t)row * HID_);
    float ss = 0.f;
    #pragma unroll
    for (int i = 0; i < 8; i++) {
        float4 v = p[lane + i * 32];
        ss += v.x * v.x + v.y * v.y + v.z * v.z + v.w * v.w;
    }
    for (int off = 16; off > 0; off >>= 1) ss += __shfl_xor_sync(0xffffffffu, ss, off);
    if (lane == 0) rs[row] = rsqrtf(ss / (float)HID_ + 1e-6f);
}

// ---------------- 1b) RMSNorm apply -> fp16 ----------------
__global__ void rms_apply_kernel(const float* __restrict__ h,
                                 const float* __restrict__ rs,
                                 const float* __restrict__ w,
                                 __half* __restrict__ xh) {
    int idx = blockIdx.x * blockDim.x + threadIdx.x;   // float4 index
    int t = idx >> 8;
    float s = rs[t];
    float4 hv = ((const float4*)h)[idx];
    float4 wv = ((const float4*)w)[idx & 255];
    uint2 u;
    u.x = pack2(hv.x * s * wv.x, hv.y * s * wv.y);
    u.y = pack2(hv.z * s * wv.z, hv.w * s * wv.w);
    ((uint2*)xh)[idx] = u;
}

// ---------------- 2) 128x128 FP16 GEMM, cp.async + ldmatrix ----------------
// C[M,N] = X[M,K] @ W[N,K]^T. smem rows padded to 40 halves (conflict-free).
#define HPAD 40
template<int OUT_HALF>
__global__ __launch_bounds__(256, 2) void gemm128_h(const __half* __restrict__ X,
                                                    const __half* __restrict__ W,
                                                    float* __restrict__ Cf,
                                                    __half* __restrict__ Ch,
                                                    int K, int ldc) {
    __shared__ __half As[2][128][HPAD];
    __shared__ __half Bs[2][128][HPAD];
    const __half* Xt = X + (size_t)blockIdx.y * 128 * K;
    const __half* Wt = W + (size_t)blockIdx.x * 128 * K;
    int tid = threadIdx.x, wid = tid >> 5, lane = tid & 31;
    int wm = (wid >> 2) * 64, wn = (wid & 3) * 32;
    int gid = lane >> 2, tig = lane & 3;
    int t4 = lane >> 3, l8 = lane & 7;
    int aRow = (t4 & 1) * 8 + l8, aCol = (t4 >> 1) * 8;
    int bRow = (t4 >> 1) * 8 + l8, bCol = (t4 & 1) * 8;

    int lr = tid >> 1, hc = (tid & 1) * 16;
    const __half* xs = Xt + (size_t)lr * K + hc;
    const __half* ws = Wt + (size_t)lr * K + hc;
    unsigned abase = (unsigned)__cvta_generic_to_shared(&As[0][0][0]);
    unsigned bbase = (unsigned)__cvta_generic_to_shared(&Bs[0][0][0]);
    unsigned daw = abase + (lr * HPAD + hc) * 2;
    unsigned dbw = bbase + (lr * HPAD + hc) * 2;
    const unsigned BUF = 128 * HPAD * 2;

    float acc[16][4];
    #pragma unroll
    for (int i = 0; i < 16; i++)
        #pragma unroll
        for (int j = 0; j < 4; j++) acc[i][j] = 0.f;

    // prologue: stage 0
    CP16(daw, xs); CP16(daw + 16, xs + 8);
    CP16(dbw, ws); CP16(dbw + 16, ws + 8);
    asm volatile("cp.async.commit_group;\n");

    int nk = K / 32;
    for (int it = 0; it < nk; it++) {
        int buf = it & 1;
        asm volatile("cp.async.wait_group 0;\n");
        __syncthreads();
        if (it + 1 < nk) {
            int k0 = (it + 1) * 32;
            unsigned boff = (buf ^ 1) * BUF;
            CP16(daw + boff, xs + k0); CP16(daw + boff + 16, xs + k0 + 8);
            CP16(dbw + boff, ws + k0); CP16(dbw + boff + 16, ws + k0 + 8);
            asm volatile("cp.async.commit_group;\n");
        }
        unsigned ab = abase + buf * BUF, bb = bbase + buf * BUF;
        #pragma unroll
        for (int k16 = 0; k16 < 2; k16++) {
            int kk = k16 * 16;
            unsigned a[4][4], b[4][2];
            #pragma unroll
            for (int mt = 0; mt < 4; mt++) {
                unsigned addr = ab + ((wm + mt * 16 + aRow) * HPAD + kk + aCol) * 2;
                LDSM4(a[mt][0], a[mt][1], a[mt][2], a[mt][3], addr);
            }
            #pragma unroll
            for (int p = 0; p < 2; p++) {
                unsigned addr = bb + ((wn + p * 16 + bRow) * HPAD + kk + bCol) * 2;
                LDSM4(b[p*2][0], b[p*2][1], b[p*2+1][0], b[p*2+1][1], addr);
            }
            #pragma unroll
            for (int mt = 0; mt < 4; mt++)
                #pragma unroll
                for (int nt = 0; nt < 4; nt++)
                    MMA_F16(acc[mt * 4 + nt], a[mt], b[nt]);
        }
    }

    size_t base = (size_t)blockIdx.y * 128 * ldc + blockIdx.x * 128;
    #pragma unroll
    for (int mt = 0; mt < 4; mt++) {
        int row = wm + mt * 16 + gid;
        #pragma unroll
        for (int nt = 0; nt < 4; nt++) {
            int col = wn + nt * 8 + tig * 2;
            float* c = acc[mt * 4 + nt];
            if (OUT_HALF) {
                *(unsigned*)&Ch[base + (size_t)row * ldc + col]       = pack2(c[0], c[1]);
                *(unsigned*)&Ch[base + (size_t)(row + 8) * ldc + col] = pack2(c[2], c[3]);
            } else {
                *(float2*)&Cf[base + (size_t)row * ldc + col]       = make_float2(c[0], c[1]);
                *(float2*)&Cf[base + (size_t)(row + 8) * ldc + col] = make_float2(c[2], c[3]);
            }
        }
    }
}

// ---------------- 3) beta / exp(g) from GEMM columns ----------------
__global__ void beta_eg_kernel(const float* __restrict__ big,
                               const float* __restrict__ dt_bias,
                               const float* __restrict__ A_log,
                               float* __restrict__ beta,
                               float* __restrict__ eg) {
    int i = blockIdx.x * 256 + threadIdx.x;   // T_*H_ = 32768
    int t = i >> 4, h = i & 15;
    float da = big[(size_t)t * BIGN_ + 6144 + h];
    float db = big[(size_t)t * BIGN_ + 6160 + h];
    beta[i] = 1.f / (1.f + expf(-db));
    float z = da + dt_bias[h];
    float sp = (z > 20.f) ? z : log1pf(expf(z));
    eg[i] = expf(-expf(A_log[h]) * sp);
}

// ---------------- 4) fused causal conv (K=4) + silu ----------------
__global__ void conv_fused_kernel(const float* __restrict__ big,
                                  const float* __restrict__ wq,
                                  const float* __restrict__ wk,
                                  const float* __restrict__ wv,
                                  float* __restrict__ oq,
                                  float* __restrict__ ok,
                                  float* __restrict__ ov) {
    int idx = blockIdx.x * blockDim.x + threadIdx.x;   // over T_*4096/4
    int t = idx >> 10;
    int c4 = (idx & 1023) * 4;
    const float* w; float* outp; int cl;
    if (c4 < 1024)      { w = wq; outp = oq + (size_t)t * QKD_ + c4;        cl = c4; }
    else if (c4 < 2048) { w = wk; outp = ok + (size_t)t * QKD_ + c4 - 1024; cl = c4 - 1024; }
    else                { w = wv; outp = ov + (size_t)t * VAL_ + c4 - 2048; cl = c4 - 2048; }
    float4 w0 = ((const float4*)w)[cl + 0];
    float4 w1 = ((const float4*)w)[cl + 1];
    float4 w2 = ((const float4*)w)[cl + 2];
    float4 w3 = ((const float4*)w)[cl + 3];
    float4 acc = make_float4(0.f, 0.f, 0.f, 0.f);
    #pragma unroll
    for (int i = 0; i < CONV_; i++) {
        int tt = t - 3 + i;
        if (tt >= 0) {
            float4 xv = *(const float4*)(big + (size_t)tt * BIGN_ + c4);
            acc.x = fmaf(xv.x, (&w0.x)[i], acc.x);
            acc.y = fmaf(xv.y, (&w1.x)[i], acc.y);
            acc.z = fmaf(xv.z, (&w2.x)[i], acc.z);
            acc.w = fmaf(xv.w, (&w3.x)[i], acc.w);
        }
    }
    acc.x *= 1.f / (1.f + __expf(-acc.x));
    acc.y *= 1.f / (1.f + __expf(-acc.y));
    acc.z *= 1.f / (1.f + __expf(-acc.z));
    acc.w *= 1.f / (1.f + __expf(-acc.w));
    *(float4*)outp = acc;
}

// ---------------- 5) k DC-removal + q/k L2 normalize ----------------
__global__ void qknorm_kernel(float* __restrict__ q, float* __restrict__ k) {
    int gw = (blockIdx.x * blockDim.x + threadIdx.x) >> 5;
    int lane = threadIdx.x & 31;
    if (gw >= T_ * H_) return;
    float* kp = k + (size_t)gw * DK_;
    float k0 = kp[lane], k1 = kp[lane + 32];
    float s = k0 + k1;
    for (int off = 16; off > 0; off >>= 1) s += __shfl_xor_sync(0xffffffffu, s, off);
    float mean = s * (1.f / 64.f);
    k0 -= mean; k1 -= mean;
    float ss = k0 * k0 + k1 * k1;
    for (int off = 16; off > 0; off >>= 1) ss += __shfl_xor_sync(0xffffffffu, ss, off);
    float sc = rsqrtf(ss + 1e-6f);
    kp[lane] = k0 * sc; kp[lane + 32] = k1 * sc;

    float* qp = q + (size_t)gw * DK_;
    float q0 = qp[lane], q1 = qp[lane + 32];
    float qq = q0 * q0 + q1 * q1;
    for (int off = 16; off > 0; off >>= 1) qq += __shfl_xor_sync(0xffffffffu, qq, off);
    float qs = rsqrtf(qq + 1e-6f) * 0.125f;
    qp[lane] = q0 * qs; qp[lane + 32] = q1 * qs;
}

// ---------------- 6) gated delta-rule scan ----------------
__global__ __launch_bounds__(128) void scan_kernel(const float* __restrict__ q,
                                                   const float* __restrict__ k,
                                                   const float* __restrict__ v,
                                                   const float* __restrict__ beta,
                                                   const float* __restrict__ eg,
                                                   float* __restrict__ o) {
    int h = blockIdx.x >> 2;
    int dvq = blockIdx.x & 3;
    int tid = threadIdx.x;
    int dv_l = tid >> 2, qr = tid & 3;
    int dv = dvq * 32 + dv_l;

    __shared__ float ks[4][4][64], qs[4][4][64], vs[4][4][32], gb[4][4][2];

    int role = tid >> 5;
    int lane = tid & 31;

    float S[16];
    #pragma unroll
    for (int i = 0; i < 16; i++) S[i] = 0.f;

    const int NP = T_ / 4;

    #define ISSUE_STAGE(P) do {                                                       \
        int set_ = (P) & 3;                                                           \
        int t0_ = (P) * 4;                                                            \
        if (role == 0) {                                                              \
            _Pragma("unroll")                                                         \
            for (int r2 = 0; r2 < 2; r2++) {                                          \
                int idx = lane + r2 * 32;                                             \
                int ss = idx >> 4, ch = idx & 15;                                     \
                unsigned d = (unsigned)__cvta_generic_to_shared(&ks[set_][ss][ch*4]); \
                const float* sp = k + ((size_t)(t0_ + ss) * H_ + h) * DK_ + ch*4;     \
                CP16(d, sp);                                                          \
            }                                                                         \
        } else if (role == 1) {                                                       \
            _Pragma("unroll")                                                         \
            for (int r2 = 0; r2 < 2; r2++) {                                          \
                int idx = lane + r2 * 32;                                             \
                int ss = idx >> 4, ch = idx & 15;                                     \
                unsigned d = (unsigned)__cvta_generic_to_shared(&qs[set_][ss][ch*4]); \
                const float* sp = q + ((size_t)(t0_ + ss) * H_ + h) * DK_ + ch*4;     \
                CP16(d, sp);                                                          \
            }                                                                         \
        } else if (role == 2) {                                                       \
            int ss = lane >> 3, ch = lane & 7;                                        \
            unsigned d = (unsigned)__cvta_generic_to_shared(&vs[set_][ss][ch*4]);     \
            const float* sp = v + ((size_t)(t0_ + ss) * H_ + h) * DV_ + dvq*32 + ch*4;\
            CP16(d, sp);                                                              \
        } else if (lane < 8) {                                                        \
            int ss = lane >> 1; int which = lane & 1;                                 \
            unsigned d = (unsigned)__cvta_generic_to_shared(&gb[set_][ss][which]);    \
            const float* sp = (which ? beta : eg) + (size_t)(t0_ + ss) * H_ + h;      \
            asm volatile("cp.async.ca.shared.global [%0], [%1], 4;\n" :: "r"(d), "l"(sp)); \
        }                                                                             \
    } while (0)

    #pragma unroll
    for (int p = 0; p < 3; p++) {
        ISSUE_STAGE(p);
        asm volatile("cp.async.commit_group;\n");
    }

    for (int p = 0; p < NP; p++) {
        asm volatile("cp.async.wait_group 2;\n");
        __syncthreads();
        if (p + 3 < NP) ISSUE_STAGE(p + 3);
        asm volatile("cp.async.commit_group;\n");
        int set = p & 3;
        #pragma unroll
        for (int s = 0; s < 4; s++) {
            float egv = gb[set][s][0];
            float bt  = gb[set][s][1];
            float vv  = vs[set][s][dv_l];
            float kr[16];
            #pragma unroll
            for (int j = 0; j < 4; j++)
                *(float4*)&kr[j*4] = *(const float4*)&ks[set][s][qr*16 + j*4];
            float kv0 = 0.f, kv1 = 0.f, kv2 = 0.f, kv3 = 0.f;
            #pragma unroll
            for (int j = 0; j < 4; j++) {
                S[j*4+0] *= egv; kv0 = fmaf(kr[j*4+0], S[j*4+0], kv0);
                S[j*4+1] *= egv; kv1 = fmaf(kr[j*4+1], S[j*4+1], kv1);
                S[j*4+2] *= egv; kv2 = fmaf(kr[j*4+2], S[j*4+2], kv2);
                S[j*4+3] *= egv; kv3 = fmaf(kr[j*4+3], S[j*4+3], kv3);
            }
            float kv = (kv0 + kv1) + (kv2 + kv3);
            kv += __shfl_xor_sync(0xffffffffu, kv, 1);
            kv += __shfl_xor_sync(0xffffffffu, kv, 2);
            float vn = (vv - kv) * bt;
            float qv[16];
            #pragma unroll
            for (int j = 0; j < 4; j++)
                *(float4*)&qv[j*4] = *(const float4*)&qs[set][s][qr*16 + j*4];
            float o0 = 0.f, o1 = 0.f, o2 = 0.f, o3 = 0.f;
            #pragma unroll
            for (int j = 0; j < 4; j++) {
                S[j*4+0] = fmaf(kr[j*4+0], vn, S[j*4+0]); o0 = fmaf(qv[j*4+0], S[j*4+0], o0);
                S[j*4+1] = fmaf(kr[j*4+1], vn, S[j*4+1]); o1 = fmaf(qv[j*4+1], S[j*4+1], o1);
                S[j*4+2] = fmaf(kr[j*4+2], vn, S[j*4+2]); o2 = fmaf(qv[j*4+2], S[j*4+2], o2);
                S[j*4+3] = fmaf(kr[j*4+3], vn, S[j*4+3]); o3 = fmaf(qv[j*4+3], S[j*4+3], o3);
            }
            float oo = (o0 + o1) + (o2 + o3);
            oo += __shfl_xor_sync(0xffffffffu, oo, 1);
            oo += __shfl_xor_sync(0xffffffffu, oo, 2);
            if (qr == 0) o[((size_t)(p*4 + s) * H_ + h) * DV_ + dv] = oo;
        }
    }
    #undef ISSUE_STAGE
}

// ---------------- 7) gated RMSNorm + silu gate -> fp16 ----------------
__global__ void onorm_kernel(const float* __restrict__ o,
                             const float* __restrict__ gateb,   // g_big + 4096, ld=BIGN_
                             const float* __restrict__ onw,
                             __half* __restrict__ o2h) {
    int th = blockIdx.x;                 // t*H + h
    int t = th >> 4, h = th & 15;
    int i = threadIdx.x;                 // 0..127 = dv
    float val = o[(size_t)th * DV_ + i];
    float ss = val * val;
    for (int off = 16; off > 0; off >>= 1) ss += __shfl_xor_sync(0xffffffffu, ss, off);
    __shared__ float red[4];
    int warp = i >> 5, lane = i & 31;
    if (lane == 0) red[warp] = ss;
    __syncthreads();
    float tot = red[0] + red[1] + red[2] + red[3];
    float scale = rsqrtf(tot / (float)DV_ + 1e-5f);
    float gv = gateb[(size_t)t * BIGN_ + h * DV_ + i];
    float r = val * scale * onw[i] * (gv / (1.f + expf(-gv)));
    o2h[(size_t)th * DV_ + i] = __float2half_rn(r);
}

// ---------------- launcher ----------------
extern "C" void kernel_launch(void* const* d_in, const int* in_sizes, int n_in,
                              void* d_out, int out_size) {
    const float* hidden    = (const float*)d_in[0];
    const float* norm_w    = (const float*)d_in[1];
    const float* q_w       = (const float*)d_in[2];
    const float* k_w       = (const float*)d_in[3];
    const float* v_w       = (const float*)d_in[4];
    const float* a_w       = (const float*)d_in[5];
    const float* b_w       = (const float*)d_in[6];
    const float* g_w       = (const float*)d_in[7];
    const float* dt_bias   = (const float*)d_in[8];
    const float* A_log     = (const float*)d_in[9];
    const float* conv_q_w  = (const float*)d_in[10];
    const float* conv_k_w  = (const float*)d_in[11];
    const float* conv_v_w  = (const float*)d_in[12];
    const float* o_norm_w  = (const float*)d_in[13];
    const float* o_proj_w  = (const float*)d_in[14];
    const float* out_proj_w= (const float*)d_in[15];
    float* out = (float*)d_out;

    float *prs, *pbig, *pq, *pk, *pv, *pbeta, *peg, *po;
    __half *pwt, *pxh, *po2h, *py1h;
    cudaGetSymbolAddress((void**)&pwt,   g_wt);
    cudaGetSymbolAddress((void**)&pxh,   g_xh);
    cudaGetSymbolAddress((void**)&prs,   g_rs);
    cudaGetSymbolAddress((void**)&pbig,  g_big);
    cudaGetSymbolAddress((void**)&pq,    g_q);
    cudaGetSymbolAddress((void**)&pk,    g_k);
    cudaGetSymbolAddress((void**)&pv,    g_v);
    cudaGetSymbolAddress((void**)&pbeta, g_beta);
    cudaGetSymbolAddress((void**)&peg,   g_eg);
    cudaGetSymbolAddress((void**)&po,    g_o);
    cudaGetSymbolAddress((void**)&po2h,  g_o2h);
    cudaGetSymbolAddress((void**)&py1h,  g_y1h);

    // 0) weights -> fp16
    cvt_weights_h<<<1179648/256, 256>>>(
        (const float4*)q_w, (const float4*)k_w, (const float4*)v_w,
        (const float4*)g_w, (const float4*)o_proj_w, (const float4*)out_proj_w, pwt);
    cvt_ab_h<<<16384/256, 256>>>(a_w, b_w, pwt);

    // 1) RMSNorm
    rms_reduce_kernel<<<T_/8, 256>>>(hidden, prs);
    rms_apply_kernel<<<(T_*HID_/4)/256, 256>>>(hidden, prs, norm_w, pxh);

    // 2) fused q/k/v/g/ab projection (fp16 MMA)
    gemm128_h<0><<<dim3(BIGN_/128, T_/128), 256>>>(pxh, pwt + WQKVG_OFF,
                                                   pbig, nullptr, HID_, BIGN_);

    // 3) beta / exp(g) from GEMM columns
    beta_eg_kernel<<<(T_*H_)/256, 256>>>(pbig, dt_bias, A_log, pbeta, peg);

    // 4) fused convs + silu
    conv_fused_kernel<<<(T_*4096/4)/256, 256>>>(pbig, conv_q_w, conv_k_w, conv_v_w,
                                                pq, pk, pv);

    // 5) q/k normalize (+ k DC removal)
    qknorm_kernel<<<(T_*H_*32)/256, 256>>>(pq, pk);

    // 6) scan
    scan_kernel<<<H_*4, 128>>>(pq, pk, pv, pbeta, peg, po);

    // 7) gated output norm -> fp16
    onorm_kernel<<<T_*H_, 128>>>(po, pbig + 4096, o_norm_w, po2h);

    // 8) output projections (fp16 MMA)
    gemm128_h<1><<<dim3(HID_/128, T_/128), 256>>>(po2h, pwt + WO_OFF,
                                                  nullptr, py1h, VAL_, HID_);
    gemm128_h<0><<<dim3(HID_/128, T_/128), 256>>>(py1h, pwt + WOUT_OFF,
                                                  out, nullptr, HID_, HID_);
}

// round 11
// speedup vs baseline: 5.5164x; 1.1461x over previous
#include <cuda_runtime.h>
#include <cuda_fp16.h>
#include <math.h>

// ---------------- problem dims (fixed) ----------------
#define T_    2048
#define HID_  1024
#define H_    16
#define DK_   64
#define DV_   128
#define VAL_  2048
#define QKD_  1024
#define CONV_ 4
#define BIGN_ 6272   // q(1024)+k(1024)+v(2048)+g(2048)+ab_pad(128)

// fp16 weight buffer offsets (halves)
#define WQKVG_OFF 0u
#define WAB_OFF   6291456u              // 6144*1024
#define WO_OFF    6422528u              // + 128*1024
#define WOUT_OFF  8519680u              // + 1024*2048
#define WT_HALVES 9568256u              // + 1024*1024

// ---------------- scratch (device globals) ----------------
__device__ __half g_wt  [WT_HALVES];
__device__ __half g_xh  [T_*HID_];
__device__ float  g_rs  [T_];
__device__ float  g_big [T_*BIGN_];
__device__ float  g_q   [T_*QKD_];
__device__ float  g_k   [T_*QKD_];
__device__ float  g_v   [T_*VAL_];
__device__ float  g_beta[T_*H_];
__device__ float  g_eg  [T_*H_];
__device__ float  g_o   [T_*VAL_];
__device__ __half g_o2h [T_*VAL_];
__device__ __half g_y1h [T_*HID_];

// ---------------- helpers ----------------
__device__ __forceinline__ unsigned pack2(float a, float b) {
    __half2 h = __floats2half2_rn(a, b);
    return *reinterpret_cast<unsigned*>(&h);
}
#define MMA_F16(C, A, B)                                                      \
    asm volatile("mma.sync.aligned.m16n8k16.row.col.f32.f16.f16.f32 "         \
                 "{%0,%1,%2,%3}, {%4,%5,%6,%7}, {%8,%9}, {%0,%1,%2,%3};"      \
                 : "+f"((C)[0]), "+f"((C)[1]), "+f"((C)[2]), "+f"((C)[3])     \
                 : "r"((A)[0]), "r"((A)[1]), "r"((A)[2]), "r"((A)[3]),        \
                   "r"((B)[0]), "r"((B)[1]))
#define LDSM4(R0, R1, R2, R3, addr)                                           \
    asm volatile("ldmatrix.sync.aligned.m8n8.x4.shared.b16 {%0,%1,%2,%3}, [%4];" \
                 : "=r"(R0), "=r"(R1), "=r"(R2), "=r"(R3) : "r"(addr))
#define CP16(dst, src) \
    asm volatile("cp.async.cg.shared.global [%0], [%1], 16;\n" :: "r"(dst), "l"(src))

// ---------------- 0a) weights -> fp16 (q,k,v,g,o,out concatenated) --------
__global__ void cvt_weights_h(const float4* __restrict__ wq,
                              const float4* __restrict__ wk,
                              const float4* __restrict__ wv,
                              const float4* __restrict__ wg,
                              const float4* __restrict__ wo,
                              const float4* __restrict__ wout,
                              __half* __restrict__ dst) {
    int idx = blockIdx.x * 256 + threadIdx.x;       // 0 .. 1179647
    int f4 = idx * 2;
    const float4* src; int off;
    if (f4 < 262144)       { src = wq;   off = f4; }
    else if (f4 < 524288)  { src = wk;   off = f4 - 262144; }
    else if (f4 < 1048576) { src = wv;   off = f4 - 524288; }
    else if (f4 < 1572864) { src = wg;   off = f4 - 1048576; }
    else if (f4 < 2097152) { src = wo;   off = f4 - 1572864; }
    else                   { src = wout; off = f4 - 2097152; }
    unsigned hbase = (unsigned)idx * 8;
    if (hbase >= WAB_OFF) hbase += 131072;          // skip ab region
    float4 v0 = src[off], v1 = src[off + 1];
    uint4 u;
    u.x = pack2(v0.x, v0.y); u.y = pack2(v0.z, v0.w);
    u.z = pack2(v1.x, v1.y); u.w = pack2(v1.z, v1.w);
    *(uint4*)&dst[hbase] = u;
}

// ---------------- 0b) a_w/b_w -> fp16 padded 128x1024 tile ----------------
__global__ void cvt_ab_h(const float* __restrict__ a_w,
                         const float* __restrict__ b_w,
                         __half* __restrict__ dst) {
    int u = blockIdx.x * 256 + threadIdx.x;
    int base = u * 8;
    int row = base >> 10, col = base & 1023;
    float vals[8];
    #pragma unroll
    for (int i = 0; i < 8; i++) vals[i] = 0.f;
    if (row < 16) {
        #pragma unroll
        for (int i = 0; i < 8; i++) vals[i] = a_w[row * 1024 + col + i];
    } else if (row < 32) {
        #pragma unroll
        for (int i = 0; i < 8; i++) vals[i] = b_w[(row - 16) * 1024 + col + i];
    }
    uint4 uu;
    uu.x = pack2(vals[0], vals[1]); uu.y = pack2(vals[2], vals[3]);
    uu.z = pack2(vals[4], vals[5]); uu.w = pack2(vals[6], vals[7]);
    *(uint4*)&dst[WAB_OFF + base] = uu;
}

// ---------------- 1a) RMSNorm reduce ----------------
__global__ void rms_reduce_kernel(const float* __restrict__ h,
                                  float* __restrict__ rs) {
    int row = blockIdx.x * 8 + (threadIdx.x >> 5);
    int lane = threadIdx.x & 31;
    const float4* p = (const float4*)(h + (size_t)row * HID_);
    float ss = 0.f;
    #pragma unroll
    for (int i = 0; i < 8; i++) {
        float4 v = p[lane + i * 32];
        ss += v.x * v.x + v.y * v.y + v.z * v.z + v.w * v.w;
    }
    for (int off = 16; off > 0; off >>= 1) ss += __shfl_xor_sync(0xffffffffu, ss, off);
    if (lane == 0) rs[row] = rsqrtf(ss / (float)HID_ + 1e-6f);
}

// ---------------- 1b) RMSNorm apply -> fp16 ----------------
__global__ void rms_apply_kernel(const float* __restrict__ h,
                                 const float* __restrict__ rs,
                                 const float* __restrict__ w,
                                 __half* __restrict__ xh) {
    int idx = blockIdx.x * blockDim.x + threadIdx.x;
    int t = idx >> 8;
    float s = rs[t];
    float4 hv = ((const float4*)h)[idx];
    float4 wv = ((const float4*)w)[idx & 255];
    uint2 u;
    u.x = pack2(hv.x * s * wv.x, hv.y * s * wv.y);
    u.y = pack2(hv.z * s * wv.z, hv.w * s * wv.w);
    ((uint2*)xh)[idx] = u;
}

// ---------------- 2) 128x128 FP16 GEMM, cp.async + ldmatrix ----------------
#define HPAD 40
template<int OUT_HALF>
__global__ __launch_bounds__(256, 2) void gemm128_h(const __half* __restrict__ X,
                                                    const __half* __restrict__ W,
                                                    float* __restrict__ Cf,
                                                    __half* __restrict__ Ch,
                                                    int K, int ldc) {
    __shared__ __half As[2][128][HPAD];
    __shared__ __half Bs[2][128][HPAD];
    const __half* Xt = X + (size_t)blockIdx.y * 128 * K;
    const __half* Wt = W + (size_t)blockIdx.x * 128 * K;
    int tid = threadIdx.x, wid = tid >> 5, lane = tid & 31;
    int wm = (wid >> 2) * 64, wn = (wid & 3) * 32;
    int gid = lane >> 2, tig = lane & 3;
    int t4 = lane >> 3, l8 = lane & 7;
    int aRow = (t4 & 1) * 8 + l8, aCol = (t4 >> 1) * 8;
    int bRow = (t4 >> 1) * 8 + l8, bCol = (t4 & 1) * 8;

    int lr = tid >> 1, hc = (tid & 1) * 16;
    const __half* xs = Xt + (size_t)lr * K + hc;
    const __half* ws = Wt + (size_t)lr * K + hc;
    unsigned abase = (unsigned)__cvta_generic_to_shared(&As[0][0][0]);
    unsigned bbase = (unsigned)__cvta_generic_to_shared(&Bs[0][0][0]);
    unsigned daw = abase + (lr * HPAD + hc) * 2;
    unsigned dbw = bbase + (lr * HPAD + hc) * 2;
    const unsigned BUF = 128 * HPAD * 2;

    float acc[16][4];
    #pragma unroll
    for (int i = 0; i < 16; i++)
        #pragma unroll
        for (int j = 0; j < 4; j++) acc[i][j] = 0.f;

    CP16(daw, xs); CP16(daw + 16, xs + 8);
    CP16(dbw, ws); CP16(dbw + 16, ws + 8);
    asm volatile("cp.async.commit_group;\n");

    int nk = K / 32;
    for (int it = 0; it < nk; it++) {
        int buf = it & 1;
        asm volatile("cp.async.wait_group 0;\n");
        __syncthreads();
        if (it + 1 < nk) {
            int k0 = (it + 1) * 32;
            unsigned boff = (buf ^ 1) * BUF;
            CP16(daw + boff, xs + k0); CP16(daw + boff + 16, xs + k0 + 8);
            CP16(dbw + boff, ws + k0); CP16(dbw + boff + 16, ws + k0 + 8);
            asm volatile("cp.async.commit_group;\n");
        }
        unsigned ab = abase + buf * BUF, bb = bbase + buf * BUF;
        #pragma unroll
        for (int k16 = 0; k16 < 2; k16++) {
            int kk = k16 * 16;
            unsigned a[4][4], b[4][2];
            #pragma unroll
            for (int mt = 0; mt < 4; mt++) {
                unsigned addr = ab + ((wm + mt * 16 + aRow) * HPAD + kk + aCol) * 2;
                LDSM4(a[mt][0], a[mt][1], a[mt][2], a[mt][3], addr);
            }
            #pragma unroll
            for (int p = 0; p < 2; p++) {
                unsigned addr = bb + ((wn + p * 16 + bRow) * HPAD + kk + bCol) * 2;
                LDSM4(b[p*2][0], b[p*2][1], b[p*2+1][0], b[p*2+1][1], addr);
            }
            #pragma unroll
            for (int mt = 0; mt < 4; mt++)
                #pragma unroll
                for (int nt = 0; nt < 4; nt++)
                    MMA_F16(acc[mt * 4 + nt], a[mt], b[nt]);
        }
    }

    size_t base = (size_t)blockIdx.y * 128 * ldc + blockIdx.x * 128;
    #pragma unroll
    for (int mt = 0; mt < 4; mt++) {
        int row = wm + mt * 16 + gid;
        #pragma unroll
        for (int nt = 0; nt < 4; nt++) {
            int col = wn + nt * 8 + tig * 2;
            float* c = acc[mt * 4 + nt];
            if (OUT_HALF) {
                *(unsigned*)&Ch[base + (size_t)row * ldc + col]       = pack2(c[0], c[1]);
                *(unsigned*)&Ch[base + (size_t)(row + 8) * ldc + col] = pack2(c[2], c[3]);
            } else {
                *(float2*)&Cf[base + (size_t)row * ldc + col]       = make_float2(c[0], c[1]);
                *(float2*)&Cf[base + (size_t)(row + 8) * ldc + col] = make_float2(c[2], c[3]);
            }
        }
    }
}

// ---------------- 3) beta / exp(g) from GEMM columns ----------------
__global__ void beta_eg_kernel(const float* __restrict__ big,
                               const float* __restrict__ dt_bias,
                               const float* __restrict__ A_log,
                               float* __restrict__ beta,
                               float* __restrict__ eg) {
    int i = blockIdx.x * 256 + threadIdx.x;   // T_*H_ = 32768
    int t = i >> 4, h = i & 15;
    float da = big[(size_t)t * BIGN_ + 6144 + h];
    float db = big[(size_t)t * BIGN_ + 6160 + h];
    beta[i] = 1.f / (1.f + expf(-db));
    float z = da + dt_bias[h];
    float sp = (z > 20.f) ? z : log1pf(expf(z));
    eg[i] = expf(-expf(A_log[h]) * sp);
}

// ---------------- 4a) fused conv(q,k) + silu + DC-removal + L2 norm -------
// one warp per (t,h): 2 q-channels + 2 k-channels per lane.
__global__ void conv_qk_kernel(const float* __restrict__ big,
                               const float* __restrict__ wq,
                               const float* __restrict__ wk,
                               float* __restrict__ qout,
                               float* __restrict__ kout) {
    int gw = (blockIdx.x * blockDim.x + threadIdx.x) >> 5;  // t*H + h
    int lane = threadIdx.x & 31;
    int t = gw >> 4, h = gw & 15;
    int c0 = h * 64 + lane * 2;            // q channel; k channel = 1024 + c0
    float4 wq0 = ((const float4*)wq)[c0], wq1 = ((const float4*)wq)[c0 + 1];
    float4 wk0 = ((const float4*)wk)[c0], wk1 = ((const float4*)wk)[c0 + 1];
    float q0 = 0.f, q1 = 0.f, k0 = 0.f, k1 = 0.f;
    #pragma unroll
    for (int i = 0; i < CONV_; i++) {
        int tt = t - 3 + i;
        if (tt >= 0) {
            const float* row = big + (size_t)tt * BIGN_;
            float2 xq = *(const float2*)(row + c0);
            float2 xk = *(const float2*)(row + 1024 + c0);
            q0 = fmaf(xq.x, (&wq0.x)[i], q0);
            q1 = fmaf(xq.y, (&wq1.x)[i], q1);
            k0 = fmaf(xk.x, (&wk0.x)[i], k0);
            k1 = fmaf(xk.y, (&wk1.x)[i], k1);
        }
    }
    // silu
    q0 *= 1.f / (1.f + __expf(-q0));
    q1 *= 1.f / (1.f + __expf(-q1));
    k0 *= 1.f / (1.f + __expf(-k0));
    k1 *= 1.f / (1.f + __expf(-k1));
    // k DC removal
    float s = k0 + k1;
    for (int off = 16; off > 0; off >>= 1) s += __shfl_xor_sync(0xffffffffu, s, off);
    float mean = s * (1.f / 64.f);
    k0 -= mean; k1 -= mean;
    // k L2 normalize
    float ss = k0 * k0 + k1 * k1;
    for (int off = 16; off > 0; off >>= 1) ss += __shfl_xor_sync(0xffffffffu, ss, off);
    float sc = rsqrtf(ss + 1e-6f);
    // q L2 normalize * DK^-0.5
    float qq = q0 * q0 + q1 * q1;
    for (int off = 16; off > 0; off >>= 1) qq += __shfl_xor_sync(0xffffffffu, qq, off);
    float qs = rsqrtf(qq + 1e-6f) * 0.125f;
    *(float2*)&qout[(size_t)gw * DK_ + lane * 2] = make_float2(q0 * qs, q1 * qs);
    *(float2*)&kout[(size_t)gw * DK_ + lane * 2] = make_float2(k0 * sc, k1 * sc);
}

// ---------------- 4b) conv(v) + silu, float4 ----------------
__global__ void conv_v_kernel(const float* __restrict__ big,
                              const float* __restrict__ wv,
                              float* __restrict__ ov) {
    int idx = blockIdx.x * 256 + threadIdx.x;   // over T_*2048/4
    int t = idx >> 9;                            // 512 float4 per row
    int c4 = (idx & 511) * 4;                    // v channel
    float4 w0 = ((const float4*)wv)[c4 + 0];
    float4 w1 = ((const float4*)wv)[c4 + 1];
    float4 w2 = ((const float4*)wv)[c4 + 2];
    float4 w3 = ((const float4*)wv)[c4 + 3];
    float4 acc = make_float4(0.f, 0.f, 0.f, 0.f);
    #pragma unroll
    for (int i = 0; i < CONV_; i++) {
        int tt = t - 3 + i;
        if (tt >= 0) {
            float4 xv = *(const float4*)(big + (size_t)tt * BIGN_ + 2048 + c4);
            acc.x = fmaf(xv.x, (&w0.x)[i], acc.x);
            acc.y = fmaf(xv.y, (&w1.x)[i], acc.y);
            acc.z = fmaf(xv.z, (&w2.x)[i], acc.z);
            acc.w = fmaf(xv.w, (&w3.x)[i], acc.w);
        }
    }
    acc.x *= 1.f / (1.f + __expf(-acc.x));
    acc.y *= 1.f / (1.f + __expf(-acc.y));
    acc.z *= 1.f / (1.f + __expf(-acc.z));
    acc.w *= 1.f / (1.f + __expf(-acc.w));
    *(float4*)&ov[(size_t)t * VAL_ + c4] = acc;
}

// ---------------- 5) gated delta-rule scan (dv split 8) ----------------
// grid = H_*8 (head, dv-eighth), block = 128: thread = dv_l(16) x qr(8),
// owns S[qr*8 + j][dv], j<8. cp.async 4-set ring, 4 timesteps/stage.
__global__ __launch_bounds__(128) void scan_kernel(const float* __restrict__ q,
                                                   const float* __restrict__ k,
                                                   const float* __restrict__ v,
                                                   const float* __restrict__ beta,
                                                   const float* __restrict__ eg,
                                                   float* __restrict__ o) {
    int h = blockIdx.x >> 3;
    int dvq = blockIdx.x & 7;
    int tid = threadIdx.x;
    int dv_l = tid >> 3, qr = tid & 7;
    int dv = dvq * 16 + dv_l;

    __shared__ float ks[4][4][64], qs[4][4][64], vs[4][4][16], gb[4][4][2];

    int role = tid >> 5;
    int lane = tid & 31;

    float S[8];
    #pragma unroll
    for (int i = 0; i < 8; i++) S[i] = 0.f;

    const int NP = T_ / 4;   // 512 stages

    #define ISSUE_STAGE(P) do {                                                       \
        int set_ = (P) & 3;                                                           \
        int t0_ = (P) * 4;                                                            \
        if (role == 0) {                                                              \
            _Pragma("unroll")                                                         \
            for (int r2 = 0; r2 < 2; r2++) {                                          \
                int idx = lane + r2 * 32;                                             \
                int ss = idx >> 4, ch = idx & 15;                                     \
                unsigned d = (unsigned)__cvta_generic_to_shared(&ks[set_][ss][ch*4]); \
                const float* sp = k + ((size_t)(t0_ + ss) * H_ + h) * DK_ + ch*4;     \
                CP16(d, sp);                                                          \
            }                                                                         \
        } else if (role == 1) {                                                       \
            _Pragma("unroll")                                                         \
            for (int r2 = 0; r2 < 2; r2++) {                                          \
                int idx = lane + r2 * 32;                                             \
                int ss = idx >> 4, ch = idx & 15;                                     \
                unsigned d = (unsigned)__cvta_generic_to_shared(&qs[set_][ss][ch*4]); \
                const float* sp = q + ((size_t)(t0_ + ss) * H_ + h) * DK_ + ch*4;     \
                CP16(d, sp);                                                          \
            }                                                                         \
        } else if (role == 2) {                                                       \
            if (lane < 16) {                                                          \
                int ss = lane >> 2, ch = lane & 3;                                    \
                unsigned d = (unsigned)__cvta_generic_to_shared(&vs[set_][ss][ch*4]); \
                const float* sp = v + ((size_t)(t0_ + ss) * H_ + h) * DV_ + dvq*16 + ch*4; \
                CP16(d, sp);                                                          \
            }                                                                         \
        } else if (lane < 8) {                                                        \
            int ss = lane >> 1; int which = lane & 1;                                 \
            unsigned d = (unsigned)__cvta_generic_to_shared(&gb[set_][ss][which]);    \
            const float* sp = (which ? beta : eg) + (size_t)(t0_ + ss) * H_ + h;      \
            asm volatile("cp.async.ca.shared.global [%0], [%1], 4;\n" :: "r"(d), "l"(sp)); \
        }                                                                             \
    } while (0)

    #pragma unroll
    for (int p = 0; p < 3; p++) {
        ISSUE_STAGE(p);
        asm volatile("cp.async.commit_group;\n");
    }

    for (int p = 0; p < NP; p++) {
        asm volatile("cp.async.wait_group 2;\n");
        __syncthreads();
        if (p + 3 < NP) ISSUE_STAGE(p + 3);
        asm volatile("cp.async.commit_group;\n");
        int set = p & 3;
        #pragma unroll
        for (int s = 0; s < 4; s++) {
            float egv = gb[set][s][0];
            float bt  = gb[set][s][1];
            float vv  = vs[set][s][dv_l];
            float kr[8];
            *(float4*)&kr[0] = *(const float4*)&ks[set][s][qr*8];
            *(float4*)&kr[4] = *(const float4*)&ks[set][s][qr*8 + 4];
            float kv0, kv1, kv2, kv3;
            S[0] *= egv; kv0 = kr[0] * S[0];
            S[1] *= egv; kv1 = kr[1] * S[1];
            S[2] *= egv; kv2 = kr[2] * S[2];
            S[3] *= egv; kv3 = kr[3] * S[3];
            S[4] *= egv; kv0 = fmaf(kr[4], S[4], kv0);
            S[5] *= egv; kv1 = fmaf(kr[5], S[5], kv1);
            S[6] *= egv; kv2 = fmaf(kr[6], S[6], kv2);
            S[7] *= egv; kv3 = fmaf(kr[7], S[7], kv3);
            float kv = (kv0 + kv1) + (kv2 + kv3);
            kv += __shfl_xor_sync(0xffffffffu, kv, 1);
            kv += __shfl_xor_sync(0xffffffffu, kv, 2);
            kv += __shfl_xor_sync(0xffffffffu, kv, 4);
            float vn = (vv - kv) * bt;
            float qv[8];
            *(float4*)&qv[0] = *(const float4*)&qs[set][s][qr*8];
            *(float4*)&qv[4] = *(const float4*)&qs[set][s][qr*8 + 4];
            float o0, o1, o2, o3;
            S[0] = fmaf(kr[0], vn, S[0]); o0 = qv[0] * S[0];
            S[1] = fmaf(kr[1], vn, S[1]); o1 = qv[1] * S[1];
            S[2] = fmaf(kr[2], vn, S[2]); o2 = qv[2] * S[2];
            S[3] = fmaf(kr[3], vn, S[3]); o3 = qv[3] * S[3];
            S[4] = fmaf(kr[4], vn, S[4]); o0 = fmaf(qv[4], S[4], o0);
            S[5] = fmaf(kr[5], vn, S[5]); o1 = fmaf(qv[5], S[5], o1);
            S[6] = fmaf(kr[6], vn, S[6]); o2 = fmaf(qv[6], S[6], o2);
            S[7] = fmaf(kr[7], vn, S[7]); o3 = fmaf(qv[7], S[7], o3);
            float oo = (o0 + o1) + (o2 + o3);
            oo += __shfl_xor_sync(0xffffffffu, oo, 1);
            oo += __shfl_xor_sync(0xffffffffu, oo, 2);
            oo += __shfl_xor_sync(0xffffffffu, oo, 4);
            if (qr == 0) o[((size_t)(p*4 + s) * H_ + h) * DV_ + dv] = oo;
        }
    }
    #undef ISSUE_STAGE
}

// ---------------- 6) gated RMSNorm + silu gate -> fp16 ----------------
__global__ void onorm_kernel(const float* __restrict__ o,
                             const float* __restrict__ gateb,
                             const float* __restrict__ onw,
                             __half* __restrict__ o2h) {
    int th = blockIdx.x;                 // t*H + h
    int t = th >> 4, h = th & 15;
    int i = threadIdx.x;                 // 0..127 = dv
    float val = o[(size_t)th * DV_ + i];
    float ss = val * val;
    for (int off = 16; off > 0; off >>= 1) ss += __shfl_xor_sync(0xffffffffu, ss, off);
    __shared__ float red[4];
    int warp = i >> 5, lane = i & 31;
    if (lane == 0) red[warp] = ss;
    __syncthreads();
    float tot = red[0] + red[1] + red[2] + red[3];
    float scale = rsqrtf(tot / (float)DV_ + 1e-5f);
    float gv = gateb[(size_t)t * BIGN_ + h * DV_ + i];
    float r = val * scale * onw[i] * (gv / (1.f + expf(-gv)));
    o2h[(size_t)th * DV_ + i] = __float2half_rn(r);
}

// ---------------- launcher ----------------
extern "C" void kernel_launch(void* const* d_in, const int* in_sizes, int n_in,
                              void* d_out, int out_size) {
    const float* hidden    = (const float*)d_in[0];
    const float* norm_w    = (const float*)d_in[1];
    const float* q_w       = (const float*)d_in[2];
    const float* k_w       = (const float*)d_in[3];
    const float* v_w       = (const float*)d_in[4];
    const float* a_w       = (const float*)d_in[5];
    const float* b_w       = (const float*)d_in[6];
    const float* g_w       = (const float*)d_in[7];
    const float* dt_bias   = (const float*)d_in[8];
    const float* A_log     = (const float*)d_in[9];
    const float* conv_q_w  = (const float*)d_in[10];
    const float* conv_k_w  = (const float*)d_in[11];
    const float* conv_v_w  = (const float*)d_in[12];
    const float* o_norm_w  = (const float*)d_in[13];
    const float* o_proj_w  = (const float*)d_in[14];
    const float* out_proj_w= (const float*)d_in[15];
    float* out = (float*)d_out;

    float *prs, *pbig, *pq, *pk, *pv, *pbeta, *peg, *po;
    __half *pwt, *pxh, *po2h, *py1h;
    cudaGetSymbolAddress((void**)&pwt,   g_wt);
    cudaGetSymbolAddress((void**)&pxh,   g_xh);
    cudaGetSymbolAddress((void**)&prs,   g_rs);
    cudaGetSymbolAddress((void**)&pbig,  g_big);
    cudaGetSymbolAddress((void**)&pq,    g_q);
    cudaGetSymbolAddress((void**)&pk,    g_k);
    cudaGetSymbolAddress((void**)&pv,    g_v);
    cudaGetSymbolAddress((void**)&pbeta, g_beta);
    cudaGetSymbolAddress((void**)&peg,   g_eg);
    cudaGetSymbolAddress((void**)&po,    g_o);
    cudaGetSymbolAddress((void**)&po2h,  g_o2h);
    cudaGetSymbolAddress((void**)&py1h,  g_y1h);

    // 0) weights -> fp16
    cvt_weights_h<<<1179648/256, 256>>>(
        (const float4*)q_w, (const float4*)k_w, (const float4*)v_w,
        (const float4*)g_w, (const float4*)o_proj_w, (const float4*)out_proj_w, pwt);
    cvt_ab_h<<<16384/256, 256>>>(a_w, b_w, pwt);

    // 1) RMSNorm
    rms_reduce_kernel<<<T_/8, 256>>>(hidden, prs);
    rms_apply_kernel<<<(T_*HID_/4)/256, 256>>>(hidden, prs, norm_w, pxh);

    // 2) fused q/k/v/g/ab projection (fp16 MMA)
    gemm128_h<0><<<dim3(BIGN_/128, T_/128), 256>>>(pxh, pwt + WQKVG_OFF,
                                                   pbig, nullptr, HID_, BIGN_);

    // 3) beta / exp(g)
    beta_eg_kernel<<<(T_*H_)/256, 256>>>(pbig, dt_bias, A_log, pbeta, peg);

    // 4) convs (+ fused qk normalization)
    conv_qk_kernel<<<(T_*H_*32)/256, 256>>>(pbig, conv_q_w, conv_k_w, pq, pk);
    conv_v_kernel<<<(T_*VAL_/4)/256, 256>>>(pbig, conv_v_w, pv);

    // 5) scan (dv split 8 -> 128 blocks)
    scan_kernel<<<H_*8, 128>>>(pq, pk, pv, pbeta, peg, po);

    // 6) gated output norm -> fp16
    onorm_kernel<<<T_*H_, 128>>>(po, pbig + 4096, o_norm_w, po2h);

    // 7) output projections (fp16 MMA)
    gemm128_h<1><<<dim3(HID_/128, T_/128), 256>>>(po2h, pwt + WO_OFF,
                                                  nullptr, py1h, VAL_, HID_);
    gemm128_h<0><<<dim3(HID_/128, T_/128), 256>>>(py1h, pwt + WOUT_OFF,
                                                  out, nullptr, HID_, HID_);
}

// round 12
// speedup vs baseline: 5.9012x; 1.0698x over previous
#include <cuda_runtime.h>
#include <cuda_fp16.h>
#include <math.h>

// ---------------- problem dims (fixed) ----------------
#define T_    2048
#define HID_  1024
#define H_    16
#define DK_   64
#define DV_   128
#define VAL_  2048
#define QKD_  1024
#define CONV_ 4
#define BIGN_ 6272   // q(1024)+k(1024)+v(2048)+g(2048)+ab_pad(128)

// fp16 weight buffer offsets (halves)
#define WQKVG_OFF 0u
#define WAB_OFF   6291456u              // 6144*1024
#define WO_OFF    6422528u              // + 128*1024
#define WOUT_OFF  8519680u              // + 1024*2048
#define WT_HALVES 9568256u              // + 1024*1024

// ---------------- scratch (device globals) ----------------
__device__ __half g_wt  [WT_HALVES];
__device__ __half g_xh  [T_*HID_];
__device__ float  g_rs  [T_];
__device__ float  g_big [T_*BIGN_];
__device__ float  g_q   [T_*QKD_];
__device__ float  g_k   [T_*QKD_];
__device__ float  g_v   [T_*VAL_];
__device__ float  g_beta[T_*H_];
__device__ float  g_eg  [T_*H_];
__device__ float  g_o   [T_*VAL_];
__device__ __half g_o2h [T_*VAL_];
__device__ __half g_y1h [T_*HID_];

// ---------------- helpers ----------------
__device__ __forceinline__ unsigned pack2(float a, float b) {
    __half2 h = __floats2half2_rn(a, b);
    return *reinterpret_cast<unsigned*>(&h);
}
#define MMA_F16(C, A, B)                                                      \
    asm volatile("mma.sync.aligned.m16n8k16.row.col.f32.f16.f16.f32 "         \
                 "{%0,%1,%2,%3}, {%4,%5,%6,%7}, {%8,%9}, {%0,%1,%2,%3};"      \
                 : "+f"((C)[0]), "+f"((C)[1]), "+f"((C)[2]), "+f"((C)[3])     \
                 : "r"((A)[0]), "r"((A)[1]), "r"((A)[2]), "r"((A)[3]),        \
                   "r"((B)[0]), "r"((B)[1]))
#define LDSM4(R0, R1, R2, R3, addr)                                           \
    asm volatile("ldmatrix.sync.aligned.m8n8.x4.shared.b16 {%0,%1,%2,%3}, [%4];" \
                 : "=r"(R0), "=r"(R1), "=r"(R2), "=r"(R3) : "r"(addr))
#define CP16(dst, src) \
    asm volatile("cp.async.cg.shared.global [%0], [%1], 16;\n" :: "r"(dst), "l"(src))

// ---------------- 0) ALL weights -> fp16 (single kernel) ----------------
// units of 8 halves. 0..1179647: q,k,v,g,o,out stream; rest: ab padded tile.
__global__ void cvt_all_h(const float4* __restrict__ wq,
                          const float4* __restrict__ wk,
                          const float4* __restrict__ wv,
                          const float4* __restrict__ wg,
                          const float4* __restrict__ wo,
                          const float4* __restrict__ wout,
                          const float*  __restrict__ a_w,
                          const float*  __restrict__ b_w,
                          __half* __restrict__ dst) {
    int idx = blockIdx.x * 256 + threadIdx.x;       // 0 .. 1196031
    if (idx < 1179648) {
        int f4 = idx * 2;
        const float4* src; int off;
        if (f4 < 262144)       { src = wq;   off = f4; }
        else if (f4 < 524288)  { src = wk;   off = f4 - 262144; }
        else if (f4 < 1048576) { src = wv;   off = f4 - 524288; }
        else if (f4 < 1572864) { src = wg;   off = f4 - 1048576; }
        else if (f4 < 2097152) { src = wo;   off = f4 - 1572864; }
        else                   { src = wout; off = f4 - 2097152; }
        unsigned hbase = (unsigned)idx * 8;
        if (hbase >= WAB_OFF) hbase += 131072;      // skip ab region
        float4 v0 = src[off], v1 = src[off + 1];
        uint4 u;
        u.x = pack2(v0.x, v0.y); u.y = pack2(v0.z, v0.w);
        u.z = pack2(v1.x, v1.y); u.w = pack2(v1.z, v1.w);
        *(uint4*)&dst[hbase] = u;
    } else {
        int u2 = idx - 1179648;                     // 0..16383
        int base = u2 * 8;
        int row = base >> 10, col = base & 1023;
        float vals[8];
        #pragma unroll
        for (int i = 0; i < 8; i++) vals[i] = 0.f;
        if (row < 16) {
            #pragma unroll
            for (int i = 0; i < 8; i++) vals[i] = a_w[row * 1024 + col + i];
        } else if (row < 32) {
            #pragma unroll
            for (int i = 0; i < 8; i++) vals[i] = b_w[(row - 16) * 1024 + col + i];
        }
        uint4 uu;
        uu.x = pack2(vals[0], vals[1]); uu.y = pack2(vals[2], vals[3]);
        uu.z = pack2(vals[4], vals[5]); uu.w = pack2(vals[6], vals[7]);
        *(uint4*)&dst[WAB_OFF + base] = uu;
    }
}

// ---------------- 1a) RMSNorm reduce ----------------
__global__ void rms_reduce_kernel(const float* __restrict__ h,
                                  float* __restrict__ rs) {
    int row = blockIdx.x * 8 + (threadIdx.x >> 5);
    int lane = threadIdx.x & 31;
    const float4* p = (const float4*)(h + (size_t)row * HID_);
    float ss = 0.f;
    #pragma unroll
    for (int i = 0; i < 8; i++) {
        float4 v = p[lane + i * 32];
        ss += v.x * v.x + v.y * v.y + v.z * v.z + v.w * v.w;
    }
    for (int off = 16; off > 0; off >>= 1) ss += __shfl_xor_sync(0xffffffffu, ss, off);
    if (lane == 0) rs[row] = rsqrtf(ss / (float)HID_ + 1e-6f);
}

// ---------------- 1b) RMSNorm apply -> fp16 ----------------
__global__ void rms_apply_kernel(const float* __restrict__ h,
                                 const float* __restrict__ rs,
                                 const float* __restrict__ w,
                                 __half* __restrict__ xh) {
    int idx = blockIdx.x * blockDim.x + threadIdx.x;
    int t = idx >> 8;
    float s = rs[t];
    float4 hv = ((const float4*)h)[idx];
    float4 wv = ((const float4*)w)[idx & 255];
    uint2 u;
    u.x = pack2(hv.x * s * wv.x, hv.y * s * wv.y);
    u.y = pack2(hv.z * s * wv.z, hv.w * s * wv.w);
    ((uint2*)xh)[idx] = u;
}

// ---------------- 2) 128x128 FP16 GEMM, 3-stage cp.async + ldmatrix -------
#define HPAD 40
#define STAGEB 10240u                   // 128*40 halves * 2B
template<int OUT_HALF>
__global__ __launch_bounds__(256, 2) void gemm128_h(const __half* __restrict__ X,
                                                    const __half* __restrict__ W,
                                                    float* __restrict__ Cf,
                                                    __half* __restrict__ Ch,
                                                    int K, int ldc) {
    extern __shared__ __half smem[];    // [A0 A1 A2 B0 B1 B2], 10240B each
    const __half* Xt = X + (size_t)blockIdx.y * 128 * K;
    const __half* Wt = W + (size_t)blockIdx.x * 128 * K;
    int tid = threadIdx.x, wid = tid >> 5, lane = tid & 31;
    int wm = (wid >> 2) * 64, wn = (wid & 3) * 32;
    int gid = lane >> 2, tig = lane & 3;
    int t4 = lane >> 3, l8 = lane & 7;
    int aRow = (t4 & 1) * 8 + l8, aCol = (t4 >> 1) * 8;
    int bRow = (t4 >> 1) * 8 + l8, bCol = (t4 & 1) * 8;

    int lr = tid >> 1, hc = (tid & 1) * 16;
    const __half* xs = Xt + (size_t)lr * K + hc;
    const __half* ws = Wt + (size_t)lr * K + hc;
    unsigned abase = (unsigned)__cvta_generic_to_shared(smem);
    unsigned bbase = abase + 3 * STAGEB;
    unsigned woff = (unsigned)(lr * HPAD + hc) * 2;

    float acc[16][4];
    #pragma unroll
    for (int i = 0; i < 16; i++)
        #pragma unroll
        for (int j = 0; j < 4; j++) acc[i][j] = 0.f;

    // prologue: stages 0,1
    #pragma unroll
    for (int s = 0; s < 2; s++) {
        unsigned da = abase + s * STAGEB + woff;
        unsigned db = bbase + s * STAGEB + woff;
        int k0 = s * 32;
        CP16(da, xs + k0); CP16(da + 16, xs + k0 + 8);
        CP16(db, ws + k0); CP16(db + 16, ws + k0 + 8);
        asm volatile("cp.async.commit_group;\n");
    }

    int nk = K / 32;
    for (int it = 0; it < nk; it++) {
        asm volatile("cp.async.wait_group 1;\n");   // stage `it` ready
        __syncthreads();
        if (it + 2 < nk) {
            int s = (it + 2) % 3;
            int k0 = (it + 2) * 32;
            unsigned da = abase + s * STAGEB + woff;
            unsigned db = bbase + s * STAGEB + woff;
            CP16(da, xs + k0); CP16(da + 16, xs + k0 + 8);
            CP16(db, ws + k0); CP16(db + 16, ws + k0 + 8);
        }
        asm volatile("cp.async.commit_group;\n");
        unsigned ab = abase + (it % 3) * STAGEB;
        unsigned bb = bbase + (it % 3) * STAGEB;
        #pragma unroll
        for (int k16 = 0; k16 < 2; k16++) {
            int kk = k16 * 16;
            unsigned a[4][4], b[4][2];
            #pragma unroll
            for (int mt = 0; mt < 4; mt++) {
                unsigned addr = ab + ((wm + mt * 16 + aRow) * HPAD + kk + aCol) * 2;
                LDSM4(a[mt][0], a[mt][1], a[mt][2], a[mt][3], addr);
            }
            #pragma unroll
            for (int p = 0; p < 2; p++) {
                unsigned addr = bb + ((wn + p * 16 + bRow) * HPAD + kk + bCol) * 2;
                LDSM4(b[p*2][0], b[p*2][1], b[p*2+1][0], b[p*2+1][1], addr);
            }
            #pragma unroll
            for (int mt = 0; mt < 4; mt++)
                #pragma unroll
                for (int nt = 0; nt < 4; nt++)
                    MMA_F16(acc[mt * 4 + nt], a[mt], b[nt]);
        }
    }

    size_t base = (size_t)blockIdx.y * 128 * ldc + blockIdx.x * 128;
    #pragma unroll
    for (int mt = 0; mt < 4; mt++) {
        int row = wm + mt * 16 + gid;
        #pragma unroll
        for (int nt = 0; nt < 4; nt++) {
            int col = wn + nt * 8 + tig * 2;
            float* c = acc[mt * 4 + nt];
            if (OUT_HALF) {
                *(unsigned*)&Ch[base + (size_t)row * ldc + col]       = pack2(c[0], c[1]);
                *(unsigned*)&Ch[base + (size_t)(row + 8) * ldc + col] = pack2(c[2], c[3]);
            } else {
                *(float2*)&Cf[base + (size_t)row * ldc + col]       = make_float2(c[0], c[1]);
                *(float2*)&Cf[base + (size_t)(row + 8) * ldc + col] = make_float2(c[2], c[3]);
            }
        }
    }
}

// ---------------- 3a) conv(q,k) + silu + DC-removal + L2 norm + beta/eg ---
__global__ void conv_qk_kernel(const float* __restrict__ big,
                               const float* __restrict__ wq,
                               const float* __restrict__ wk,
                               const float* __restrict__ dt_bias,
                               const float* __restrict__ A_log,
                               float* __restrict__ qout,
                               float* __restrict__ kout,
                               float* __restrict__ beta,
                               float* __restrict__ eg) {
    int gw = (blockIdx.x * blockDim.x + threadIdx.x) >> 5;  // t*H + h
    int lane = threadIdx.x & 31;
    int t = gw >> 4, h = gw & 15;
    // beta/eg inputs (lane 0 only uses them; issue loads early)
    float da = 0.f, db = 0.f;
    if (lane == 0) {
        da = big[(size_t)t * BIGN_ + 6144 + h];
        db = big[(size_t)t * BIGN_ + 6160 + h];
    }
    int c0 = h * 64 + lane * 2;            // q channel; k channel = 1024 + c0
    float4 wq0 = ((const float4*)wq)[c0], wq1 = ((const float4*)wq)[c0 + 1];
    float4 wk0 = ((const float4*)wk)[c0], wk1 = ((const float4*)wk)[c0 + 1];
    float q0 = 0.f, q1 = 0.f, k0 = 0.f, k1 = 0.f;
    #pragma unroll
    for (int i = 0; i < CONV_; i++) {
        int tt = t - 3 + i;
        if (tt >= 0) {
            const float* row = big + (size_t)tt * BIGN_;
            float2 xq = *(const float2*)(row + c0);
            float2 xk = *(const float2*)(row + 1024 + c0);
            q0 = fmaf(xq.x, (&wq0.x)[i], q0);
            q1 = fmaf(xq.y, (&wq1.x)[i], q1);
            k0 = fmaf(xk.x, (&wk0.x)[i], k0);
            k1 = fmaf(xk.y, (&wk1.x)[i], k1);
        }
    }
    q0 *= 1.f / (1.f + __expf(-q0));
    q1 *= 1.f / (1.f + __expf(-q1));
    k0 *= 1.f / (1.f + __expf(-k0));
    k1 *= 1.f / (1.f + __expf(-k1));
    float s = k0 + k1;
    for (int off = 16; off > 0; off >>= 1) s += __shfl_xor_sync(0xffffffffu, s, off);
    float mean = s * (1.f / 64.f);
    k0 -= mean; k1 -= mean;
    float ss = k0 * k0 + k1 * k1;
    for (int off = 16; off > 0; off >>= 1) ss += __shfl_xor_sync(0xffffffffu, ss, off);
    float sc = rsqrtf(ss + 1e-6f);
    float qq = q0 * q0 + q1 * q1;
    for (int off = 16; off > 0; off >>= 1) qq += __shfl_xor_sync(0xffffffffu, qq, off);
    float qs = rsqrtf(qq + 1e-6f) * 0.125f;
    *(float2*)&qout[(size_t)gw * DK_ + lane * 2] = make_float2(q0 * qs, q1 * qs);
    *(float2*)&kout[(size_t)gw * DK_ + lane * 2] = make_float2(k0 * sc, k1 * sc);
    if (lane == 0) {
        beta[gw] = 1.f / (1.f + expf(-db));
        float z = da + dt_bias[h];
        float sp = (z > 20.f) ? z : log1pf(expf(z));
        eg[gw] = expf(-expf(A_log[h]) * sp);
    }
}

// ---------------- 3b) conv(v) + silu ----------------
__global__ void conv_v_kernel(const float* __restrict__ big,
                              const float* __restrict__ wv,
                              float* __restrict__ ov) {
    int idx = blockIdx.x * 256 + threadIdx.x;   // over T_*2048/4
    int t = idx >> 9;
    int c4 = (idx & 511) * 4;
    float4 w0 = ((const float4*)wv)[c4 + 0];
    float4 w1 = ((const float4*)wv)[c4 + 1];
    float4 w2 = ((const float4*)wv)[c4 + 2];
    float4 w3 = ((const float4*)wv)[c4 + 3];
    float4 acc = make_float4(0.f, 0.f, 0.f, 0.f);
    #pragma unroll
    for (int i = 0; i < CONV_; i++) {
        int tt = t - 3 + i;
        if (tt >= 0) {
            float4 xv = *(const float4*)(big + (size_t)tt * BIGN_ + 2048 + c4);
            acc.x = fmaf(xv.x, (&w0.x)[i], acc.x);
            acc.y = fmaf(xv.y, (&w1.x)[i], acc.y);
            acc.z = fmaf(xv.z, (&w2.x)[i], acc.z);
            acc.w = fmaf(xv.w, (&w3.x)[i], acc.w);
        }
    }
    acc.x *= 1.f / (1.f + __expf(-acc.x));
    acc.y *= 1.f / (1.f + __expf(-acc.y));
    acc.z *= 1.f / (1.f + __expf(-acc.z));
    acc.w *= 1.f / (1.f + __expf(-acc.w));
    *(float4*)&ov[(size_t)t * VAL_ + c4] = acc;
}

// ---------------- 4) gated delta-rule scan (dv split 8) ----------------
__global__ __launch_bounds__(128) void scan_kernel(const float* __restrict__ q,
                                                   const float* __restrict__ k,
                                                   const float* __restrict__ v,
                                                   const float* __restrict__ beta,
                                                   const float* __restrict__ eg,
                                                   float* __restrict__ o) {
    int h = blockIdx.x >> 3;
    int dvq = blockIdx.x & 7;
    int tid = threadIdx.x;
    int dv_l = tid >> 3, qr = tid & 7;
    int dv = dvq * 16 + dv_l;

    __shared__ float ks[4][4][64], qs[4][4][64], vs[4][4][16], gb[4][4][2];

    int role = tid >> 5;
    int lane = tid & 31;

    float S[8];
    #pragma unroll
    for (int i = 0; i < 8; i++) S[i] = 0.f;

    const int NP = T_ / 4;   // 512 stages

    #define ISSUE_STAGE(P) do {                                                       \
        int set_ = (P) & 3;                                                           \
        int t0_ = (P) * 4;                                                            \
        if (role == 0) {                                                              \
            _Pragma("unroll")                                                         \
            for (int r2 = 0; r2 < 2; r2++) {                                          \
                int idx = lane + r2 * 32;                                             \
                int ss = idx >> 4, ch = idx & 15;                                     \
                unsigned d = (unsigned)__cvta_generic_to_shared(&ks[set_][ss][ch*4]); \
                const float* sp = k + ((size_t)(t0_ + ss) * H_ + h) * DK_ + ch*4;     \
                CP16(d, sp);                                                          \
            }                                                                         \
        } else if (role == 1) {                                                       \
            _Pragma("unroll")                                                         \
            for (int r2 = 0; r2 < 2; r2++) {                                          \
                int idx = lane + r2 * 32;                                             \
                int ss = idx >> 4, ch = idx & 15;                                     \
                unsigned d = (unsigned)__cvta_generic_to_shared(&qs[set_][ss][ch*4]); \
                const float* sp = q + ((size_t)(t0_ + ss) * H_ + h) * DK_ + ch*4;     \
                CP16(d, sp);                                                          \
            }                                                                         \
        } else if (role == 2) {                                                       \
            if (lane < 16) {                                                          \
                int ss = lane >> 2, ch = lane & 3;                                    \
                unsigned d = (unsigned)__cvta_generic_to_shared(&vs[set_][ss][ch*4]); \
                const float* sp = v + ((size_t)(t0_ + ss) * H_ + h) * DV_ + dvq*16 + ch*4; \
                CP16(d, sp);                                                          \
            }                                                                         \
        } else if (lane < 8) {                                                        \
            int ss = lane >> 1; int which = lane & 1;                                 \
            unsigned d = (unsigned)__cvta_generic_to_shared(&gb[set_][ss][which]);    \
            const float* sp = (which ? beta : eg) + (size_t)(t0_ + ss) * H_ + h;      \
            asm volatile("cp.async.ca.shared.global [%0], [%1], 4;\n" :: "r"(d), "l"(sp)); \
        }                                                                             \
    } while (0)

    #pragma unroll
    for (int p = 0; p < 3; p++) {
        ISSUE_STAGE(p);
        asm volatile("cp.async.commit_group;\n");
    }

    for (int p = 0; p < NP; p++) {
        asm volatile("cp.async.wait_group 2;\n");
        __syncthreads();
        if (p + 3 < NP) ISSUE_STAGE(p + 3);
        asm volatile("cp.async.commit_group;\n");
        int set = p & 3;
        #pragma unroll
        for (int s = 0; s < 4; s++) {
            float egv = gb[set][s][0];
            float bt  = gb[set][s][1];
            float vv  = vs[set][s][dv_l];
            float kr[8];
            *(float4*)&kr[0] = *(const float4*)&ks[set][s][qr*8];
            *(float4*)&kr[4] = *(const float4*)&ks[set][s][qr*8 + 4];
            float kv0, kv1, kv2, kv3;
            S[0] *= egv; kv0 = kr[0] * S[0];
            S[1] *= egv; kv1 = kr[1] * S[1];
            S[2] *= egv; kv2 = kr[2] * S[2];
            S[3] *= egv; kv3 = kr[3] * S[3];
            S[4] *= egv; kv0 = fmaf(kr[4], S[4], kv0);
            S[5] *= egv; kv1 = fmaf(kr[5], S[5], kv1);
            S[6] *= egv; kv2 = fmaf(kr[6], S[6], kv2);
            S[7] *= egv; kv3 = fmaf(kr[7], S[7], kv3);
            float kv = (kv0 + kv1) + (kv2 + kv3);
            kv += __shfl_xor_sync(0xffffffffu, kv, 1);
            kv += __shfl_xor_sync(0xffffffffu, kv, 2);
            kv += __shfl_xor_sync(0xffffffffu, kv, 4);
            float vn = (vv - kv) * bt;
            float qv[8];
            *(float4*)&qv[0] = *(const float4*)&qs[set][s][qr*8];
            *(float4*)&qv[4] = *(const float4*)&qs[set][s][qr*8 + 4];
            float o0, o1, o2, o3;
            S[0] = fmaf(kr[0], vn, S[0]); o0 = qv[0] * S[0];
            S[1] = fmaf(kr[1], vn, S[1]); o1 = qv[1] * S[1];
            S[2] = fmaf(kr[2], vn, S[2]); o2 = qv[2] * S[2];
            S[3] = fmaf(kr[3], vn, S[3]); o3 = qv[3] * S[3];
            S[4] = fmaf(kr[4], vn, S[4]); o0 = fmaf(qv[4], S[4], o0);
            S[5] = fmaf(kr[5], vn, S[5]); o1 = fmaf(qv[5], S[5], o1);
            S[6] = fmaf(kr[6], vn, S[6]); o2 = fmaf(qv[6], S[6], o2);
            S[7] = fmaf(kr[7], vn, S[7]); o3 = fmaf(qv[7], S[7], o3);
            float oo = (o0 + o1) + (o2 + o3);
            oo += __shfl_xor_sync(0xffffffffu, oo, 1);
            oo += __shfl_xor_sync(0xffffffffu, oo, 2);
            oo += __shfl_xor_sync(0xffffffffu, oo, 4);
            if (qr == 0) o[((size_t)(p*4 + s) * H_ + h) * DV_ + dv] = oo;
        }
    }
    #undef ISSUE_STAGE
}

// ---------------- 5) gated RMSNorm + silu gate -> fp16 ----------------
__global__ void onorm_kernel(const float* __restrict__ o,
                             const float* __restrict__ gateb,
                             const float* __restrict__ onw,
                             __half* __restrict__ o2h) {
    int th = blockIdx.x;                 // t*H + h
    int t = th >> 4, h = th & 15;
    int i = threadIdx.x;                 // 0..127 = dv
    float val = o[(size_t)th * DV_ + i];
    float ss = val * val;
    for (int off = 16; off > 0; off >>= 1) ss += __shfl_xor_sync(0xffffffffu, ss, off);
    __shared__ float red[4];
    int warp = i >> 5, lane = i & 31;
    if (lane == 0) red[warp] = ss;
    __syncthreads();
    float tot = red[0] + red[1] + red[2] + red[3];
    float scale = rsqrtf(tot / (float)DV_ + 1e-5f);
    float gv = gateb[(size_t)t * BIGN_ + h * DV_ + i];
    float r = val * scale * onw[i] * (gv / (1.f + expf(-gv)));
    o2h[(size_t)th * DV_ + i] = __float2half_rn(r);
}

// ---------------- launcher ----------------
extern "C" void kernel_launch(void* const* d_in, const int* in_sizes, int n_in,
                              void* d_out, int out_size) {
    const float* hidden    = (const float*)d_in[0];
    const float* norm_w    = (const float*)d_in[1];
    const float* q_w       = (const float*)d_in[2];
    const float* k_w       = (const float*)d_in[3];
    const float* v_w       = (const float*)d_in[4];
    const float* a_w       = (const float*)d_in[5];
    const float* b_w       = (const float*)d_in[6];
    const float* g_w       = (const float*)d_in[7];
    const float* dt_bias   = (const float*)d_in[8];
    const float* A_log     = (const float*)d_in[9];
    const float* conv_q_w  = (const float*)d_in[10];
    const float* conv_k_w  = (const float*)d_in[11];
    const float* conv_v_w  = (const float*)d_in[12];
    const float* o_norm_w  = (const float*)d_in[13];
    const float* o_proj_w  = (const float*)d_in[14];
    const float* out_proj_w= (const float*)d_in[15];
    float* out = (float*)d_out;

    float *prs, *pbig, *pq, *pk, *pv, *pbeta, *peg, *po;
    __half *pwt, *pxh, *po2h, *py1h;
    cudaGetSymbolAddress((void**)&pwt,   g_wt);
    cudaGetSymbolAddress((void**)&pxh,   g_xh);
    cudaGetSymbolAddress((void**)&prs,   g_rs);
    cudaGetSymbolAddress((void**)&pbig,  g_big);
    cudaGetSymbolAddress((void**)&pq,    g_q);
    cudaGetSymbolAddress((void**)&pk,    g_k);
    cudaGetSymbolAddress((void**)&pv,    g_v);
    cudaGetSymbolAddress((void**)&pbeta, g_beta);
    cudaGetSymbolAddress((void**)&peg,   g_eg);
    cudaGetSymbolAddress((void**)&po,    g_o);
    cudaGetSymbolAddress((void**)&po2h,  g_o2h);
    cudaGetSymbolAddress((void**)&py1h,  g_y1h);

    // opt-in to 60KB dynamic smem for the GEMMs (idempotent host calls)
    cudaFuncSetAttribute(gemm128_h<0>, cudaFuncAttributeMaxDynamicSharedMemorySize, 61440);
    cudaFuncSetAttribute(gemm128_h<1>, cudaFuncAttributeMaxDynamicSharedMemorySize, 61440);

    // 1) weights -> fp16 (single launch)
    cvt_all_h<<<4672, 256>>>(
        (const float4*)q_w, (const float4*)k_w, (const float4*)v_w,
        (const float4*)g_w, (const float4*)o_proj_w, (const float4*)out_proj_w,
        a_w, b_w, pwt);

    // 2,3) RMSNorm
    rms_reduce_kernel<<<T_/8, 256>>>(hidden, prs);
    rms_apply_kernel<<<(T_*HID_/4)/256, 256>>>(hidden, prs, norm_w, pxh);

    // 4) fused q/k/v/g/ab projection (launch #4 -> ncu slot)
    gemm128_h<0><<<dim3(BIGN_/128, T_/128), 256, 61440>>>(pxh, pwt + WQKVG_OFF,
                                                          pbig, nullptr, HID_, BIGN_);

    // 5) conv(q,k) + norms + beta/eg ; 6) conv(v)
    conv_qk_kernel<<<(T_*H_*32)/256, 256>>>(pbig, conv_q_w, conv_k_w,
                                            dt_bias, A_log, pq, pk, pbeta, peg);
    conv_v_kernel<<<(T_*VAL_/4)/256, 256>>>(pbig, conv_v_w, pv);

    // 7) scan
    scan_kernel<<<H_*8, 128>>>(pq, pk, pv, pbeta, peg, po);

    // 8) gated output norm -> fp16
    onorm_kernel<<<T_*H_, 128>>>(po, pbig + 4096, o_norm_w, po2h);

    // 9,10) output projections
    gemm128_h<1><<<dim3(HID_/128, T_/128), 256, 61440>>>(po2h, pwt + WO_OFF,
                                                         nullptr, py1h, VAL_, HID_);
    gemm128_h<0><<<dim3(HID_/128, T_/128), 256, 61440>>>(py1h, pwt + WOUT_OFF,
                                                         out, nullptr, HID_, HID_);
}